// round 7
// baseline (speedup 1.0000x reference)
#include <cuda_runtime.h>
#include <cuda_bf16.h>
#include <mma.h>
#include <math.h>
#include <stdint.h>

using namespace nvcuda;

#define D1 768
#define D2 768
#define D2R 385
#define NF (D1*D2R)     // 295680
#define KN_ 4
#define B_ 8
#define C_ 256
#define HW_ 64

// GEMM layout constants
#define QPAD 512          // padded N for stage A (q dimension)
#define KB2  800          // padded K for stage B (770 -> 800)

// pipelined GEMM tile constants
#define AST 40            // smem row stride (elements)
#define PIPE 3
#define ASTAGE_E (128*AST)            // A stage elements (5120)
#define BSTAGE_E (256*AST)            // B stage elements (10240)
#define ASTAGE_B (ASTAGE_E*2)         // bytes (10240)
#define BSTAGE_B (BSTAGE_E*2)         // bytes (20480)
#define SMEM_GEMM (PIPE*(ASTAGE_B + BSTAGE_B))   // 92160 bytes

// ---------------- scratch (static device globals; no allocation) ----------
__device__ float  g_att[B_*KN_];
__device__ float2 g_tw[D1];                 // (cos, sin) of 2*pi*j/768

// Stage A operands: A = stacked twiddles [1536][1536]; B = G^T [k][512][1536]
__device__ __align__(128) __nv_bfloat16 g_TA_hi[1536*1536];
__device__ __align__(128) __nv_bfloat16 g_TA_lo[1536*1536];
__device__ __align__(128) __nv_bfloat16 g_GT_hi[KN_*QPAD*1536];
__device__ __align__(128) __nv_bfloat16 g_GT_lo[KN_*QPAD*1536];
// Stage A output (fp32): [k][1536][512]  (rows 0..767 = Yr, 768..1535 = Yi)
__device__ __align__(128) float g_Ytmp[KN_*1536*QPAD];
// Stage B operands: A = scaled Y [3072][800]; B = irfft twiddles [768][800]
__device__ __align__(128) __nv_bfloat16 g_YA_hi[KN_*D1*KB2];
__device__ __align__(128) __nv_bfloat16 g_YA_lo[KN_*D1*KB2];
__device__ __align__(128) __nv_bfloat16 g_TB_hi[D2*KB2];
__device__ __align__(128) __nv_bfloat16 g_TB_lo[D2*KB2];
// spatial weights [k][m][t]
__device__ __align__(128) float g_S[KN_][D1*D2];

// bf16 hi/lo weights, per batch, K-major rows: [b][o][st*256 + i]
__device__ __align__(128) __nv_bfloat16 g_Whi[B_*C_*9*C_];
__device__ __align__(128) __nv_bfloat16 g_Wlo[B_*C_*9*C_];
// bf16 hi/lo input, channel-last: [b][pixel][i]
__device__ __align__(128) __nv_bfloat16 g_Xhi[B_*HW_*HW_*C_];
__device__ __align__(128) __nv_bfloat16 g_Xlo[B_*HW_*HW_*C_];

// ============================ helpers ======================================
__device__ __forceinline__ uint32_t smem_u32(const void* p) {
    uint32_t a;
    asm("{ .reg .u64 t; cvta.to.shared.u64 t, %1; cvt.u32.u64 %0, t; }"
        : "=r"(a) : "l"(p));
    return a;
}
__device__ __forceinline__ void cp_async16(uint32_t dst, const void* src, int pbytes) {
    asm volatile("cp.async.cg.shared.global [%0], [%1], 16, %2;"
                 :: "r"(dst), "l"(src), "r"(pbytes));
}
#define CP_COMMIT() asm volatile("cp.async.commit_group;" ::: "memory")
#define CP_WAIT(N)  asm volatile("cp.async.wait_group %0;" :: "n"(N) : "memory")

__device__ __forceinline__ void bf16_split(float v, __nv_bfloat16& hi, __nv_bfloat16& lo) {
    hi = __float2bfloat16(v);
    lo = __float2bfloat16(v - __bfloat162float(hi));
}

// ---------------- setup: attention + twiddle table -------------------------
__global__ void k_setup(const float* __restrict__ katt) {
    int j = threadIdx.x;
    if (j < D1) {
        double ang = 2.0 * M_PI * (double)j / (double)D1;
        g_tw[j] = make_float2((float)cos(ang), (float)sin(ang));
    }
    if (j < B_*KN_) {
        g_att[j] = 0.5f / (1.0f + expf(-katt[j]));
    }
}

// ---------------- fill stage-A twiddle matrix (1536x1536) ------------------
__global__ void k_fillTA() {
    int id = blockIdx.x * 256 + threadIdx.x;
    if (id >= 1536*1536) return;
    int i = id / 1536;
    int j = id - i*1536;
    int m = (i < 768) ? i : i - 768;
    int p = (j < 768) ? j : j - 768;
    int idx = (m * p) % 768;
    float2 cs = g_tw[idx];
    float v = (i < 768) ? ((j < 768) ? cs.x : -cs.y)
                        : ((j < 768) ? cs.y :  cs.x);
    __nv_bfloat16 hi, lo; bf16_split(v, hi, lo);
    g_TA_hi[id] = hi; g_TA_lo[id] = lo;
}

// ---------------- fill stage-B twiddle matrix (768 x 800) ------------------
__global__ void k_fillTB() {
    int id = blockIdx.x * 256 + threadIdx.x;
    if (id >= D2*KB2) return;
    int t = id / KB2;
    int c = id - t*KB2;
    float v = 0.f;
    if (c < 385) {
        v = g_tw[(c * t) % 768].x;
    } else if (c < 770) {
        int q = c - 385;
        v = -g_tw[(q * t) % 768].y;
    }
    __nv_bfloat16 hi, lo; bf16_split(v, hi, lo);
    g_TB_hi[id] = hi; g_TB_lo[id] = lo;
}

// ---------------- scatter dft_weight into transposed G, bf16 hi/lo ---------
__global__ void k_scatter(const float* __restrict__ dw,
                          const int*   __restrict__ fh,
                          const int*   __restrict__ fw) {
    int n = blockIdx.x * 256 + threadIdx.x;
    if (n >= NF) return;
    int p = fh[n];
    int q = fw[n];
    const float2* dw2 = (const float2*)dw;
#pragma unroll
    for (int k = 0; k < KN_; ++k) {
        float2 v = dw2[(size_t)k*NF + n];
        size_t base = (size_t)k*(QPAD*1536) + (size_t)q*1536;
        __nv_bfloat16 hi, lo;
        bf16_split(v.x, hi, lo);
        g_GT_hi[base + p] = hi;       g_GT_lo[base + p] = lo;
        bf16_split(v.y, hi, lo);
        g_GT_hi[base + 768 + p] = hi; g_GT_lo[base + 768 + p] = lo;
    }
}

// ---------------- convert stage-A output -> stage-B A operand --------------
__global__ void k_yconv() {
    int id = blockIdx.x * 256 + threadIdx.x;
    if (id >= KN_*D1*D2R) return;
    int q = id % D2R;
    int r = id / D2R;          // k*768 + m
    int m = r % D1;
    int k = r / D1;
    const float* Yk = g_Ytmp + (size_t)k*(1536*QPAD);
    float yr = Yk[(size_t)m*QPAD + q];
    float yi = Yk[(size_t)(768 + m)*QPAD + q];
    bool edge = (q == 0) || (q == 384);
    float sc  = (edge ? 1.f : 2.f) * (1.f/((float)D1*(float)D2));
    yr *= sc;
    yi  = edge ? 0.f : yi*sc;
    size_t base = (size_t)r*KB2;
    __nv_bfloat16 hi, lo;
    bf16_split(yr, hi, lo);
    g_YA_hi[base + q] = hi;        g_YA_lo[base + q] = lo;
    bf16_split(yi, hi, lo);
    g_YA_hi[base + 385 + q] = hi;  g_YA_lo[base + 385 + q] = lo;
}

// ============ pipelined bf16 hi/lo 3-pass wmma GEMM body ===================
// CTA: 128(M) x 256(N). 8 warps (2x4), warp tile 64x64.
// A row-major [M][lda]; B stored [N][ldb] (K contiguous). K mult of 32.
// 3-stage cp.async pipeline, ONE __syncthreads per chunk:
//   wait(<=1) -> sync -> compute(stage c%3) -> issue(c+2 into (c+2)%3)
__device__ __forceinline__ void gemm_body(
    const __nv_bfloat16* Ah, const __nv_bfloat16* Al, int lda,
    const __nv_bfloat16* Bh, const __nv_bfloat16* Bl, int ldb,
    float* Cc, int ldc, int K32)
{
    extern __shared__ __nv_bfloat16 dsm[];
    __nv_bfloat16* sA = dsm;                     // PIPE stages of 128x40
    __nv_bfloat16* sB = dsm + PIPE*ASTAGE_E;     // PIPE stages of 256x40

    int tid = threadIdx.x;
    int wid = tid >> 5;
    int warp_m = wid >> 2;            // 0..1 -> *64
    int warp_n = wid & 3;             // 0..3 -> *64
    int m0 = blockIdx.y * 128;
    int n0 = blockIdx.x * 256;

    int lrow  = tid >> 1;             // A row 0..127
    int lhalf = (tid & 1) << 4;       // 0 or 16

    uint32_t aB = smem_u32(sA);
    uint32_t bB = smem_u32(sB);
    uint32_t aOff = (uint32_t)(lrow*AST + lhalf) * 2;
    uint32_t bOff = (uint32_t)(tid*AST) * 2;

    wmma::fragment<wmma::accumulator, 16, 16, 16, float> acc[4][4];
#pragma unroll
    for (int i = 0; i < 4; ++i)
#pragma unroll
        for (int j = 0; j < 4; ++j)
            wmma::fill_fragment(acc[i][j], 0.f);

    int nchunk = 3*K32;

    auto issue = [&](int c, int stg) {
        int pass = (c >= 2*K32) ? 2 : ((c >= K32) ? 1 : 0);
        int k0   = (c - pass*K32) * 32;
        const __nv_bfloat16* Ap = (pass == 2) ? Al : Ah;
        const __nv_bfloat16* Bp = (pass == 1) ? Bl : Bh;

        const __nv_bfloat16* asrc = Ap + (size_t)(m0 + lrow)*lda + k0 + lhalf;
        uint32_t ad = aB + stg*ASTAGE_B + aOff;
        cp_async16(ad,      asrc,     16);
        cp_async16(ad + 16, asrc + 8, 16);

        const __nv_bfloat16* bsrc = Bp + (size_t)(n0 + tid)*ldb + k0;
        uint32_t bd = bB + stg*BSTAGE_B + bOff;
#pragma unroll
        for (int j = 0; j < 4; ++j)
            cp_async16(bd + j*16, bsrc + j*8, 16);
        CP_COMMIT();
    };

    issue(0, 0);
    issue(1, 1);

    for (int c = 0; c < nchunk; ++c) {
        int stg = c % PIPE;
        CP_WAIT(PIPE-2);
        __syncthreads();

        const __nv_bfloat16* sAc = sA + stg*ASTAGE_E;
        const __nv_bfloat16* sBc = sB + stg*BSTAGE_E;
#pragma unroll
        for (int kk = 0; kk < 2; ++kk) {
            wmma::fragment<wmma::matrix_a, 16, 16, 16, __nv_bfloat16, wmma::row_major> af[4];
            wmma::fragment<wmma::matrix_b, 16, 16, 16, __nv_bfloat16, wmma::col_major> bfr[4];
#pragma unroll
            for (int i = 0; i < 4; ++i)
                wmma::load_matrix_sync(af[i],
                    sAc + (warp_m*64 + i*16)*AST + kk*16, AST);
#pragma unroll
            for (int j = 0; j < 4; ++j)
                wmma::load_matrix_sync(bfr[j],
                    sBc + (warp_n*64 + j*16)*AST + kk*16, AST);
#pragma unroll
            for (int i = 0; i < 4; ++i)
#pragma unroll
                for (int j = 0; j < 4; ++j)
                    wmma::mma_sync(acc[i][j], af[i], bfr[j], acc[i][j]);
        }

        if (c + PIPE - 1 < nchunk)
            issue(c + PIPE - 1, (c + PIPE - 1) % PIPE);
    }

    float* ob = Cc + (size_t)(m0 + warp_m*64)*ldc + n0 + warp_n*64;
#pragma unroll
    for (int i = 0; i < 4; ++i)
#pragma unroll
        for (int j = 0; j < 4; ++j)
            wmma::store_matrix_sync(ob + (size_t)i*16*ldc + j*16,
                                    acc[i][j], ldc, wmma::mem_row_major);
}

// Stage A: [Yr;Yi](1536 x 512) = TA(1536x1536) * G^T, per k (blockIdx.z)
__global__ void __launch_bounds__(256, 1) k_gemmA() {
    int z = blockIdx.z;
    gemm_body(g_TA_hi, g_TA_lo, 1536,
              g_GT_hi + (size_t)z*(QPAD*1536), g_GT_lo + (size_t)z*(QPAD*1536), 1536,
              g_Ytmp + (size_t)z*(1536*QPAD), QPAD,
              1536/32);
}

// Stage B: S(3072 x 768) = YA(3072x800) * TB^T
__global__ void __launch_bounds__(256, 1) k_gemmB() {
    gemm_body(g_YA_hi, g_YA_lo, KB2,
              g_TB_hi, g_TB_lo, KB2,
              &g_S[0][0], D2,
              KB2/32);
}

// ------------- combine per-batch weights -> bf16 hi/lo, K-major ------------
__global__ void k_combine_bf16() {
    int id = blockIdx.x * 256 + threadIdx.x;
    int i  = id & 255;
    int r  = id >> 8;          // (b*256+o)*9 + st
    int st = r % 9;
    int bo = r / 9;
    int o  = bo & 255;
    int b  = bo >> 8;
    int s = st / 3, tt = st % 3;
    int sidx = (o*3 + s)*D2 + i*3 + tt;
    float v = 0.f;
#pragma unroll
    for (int k = 0; k < KN_; ++k)
        v += g_att[b*KN_ + k] * g_S[k][sidx];
    __nv_bfloat16 hi, lo; bf16_split(v, hi, lo);
    g_Whi[id] = hi;
    g_Wlo[id] = lo;
}

// ------------- x: split to bf16 hi/lo + transpose to channel-last ----------
__global__ void k_xsplit(const float* __restrict__ xin) {
    __shared__ float tile[32][33];
    int b  = blockIdx.z;
    int p0 = blockIdx.x * 32;
    int c0 = blockIdx.y * 32;
    int tx = threadIdx.x, ty = threadIdx.y;   // 32 x 8
#pragma unroll
    for (int j = 0; j < 4; ++j) {
        int ch = c0 + ty + j*8;
        tile[ty + j*8][tx] = xin[((size_t)b*C_ + ch)*(HW_*HW_) + p0 + tx];
    }
    __syncthreads();
#pragma unroll
    for (int j = 0; j < 4; ++j) {
        int p = p0 + ty + j*8;
        float v = tile[tx][ty + j*8];
        __nv_bfloat16 hi, lo; bf16_split(v, hi, lo);
        size_t oidx = ((size_t)b*(HW_*HW_) + p)*C_ + c0 + tx;
        g_Xhi[oidx] = hi;
        g_Xlo[oidx] = lo;
    }
}

// ---------------- pipelined wmma bf16 implicit-GEMM conv -------------------
// CTA: 128 out-ch x 256 pixels. K = 3 passes x 9 taps x 8 chunks of 32.
#define NCHUNK 216

__global__ void __launch_bounds__(256, 1) k_conv_wmma(float* __restrict__ out) {
    extern __shared__ __nv_bfloat16 dsm[];
    __nv_bfloat16* sA = dsm;
    __nv_bfloat16* sB = dsm + PIPE*ASTAGE_E;

    int tid = threadIdx.x;
    int wid = tid >> 5;
    int warp_m = wid >> 2;
    int warp_n = wid & 3;
    int b  = blockIdx.z;
    int o0 = blockIdx.y * 128;
    int n0 = blockIdx.x * 256;

    int lrow  = tid >> 1;
    int lhalf = (tid & 1) << 4;

    uint32_t aB = smem_u32(sA);
    uint32_t bB = smem_u32(sB);
    uint32_t aOff = (uint32_t)(lrow*AST + lhalf) * 2;
    uint32_t bOff = (uint32_t)(tid*AST) * 2;

    wmma::fragment<wmma::accumulator, 16, 16, 16, float> acc[4][4];
#pragma unroll
    for (int i = 0; i < 4; ++i)
#pragma unroll
        for (int j = 0; j < 4; ++j)
            wmma::fill_fragment(acc[i][j], 0.f);

    auto issue = [&](int c, int stg) {
        int pass = c / 72;
        int rem  = c % 72;
        int st   = rem >> 3;
        int i0   = (rem & 7) << 5;
        int s    = st / 3, t = st % 3;
        const __nv_bfloat16* Wp = (pass == 2) ? g_Wlo : g_Whi;
        const __nv_bfloat16* Xp = (pass == 1) ? g_Xlo : g_Xhi;

        const __nv_bfloat16* asrc = Wp + (size_t)b*(C_*9*C_)
                                    + (size_t)(o0 + lrow)*2304 + st*256 + i0 + lhalf;
        uint32_t ad = aB + stg*ASTAGE_B + aOff;
        cp_async16(ad,      asrc,     16);
        cp_async16(ad + 16, asrc + 8, 16);

        int n  = n0 + tid;
        int yy = (n >> 6) + s - 1;
        int xx = (n & 63) + t - 1;
        int ok = (((unsigned)yy < HW_) && ((unsigned)xx < HW_)) ? 16 : 0;
        const __nv_bfloat16* bsrc = Xp + (((size_t)b*(HW_*HW_) + yy*HW_ + xx)*C_ + i0);
        uint32_t bd = bB + stg*BSTAGE_B + bOff;
#pragma unroll
        for (int j = 0; j < 4; ++j)
            cp_async16(bd + j*16, bsrc + j*8, ok);
        CP_COMMIT();
    };

    issue(0, 0);
    issue(1, 1);

    for (int c = 0; c < NCHUNK; ++c) {
        int stg = c % PIPE;
        CP_WAIT(PIPE-2);
        __syncthreads();

        const __nv_bfloat16* sAc = sA + stg*ASTAGE_E;
        const __nv_bfloat16* sBc = sB + stg*BSTAGE_E;
#pragma unroll
        for (int kk = 0; kk < 2; ++kk) {
            wmma::fragment<wmma::matrix_a, 16, 16, 16, __nv_bfloat16, wmma::row_major> af[4];
            wmma::fragment<wmma::matrix_b, 16, 16, 16, __nv_bfloat16, wmma::col_major> bfr[4];
#pragma unroll
            for (int i = 0; i < 4; ++i)
                wmma::load_matrix_sync(af[i],
                    sAc + (warp_m*64 + i*16)*AST + kk*16, AST);
#pragma unroll
            for (int j = 0; j < 4; ++j)
                wmma::load_matrix_sync(bfr[j],
                    sBc + (warp_n*64 + j*16)*AST + kk*16, AST);
#pragma unroll
            for (int i = 0; i < 4; ++i)
#pragma unroll
                for (int j = 0; j < 4; ++j)
                    wmma::mma_sync(acc[i][j], af[i], bfr[j], acc[i][j]);
        }

        if (c + PIPE - 1 < NCHUNK)
            issue(c + PIPE - 1, (c + PIPE - 1) % PIPE);
    }

    float* ob = out + ((size_t)b*C_ + o0 + warp_m*64)*(HW_*HW_) + n0 + warp_n*64;
#pragma unroll
    for (int i = 0; i < 4; ++i)
#pragma unroll
        for (int j = 0; j < 4; ++j)
            wmma::store_matrix_sync(ob + (size_t)i*16*(HW_*HW_) + j*16,
                                    acc[i][j], HW_*HW_, wmma::mem_row_major);
}

// ---------------- launch ----------------------------------------------------
extern "C" void kernel_launch(void* const* d_in, const int* in_sizes, int n_in,
                              void* d_out, int out_size) {
    const float* x    = (const float*)d_in[0];
    const float* dw   = (const float*)d_in[1];
    const float* katt = (const float*)d_in[2];
    const int*   fh   = (const int*)d_in[3];
    const int*   fw   = (const int*)d_in[4];
    float* out = (float*)d_out;

    cudaFuncSetAttribute(k_gemmA, cudaFuncAttributeMaxDynamicSharedMemorySize, SMEM_GEMM);
    cudaFuncSetAttribute(k_gemmB, cudaFuncAttributeMaxDynamicSharedMemorySize, SMEM_GEMM);
    cudaFuncSetAttribute(k_conv_wmma, cudaFuncAttributeMaxDynamicSharedMemorySize, SMEM_GEMM);

    k_setup  <<<1, 768>>>(katt);
    k_fillTA <<<(1536*1536 + 255)/256, 256>>>();
    k_fillTB <<<(D2*KB2 + 255)/256, 256>>>();
    k_scatter<<<(NF + 255)/256, 256>>>(dw, fh, fw);
    k_xsplit <<<dim3(HW_*HW_/32, C_/32, B_), dim3(32, 8)>>>(x);

    k_gemmA<<<dim3(QPAD/256, 1536/128, KN_), 256, SMEM_GEMM>>>();
    k_yconv<<<(KN_*D1*D2R + 255)/256, 256>>>();
    k_gemmB<<<dim3(D2/256, (KN_*D1)/128, 1), 256, SMEM_GEMM>>>();

    k_combine_bf16<<<(B_*C_*C_*9)/256, 256>>>();
    k_conv_wmma   <<<dim3(HW_*HW_/256, C_/128, B_), 256, SMEM_GEMM>>>(out);
}

// round 8
// speedup vs baseline: 1.3567x; 1.3567x over previous
#include <cuda_runtime.h>
#include <cuda_bf16.h>
#include <cuda_fp16.h>
#include <mma.h>
#include <math.h>
#include <stdint.h>

using namespace nvcuda;

#define D1 768
#define D2 768
#define D2R 385
#define NF (D1*D2R)     // 295680
#define KN_ 4
#define B_ 8
#define C_ 256
#define HW_ 64

// GEMM layout constants
#define QPAD 512          // padded N for stage A (q dimension)
#define KB2  800          // padded K for stage B (770 -> 800)

// W scale: conv weights ~1e-9, lift into fp16 range
#define WSCALE 2147483648.0f          // 2^31
#define OSCALE 4.6566128730773926e-10f // 2^-31

// ---------------- scratch (static device globals; no allocation) ----------
__device__ float  g_att[B_*KN_];
__device__ float2 g_tw[D1];                 // (cos, sin) of 2*pi*j/768

// Stage A operands: A = stacked twiddles [1536][1536]; B = G^T [k][512][1536]
__device__ __align__(128) __nv_bfloat16 g_TA_hi[1536*1536];
__device__ __align__(128) __nv_bfloat16 g_TA_lo[1536*1536];
__device__ __align__(128) __nv_bfloat16 g_GT_hi[KN_*QPAD*1536];
__device__ __align__(128) __nv_bfloat16 g_GT_lo[KN_*QPAD*1536];
// Stage A output (fp32): [k][1536][512]  (rows 0..767 = Yr, 768..1535 = Yi)
__device__ __align__(128) float g_Ytmp[KN_*1536*QPAD];
// Stage B operands: A = scaled Y [3072][800]; B = irfft twiddles [768][800]
__device__ __align__(128) __nv_bfloat16 g_YA_hi[KN_*D1*KB2];
__device__ __align__(128) __nv_bfloat16 g_YA_lo[KN_*D1*KB2];
__device__ __align__(128) __nv_bfloat16 g_TB_hi[D2*KB2];
__device__ __align__(128) __nv_bfloat16 g_TB_lo[D2*KB2];
// spatial weights [k][m][t]
__device__ __align__(128) float g_S[KN_][D1*D2];

// fp16 hi/lo conv weights (scaled by 2^31), per batch, K-major:
// [b][o][st*256 + i]
__device__ __align__(128) __half g_Whi[B_*C_*9*C_];
__device__ __align__(128) __half g_Wlo[B_*C_*9*C_];
// fp16 input, channel-last: [b][pixel][i]
__device__ __align__(128) __half g_Xh[B_*HW_*HW_*C_];

// ============================ helpers ======================================
__device__ __forceinline__ uint32_t smem_u32(const void* p) {
    uint32_t a;
    asm("{ .reg .u64 t; cvta.to.shared.u64 t, %1; cvt.u32.u64 %0, t; }"
        : "=r"(a) : "l"(p));
    return a;
}
__device__ __forceinline__ void cp_async16(uint32_t dst, const void* src, int pbytes) {
    asm volatile("cp.async.cg.shared.global [%0], [%1], 16, %2;"
                 :: "r"(dst), "l"(src), "r"(pbytes));
}
#define CP_COMMIT() asm volatile("cp.async.commit_group;" ::: "memory")
#define CP_WAIT(N)  asm volatile("cp.async.wait_group %0;" :: "n"(N) : "memory")

__device__ __forceinline__ void bf16_split(float v, __nv_bfloat16& hi, __nv_bfloat16& lo) {
    hi = __float2bfloat16(v);
    lo = __float2bfloat16(v - __bfloat162float(hi));
}

// ---------------- setup: attention + twiddle table -------------------------
__global__ void k_setup(const float* __restrict__ katt) {
    int j = threadIdx.x;
    if (j < D1) {
        double ang = 2.0 * M_PI * (double)j / (double)D1;
        g_tw[j] = make_float2((float)cos(ang), (float)sin(ang));
    }
    if (j < B_*KN_) {
        g_att[j] = 0.5f / (1.0f + expf(-katt[j]));
    }
}

// ---------------- fill stage-A twiddle matrix (1536x1536) ------------------
__global__ void k_fillTA() {
    int id = blockIdx.x * 256 + threadIdx.x;
    if (id >= 1536*1536) return;
    int i = id / 1536;
    int j = id - i*1536;
    int m = (i < 768) ? i : i - 768;
    int p = (j < 768) ? j : j - 768;
    int idx = (m * p) % 768;
    float2 cs = g_tw[idx];
    float v = (i < 768) ? ((j < 768) ? cs.x : -cs.y)
                        : ((j < 768) ? cs.y :  cs.x);
    __nv_bfloat16 hi, lo; bf16_split(v, hi, lo);
    g_TA_hi[id] = hi; g_TA_lo[id] = lo;
}

// ---------------- fill stage-B twiddle matrix (768 x 800) ------------------
__global__ void k_fillTB() {
    int id = blockIdx.x * 256 + threadIdx.x;
    if (id >= D2*KB2) return;
    int t = id / KB2;
    int c = id - t*KB2;
    float v = 0.f;
    if (c < 385) {
        v = g_tw[(c * t) % 768].x;
    } else if (c < 770) {
        int q = c - 385;
        v = -g_tw[(q * t) % 768].y;
    }
    __nv_bfloat16 hi, lo; bf16_split(v, hi, lo);
    g_TB_hi[id] = hi; g_TB_lo[id] = lo;
}

// ---------------- scatter dft_weight into transposed G, bf16 hi/lo ---------
__global__ void k_scatter(const float* __restrict__ dw,
                          const int*   __restrict__ fh,
                          const int*   __restrict__ fw) {
    int n = blockIdx.x * 256 + threadIdx.x;
    if (n >= NF) return;
    int p = fh[n];
    int q = fw[n];
    const float2* dw2 = (const float2*)dw;
#pragma unroll
    for (int k = 0; k < KN_; ++k) {
        float2 v = dw2[(size_t)k*NF + n];
        size_t base = (size_t)k*(QPAD*1536) + (size_t)q*1536;
        __nv_bfloat16 hi, lo;
        bf16_split(v.x, hi, lo);
        g_GT_hi[base + p] = hi;       g_GT_lo[base + p] = lo;
        bf16_split(v.y, hi, lo);
        g_GT_hi[base + 768 + p] = hi; g_GT_lo[base + 768 + p] = lo;
    }
}

// ---------------- convert stage-A output -> stage-B A operand --------------
__global__ void k_yconv() {
    int id = blockIdx.x * 256 + threadIdx.x;
    if (id >= KN_*D1*D2R) return;
    int q = id % D2R;
    int r = id / D2R;          // k*768 + m
    int m = r % D1;
    int k = r / D1;
    const float* Yk = g_Ytmp + (size_t)k*(1536*QPAD);
    float yr = Yk[(size_t)m*QPAD + q];
    float yi = Yk[(size_t)(768 + m)*QPAD + q];
    bool edge = (q == 0) || (q == 384);
    float sc  = (edge ? 1.f : 2.f) * (1.f/((float)D1*(float)D2));
    yr *= sc;
    yi  = edge ? 0.f : yi*sc;
    size_t base = (size_t)r*KB2;
    __nv_bfloat16 hi, lo;
    bf16_split(yr, hi, lo);
    g_YA_hi[base + q] = hi;        g_YA_lo[base + q] = lo;
    bf16_split(yi, hi, lo);
    g_YA_hi[base + 385 + q] = hi;  g_YA_lo[base + 385 + q] = lo;
}

// ---------------- generic bf16 hi/lo 3-pass wmma GEMM body -----------------
// (unchanged from the 987us kernel)
#define AST 40

__device__ __forceinline__ void gemm_body(
    const __nv_bfloat16* Ah, const __nv_bfloat16* Al, int lda,
    const __nv_bfloat16* Bh, const __nv_bfloat16* Bl, int ldb,
    float* Cc, int ldc, int K32)
{
    __shared__ __nv_bfloat16 sA[2][128*AST];
    __shared__ __nv_bfloat16 sB[2][128*AST];

    int tid = threadIdx.x;
    int wid = tid >> 5;
    int warp_m = wid >> 2;
    int warp_n = wid & 3;
    int m0 = blockIdx.y * 128;
    int n0 = blockIdx.x * 128;

    int lrow  = tid >> 1;
    int lhalf = (tid & 1) << 4;

    uint32_t aBase[2] = { smem_u32(&sA[0][0]), smem_u32(&sA[1][0]) };
    uint32_t bBase[2] = { smem_u32(&sB[0][0]), smem_u32(&sB[1][0]) };
    uint32_t dOff = (uint32_t)(lrow*AST + lhalf) * 2;

    wmma::fragment<wmma::accumulator, 16, 16, 16, float> acc[4][2];
#pragma unroll
    for (int i = 0; i < 4; ++i)
#pragma unroll
        for (int j = 0; j < 2; ++j)
            wmma::fill_fragment(acc[i][j], 0.f);

    int nchunk = 3*K32;

    auto issue = [&](int c, int buf) {
        int pass = (c >= 2*K32) ? 2 : ((c >= K32) ? 1 : 0);
        int k0   = (c - pass*K32) * 32;
        const __nv_bfloat16* Ap = (pass == 2) ? Al : Ah;
        const __nv_bfloat16* Bp = (pass == 1) ? Bl : Bh;

        const __nv_bfloat16* asrc = Ap + (size_t)(m0 + lrow)*lda + k0 + lhalf;
        uint32_t ad = aBase[buf] + dOff;
        cp_async16(ad,      asrc,     16);
        cp_async16(ad + 16, asrc + 8, 16);

        const __nv_bfloat16* bsrc = Bp + (size_t)(n0 + lrow)*ldb + k0 + lhalf;
        uint32_t bd = bBase[buf] + dOff;
        cp_async16(bd,      bsrc,     16);
        cp_async16(bd + 16, bsrc + 8, 16);
        CP_COMMIT();
    };

    issue(0, 0);

    for (int c = 0; c < nchunk; ++c) {
        int buf = c & 1;
        if (c + 1 < nchunk) {
            issue(c + 1, (c + 1) & 1);
            CP_WAIT(1);
        } else {
            CP_WAIT(0);
        }
        __syncthreads();

#pragma unroll
        for (int kk = 0; kk < 2; ++kk) {
            wmma::fragment<wmma::matrix_a, 16, 16, 16, __nv_bfloat16, wmma::row_major> af[4];
            wmma::fragment<wmma::matrix_b, 16, 16, 16, __nv_bfloat16, wmma::col_major> bfr[2];
#pragma unroll
            for (int i = 0; i < 4; ++i)
                wmma::load_matrix_sync(af[i],
                    &sA[buf][(warp_m*64 + i*16)*AST + kk*16], AST);
#pragma unroll
            for (int j = 0; j < 2; ++j)
                wmma::load_matrix_sync(bfr[j],
                    &sB[buf][(warp_n*32 + j*16)*AST + kk*16], AST);
#pragma unroll
            for (int i = 0; i < 4; ++i)
#pragma unroll
                for (int j = 0; j < 2; ++j)
                    wmma::mma_sync(acc[i][j], af[i], bfr[j], acc[i][j]);
        }
        __syncthreads();
    }

    float* ob = Cc + (size_t)(m0 + warp_m*64)*ldc + n0 + warp_n*32;
#pragma unroll
    for (int i = 0; i < 4; ++i)
#pragma unroll
        for (int j = 0; j < 2; ++j)
            wmma::store_matrix_sync(ob + (size_t)i*16*ldc + j*16,
                                    acc[i][j], ldc, wmma::mem_row_major);
}

// Stage A: [Yr;Yi](1536 x 512) = TA(1536x1536) * G^T, per k (blockIdx.z)
__global__ void __launch_bounds__(256) k_gemmA() {
    int z = blockIdx.z;
    gemm_body(g_TA_hi, g_TA_lo, 1536,
              g_GT_hi + (size_t)z*(QPAD*1536), g_GT_lo + (size_t)z*(QPAD*1536), 1536,
              g_Ytmp + (size_t)z*(1536*QPAD), QPAD,
              1536/32);
}

// Stage B: S(3072 x 768) = YA(3072x800) * TB^T
__global__ void __launch_bounds__(256) k_gemmB() {
    gemm_body(g_YA_hi, g_YA_lo, KB2,
              g_TB_hi, g_TB_lo, KB2,
              &g_S[0][0], D2,
              KB2/32);
}

// ------- combine per-batch weights -> fp16 hi/lo (scaled 2^31), K-major ----
__global__ void k_combine_fp16() {
    int id = blockIdx.x * 256 + threadIdx.x;
    int i  = id & 255;
    int r  = id >> 8;          // (b*256+o)*9 + st
    int st = r % 9;
    int bo = r / 9;
    int o  = bo & 255;
    int b  = bo >> 8;
    int s = st / 3, tt = st % 3;
    int sidx = (o*3 + s)*D2 + i*3 + tt;
    float v = 0.f;
#pragma unroll
    for (int k = 0; k < KN_; ++k)
        v += g_att[b*KN_ + k] * g_S[k][sidx];
    v *= WSCALE;
    __half hi = __float2half(v);
    __half lo = __float2half(v - __half2float(hi));
    g_Whi[id] = hi;
    g_Wlo[id] = lo;
}

// ------------- x: convert to fp16 + transpose to channel-last --------------
__global__ void k_xsplit(const float* __restrict__ xin) {
    __shared__ float tile[32][33];
    int b  = blockIdx.z;
    int p0 = blockIdx.x * 32;
    int c0 = blockIdx.y * 32;
    int tx = threadIdx.x, ty = threadIdx.y;   // 32 x 8
#pragma unroll
    for (int j = 0; j < 4; ++j) {
        int ch = c0 + ty + j*8;
        tile[ty + j*8][tx] = xin[((size_t)b*C_ + ch)*(HW_*HW_) + p0 + tx];
    }
    __syncthreads();
#pragma unroll
    for (int j = 0; j < 4; ++j) {
        int p = p0 + ty + j*8;
        float v = tile[tx][ty + j*8];
        size_t oidx = ((size_t)b*(HW_*HW_) + p)*C_ + c0 + tx;
        g_Xh[oidx] = __float2half(v);
    }
}

// ---------------- wmma fp16 2-pass implicit-GEMM conv ----------------------
// out = (Whi + Wlo) * X, X single fp16. K = 2 passes x 9 taps x 8 chunks of 32.
#define NCHUNK 144

__global__ void __launch_bounds__(256) k_conv_wmma(float* __restrict__ out) {
    __shared__ __half sA[2][128*AST];
    __shared__ __half sB[2][128*AST];

    int tid = threadIdx.x;
    int wid = tid >> 5;
    int warp_m = wid >> 2;
    int warp_n = wid & 3;
    int b  = blockIdx.z;
    int o0 = blockIdx.y * 128;
    int n0 = blockIdx.x * 128;

    int lrow  = tid >> 1;
    int lhalf = (tid & 1) << 4;

    uint32_t aBase[2] = { smem_u32(&sA[0][0]), smem_u32(&sA[1][0]) };
    uint32_t bBase[2] = { smem_u32(&sB[0][0]), smem_u32(&sB[1][0]) };
    uint32_t aDst0 = (uint32_t)(lrow*AST + lhalf) * 2;
    uint32_t bDst0 = aDst0;

    wmma::fragment<wmma::accumulator, 16, 16, 16, float> acc[4][2];
#pragma unroll
    for (int i = 0; i < 4; ++i)
#pragma unroll
        for (int j = 0; j < 2; ++j)
            wmma::fill_fragment(acc[i][j], 0.f);

    auto issue = [&](int c, int buf) {
        int pass = c / 72;                 // 0: Whi, 1: Wlo
        int rem  = c % 72;
        int st   = rem >> 3;
        int i0   = (rem & 7) << 5;
        int s    = st / 3, t = st % 3;
        const __half* Wp = pass ? g_Wlo : g_Whi;

        const __half* asrc = Wp + (size_t)b*(C_*9*C_)
                             + (size_t)(o0 + lrow)*2304 + st*256 + i0 + lhalf;
        uint32_t ad = aBase[buf] + aDst0;
        cp_async16(ad,      asrc,     16);
        cp_async16(ad + 16, asrc + 8, 16);

        int n  = n0 + lrow;
        int yy = (n >> 6) + s - 1;
        int xx = (n & 63) + t - 1;
        int ok = (((unsigned)yy < HW_) && ((unsigned)xx < HW_)) ? 16 : 0;
        const __half* bsrc = g_Xh + (((size_t)b*(HW_*HW_) + yy*HW_ + xx)*C_
                                     + i0 + lhalf);
        uint32_t bd = bBase[buf] + bDst0;
        cp_async16(bd,      bsrc,     ok);
        cp_async16(bd + 16, bsrc + 8, ok);
        CP_COMMIT();
    };

    issue(0, 0);

    for (int c = 0; c < NCHUNK; ++c) {
        int buf = c & 1;
        if (c + 1 < NCHUNK) {
            issue(c + 1, (c + 1) & 1);
            CP_WAIT(1);
        } else {
            CP_WAIT(0);
        }
        __syncthreads();

#pragma unroll
        for (int kk = 0; kk < 2; ++kk) {
            wmma::fragment<wmma::matrix_a, 16, 16, 16, __half, wmma::row_major> af[4];
            wmma::fragment<wmma::matrix_b, 16, 16, 16, __half, wmma::col_major> bfr[2];
#pragma unroll
            for (int i = 0; i < 4; ++i)
                wmma::load_matrix_sync(af[i],
                    &sA[buf][(warp_m*64 + i*16)*AST + kk*16], AST);
#pragma unroll
            for (int j = 0; j < 2; ++j)
                wmma::load_matrix_sync(bfr[j],
                    &sB[buf][(warp_n*32 + j*16)*AST + kk*16], AST);
#pragma unroll
            for (int i = 0; i < 4; ++i)
#pragma unroll
                for (int j = 0; j < 2; ++j)
                    wmma::mma_sync(acc[i][j], af[i], bfr[j], acc[i][j]);
        }
        __syncthreads();
    }

    // epilogue: undo the 2^31 weight scale, then store
    float* ob = out + ((size_t)b*C_ + o0 + warp_m*64)*(HW_*HW_) + n0 + warp_n*32;
#pragma unroll
    for (int i = 0; i < 4; ++i)
#pragma unroll
        for (int j = 0; j < 2; ++j) {
#pragma unroll
            for (int e = 0; e < acc[i][j].num_elements; ++e)
                acc[i][j].x[e] *= OSCALE;
            wmma::store_matrix_sync(ob + (size_t)i*16*(HW_*HW_) + j*16,
                                    acc[i][j], HW_*HW_, wmma::mem_row_major);
        }
}

// ---------------- launch ----------------------------------------------------
extern "C" void kernel_launch(void* const* d_in, const int* in_sizes, int n_in,
                              void* d_out, int out_size) {
    const float* x    = (const float*)d_in[0];
    const float* dw   = (const float*)d_in[1];
    const float* katt = (const float*)d_in[2];
    const int*   fh   = (const int*)d_in[3];
    const int*   fw   = (const int*)d_in[4];
    float* out = (float*)d_out;

    k_setup  <<<1, 768>>>(katt);
    k_fillTA <<<(1536*1536 + 255)/256, 256>>>();
    k_fillTB <<<(D2*KB2 + 255)/256, 256>>>();
    k_scatter<<<(NF + 255)/256, 256>>>(dw, fh, fw);
    k_xsplit <<<dim3(HW_*HW_/32, C_/32, B_), dim3(32, 8)>>>(x);

    k_gemmA<<<dim3(QPAD/128, 1536/128, KN_), 256>>>();
    k_yconv<<<(KN_*D1*D2R + 255)/256, 256>>>();
    k_gemmB<<<dim3(D2/128, (KN_*D1)/128, 1), 256>>>();

    k_combine_fp16<<<(B_*C_*C_*9)/256, 256>>>();
    k_conv_wmma   <<<dim3(HW_*HW_/128, C_/128, B_), 256>>>(out);
}

// round 9
// speedup vs baseline: 1.5892x; 1.1714x over previous
#include <cuda_runtime.h>
#include <cuda_bf16.h>
#include <cuda_fp16.h>
#include <mma.h>
#include <math.h>
#include <stdint.h>

using namespace nvcuda;

#define D1 768
#define D2 768
#define D2R 385
#define NF (D1*D2R)     // 295680
#define KN_ 4
#define B_ 8
#define C_ 256
#define HW_ 64

// GEMM layout constants
#define QPAD 512          // padded N for stage A (q dimension)
#define KB2  800          // padded K for stage B (770 -> 800)

// scales
#define WSCALE 2147483648.0f            // 2^31  (conv weights)
#define OSCALE 4.6566128730773926e-10f  // 2^-31
#define GSCALE 1048576.0f               // 2^20  (freq-domain G)
#define SINV   1.1641532182693481e-10f  // 2^-33 (gemmB epilogue)

// ---------------- scratch (static device globals; no allocation) ----------
__device__ float  g_att[B_*KN_];
__device__ float2 g_tw[D1];                 // (cos, sin) of 2*pi*j/768

// Stage A operands: A = stacked twiddles [1536][1536] fp16 hi/lo;
// B = G^T [k][512][1536] single fp16 (scaled by 2^20)
__device__ __align__(128) __half g_TA_hi[1536*1536];
__device__ __align__(128) __half g_TA_lo[1536*1536];
__device__ __align__(128) __half g_GTh[KN_*QPAD*1536];
// Stage A output (fp32, = Y_true * 2^20): [k][1536][512]
__device__ __align__(128) float g_Ytmp[KN_*1536*QPAD];
// Stage B operands: A = scaled Y hi/lo [3072][800]; B = twiddles hi/lo [768][800]
__device__ __align__(128) __half g_YAh[KN_*D1*KB2];
__device__ __align__(128) __half g_YAl[KN_*D1*KB2];
__device__ __align__(128) __half g_TB_hi[D2*KB2];
__device__ __align__(128) __half g_TB_lo[D2*KB2];
// spatial weights [k][m][t]
__device__ __align__(128) float g_S[KN_][D1*D2];

// fp16 hi/lo conv weights (scaled by 2^31), per batch, K-major: [b][o][st*256+i]
__device__ __align__(128) __half g_Whi[B_*C_*9*C_];
__device__ __align__(128) __half g_Wlo[B_*C_*9*C_];
// fp16 input, channel-last: [b][pixel][i]
__device__ __align__(128) __half g_Xh[B_*HW_*HW_*C_];

// ============================ helpers ======================================
__device__ __forceinline__ uint32_t smem_u32(const void* p) {
    uint32_t a;
    asm("{ .reg .u64 t; cvta.to.shared.u64 t, %1; cvt.u32.u64 %0, t; }"
        : "=r"(a) : "l"(p));
    return a;
}
__device__ __forceinline__ void cp_async16(uint32_t dst, const void* src, int pbytes) {
    asm volatile("cp.async.cg.shared.global [%0], [%1], 16, %2;"
                 :: "r"(dst), "l"(src), "r"(pbytes));
}
#define CP_COMMIT() asm volatile("cp.async.commit_group;" ::: "memory")
#define CP_WAIT(N)  asm volatile("cp.async.wait_group %0;" :: "n"(N) : "memory")

__device__ __forceinline__ void h_split(float v, __half& hi, __half& lo) {
    hi = __float2half(v);
    lo = __float2half(v - __half2float(hi));
}

// ---------------- setup: attention + twiddle table -------------------------
__global__ void k_setup(const float* __restrict__ katt) {
    int j = threadIdx.x;
    if (j < D1) {
        double ang = 2.0 * M_PI * (double)j / (double)D1;
        g_tw[j] = make_float2((float)cos(ang), (float)sin(ang));
    }
    if (j < B_*KN_) {
        g_att[j] = 0.5f / (1.0f + expf(-katt[j]));
    }
}

// ---------------- fill stage-A twiddle matrix (1536x1536), fp16 hi/lo ------
__global__ void k_fillTA() {
    int id = blockIdx.x * 256 + threadIdx.x;
    if (id >= 1536*1536) return;
    int i = id / 1536;
    int j = id - i*1536;
    int m = (i < 768) ? i : i - 768;
    int p = (j < 768) ? j : j - 768;
    int idx = (m * p) % 768;
    float2 cs = g_tw[idx];
    float v = (i < 768) ? ((j < 768) ? cs.x : -cs.y)
                        : ((j < 768) ? cs.y :  cs.x);
    __half hi, lo; h_split(v, hi, lo);
    g_TA_hi[id] = hi; g_TA_lo[id] = lo;
}

// ---------------- fill stage-B twiddle matrix (768 x 800), fp16 hi/lo ------
__global__ void k_fillTB() {
    int id = blockIdx.x * 256 + threadIdx.x;
    if (id >= D2*KB2) return;
    int t = id / KB2;
    int c = id - t*KB2;
    float v = 0.f;
    if (c < 385) {
        v = g_tw[(c * t) % 768].x;
    } else if (c < 770) {
        int q = c - 385;
        v = -g_tw[(q * t) % 768].y;
    }
    __half hi, lo; h_split(v, hi, lo);
    g_TB_hi[id] = hi; g_TB_lo[id] = lo;
}

// ------- scatter dft_weight into transposed G (x 2^20), single fp16 --------
__global__ void k_scatter(const float* __restrict__ dw,
                          const int*   __restrict__ fh,
                          const int*   __restrict__ fw) {
    int n = blockIdx.x * 256 + threadIdx.x;
    if (n >= NF) return;
    int p = fh[n];
    int q = fw[n];
    const float2* dw2 = (const float2*)dw;
#pragma unroll
    for (int k = 0; k < KN_; ++k) {
        float2 v = dw2[(size_t)k*NF + n];
        size_t base = (size_t)k*(QPAD*1536) + (size_t)q*1536;
        g_GTh[base + p]       = __float2half(v.x * GSCALE);
        g_GTh[base + 768 + p] = __float2half(v.y * GSCALE);
    }
}

// --------- convert stage-A output -> stage-B A operand (hi/lo fp16) --------
// Ys = Ytmp * (edge?1:2)/72  == Y_true * fold * 2^33
__global__ void k_yconv() {
    int id = blockIdx.x * 256 + threadIdx.x;
    if (id >= KN_*D1*D2R) return;
    int q = id % D2R;
    int r = id / D2R;          // k*768 + m
    int m = r % D1;
    int k = r / D1;
    const float* Yk = g_Ytmp + (size_t)k*(1536*QPAD);
    float yr = Yk[(size_t)m*QPAD + q];
    float yi = Yk[(size_t)(768 + m)*QPAD + q];
    bool edge = (q == 0) || (q == 384);
    float sc  = (edge ? 1.f : 2.f) * (1.f/72.f);
    yr *= sc;
    yi  = edge ? 0.f : yi*sc;
    size_t base = (size_t)r*KB2;
    __half hi, lo;
    h_split(yr, hi, lo);
    g_YAh[base + q] = hi;        g_YAl[base + q] = lo;
    h_split(yi, hi, lo);
    g_YAh[base + 385 + q] = hi;  g_YAl[base + 385 + q] = lo;
}

// ---------------- generic fp16 multi-pass wmma GEMM body -------------------
// NP passes; pass p multiplies A<p> x B<p>. CTA 128x128, 8 warps of 64x32,
// double-buffered cp.async. Epilogue multiplies by osc.
#define AST 40

template<int NP>
__device__ __forceinline__ void gemm_body_h(
    const __half* A0, const __half* A1, const __half* A2, int lda,
    const __half* B0, const __half* B1, const __half* B2, int ldb,
    float* Cc, int ldc, int K32, float osc)
{
    __shared__ __half sA[2][128*AST];
    __shared__ __half sB[2][128*AST];

    int tid = threadIdx.x;
    int wid = tid >> 5;
    int warp_m = wid >> 2;
    int warp_n = wid & 3;
    int m0 = blockIdx.y * 128;
    int n0 = blockIdx.x * 128;

    int lrow  = tid >> 1;
    int lhalf = (tid & 1) << 4;

    uint32_t aBase[2] = { smem_u32(&sA[0][0]), smem_u32(&sA[1][0]) };
    uint32_t bBase[2] = { smem_u32(&sB[0][0]), smem_u32(&sB[1][0]) };
    uint32_t dOff = (uint32_t)(lrow*AST + lhalf) * 2;

    wmma::fragment<wmma::accumulator, 16, 16, 16, float> acc[4][2];
#pragma unroll
    for (int i = 0; i < 4; ++i)
#pragma unroll
        for (int j = 0; j < 2; ++j)
            wmma::fill_fragment(acc[i][j], 0.f);

    int nchunk = NP*K32;

    auto issue = [&](int c, int buf) {
        int pass = c / K32;
        int k0   = (c - pass*K32) * 32;
        const __half* Ap = (pass == 0) ? A0 : ((pass == 1) ? A1 : A2);
        const __half* Bp = (pass == 0) ? B0 : ((pass == 1) ? B1 : B2);

        const __half* asrc = Ap + (size_t)(m0 + lrow)*lda + k0 + lhalf;
        uint32_t ad = aBase[buf] + dOff;
        cp_async16(ad,      asrc,     16);
        cp_async16(ad + 16, asrc + 8, 16);

        const __half* bsrc = Bp + (size_t)(n0 + lrow)*ldb + k0 + lhalf;
        uint32_t bd = bBase[buf] + dOff;
        cp_async16(bd,      bsrc,     16);
        cp_async16(bd + 16, bsrc + 8, 16);
        CP_COMMIT();
    };

    issue(0, 0);

    for (int c = 0; c < nchunk; ++c) {
        int buf = c & 1;
        if (c + 1 < nchunk) {
            issue(c + 1, (c + 1) & 1);
            CP_WAIT(1);
        } else {
            CP_WAIT(0);
        }
        __syncthreads();

#pragma unroll
        for (int kk = 0; kk < 2; ++kk) {
            wmma::fragment<wmma::matrix_a, 16, 16, 16, __half, wmma::row_major> af[4];
            wmma::fragment<wmma::matrix_b, 16, 16, 16, __half, wmma::col_major> bfr[2];
#pragma unroll
            for (int i = 0; i < 4; ++i)
                wmma::load_matrix_sync(af[i],
                    &sA[buf][(warp_m*64 + i*16)*AST + kk*16], AST);
#pragma unroll
            for (int j = 0; j < 2; ++j)
                wmma::load_matrix_sync(bfr[j],
                    &sB[buf][(warp_n*32 + j*16)*AST + kk*16], AST);
#pragma unroll
            for (int i = 0; i < 4; ++i)
#pragma unroll
                for (int j = 0; j < 2; ++j)
                    wmma::mma_sync(acc[i][j], af[i], bfr[j], acc[i][j]);
        }
        __syncthreads();
    }

    float* ob = Cc + (size_t)(m0 + warp_m*64)*ldc + n0 + warp_n*32;
#pragma unroll
    for (int i = 0; i < 4; ++i)
#pragma unroll
        for (int j = 0; j < 2; ++j) {
#pragma unroll
            for (int e = 0; e < acc[i][j].num_elements; ++e)
                acc[i][j].x[e] *= osc;
            wmma::store_matrix_sync(ob + (size_t)i*16*ldc + j*16,
                                    acc[i][j], ldc, wmma::mem_row_major);
        }
}

// Stage A: [Yr;Yi](1536 x 512) = TA * G^T, per k. 2 passes: TAhi*G + TAlo*G.
__global__ void __launch_bounds__(256) k_gemmA() {
    int z = blockIdx.z;
    const __half* G = g_GTh + (size_t)z*(QPAD*1536);
    gemm_body_h<2>(g_TA_hi, g_TA_lo, g_TA_lo, 1536,
                   G, G, G, 1536,
                   g_Ytmp + (size_t)z*(1536*QPAD), QPAD,
                   1536/32, 1.f);
}

// Stage B: S(3072 x 768) = YA * TB^T. 3 passes: Yhi*TBhi + Ylo*TBhi + Yhi*TBlo.
__global__ void __launch_bounds__(256) k_gemmB() {
    gemm_body_h<3>(g_YAh, g_YAl, g_YAh, KB2,
                   g_TB_hi, g_TB_hi, g_TB_lo, KB2,
                   &g_S[0][0], D2,
                   KB2/32, SINV);
}

// ------- combine per-batch weights -> fp16 hi/lo (scaled 2^31), K-major ----
__global__ void k_combine_fp16() {
    int id = blockIdx.x * 256 + threadIdx.x;
    int i  = id & 255;
    int r  = id >> 8;          // (b*256+o)*9 + st
    int st = r % 9;
    int bo = r / 9;
    int o  = bo & 255;
    int b  = bo >> 8;
    int s = st / 3, tt = st % 3;
    int sidx = (o*3 + s)*D2 + i*3 + tt;
    float v = 0.f;
#pragma unroll
    for (int k = 0; k < KN_; ++k)
        v += g_att[b*KN_ + k] * g_S[k][sidx];
    v *= WSCALE;
    __half hi, lo; h_split(v, hi, lo);
    g_Whi[id] = hi;
    g_Wlo[id] = lo;
}

// ------------- x: convert to fp16 + transpose to channel-last --------------
__global__ void k_xsplit(const float* __restrict__ xin) {
    __shared__ float tile[32][33];
    int b  = blockIdx.z;
    int p0 = blockIdx.x * 32;
    int c0 = blockIdx.y * 32;
    int tx = threadIdx.x, ty = threadIdx.y;   // 32 x 8
#pragma unroll
    for (int j = 0; j < 4; ++j) {
        int ch = c0 + ty + j*8;
        tile[ty + j*8][tx] = xin[((size_t)b*C_ + ch)*(HW_*HW_) + p0 + tx];
    }
    __syncthreads();
#pragma unroll
    for (int j = 0; j < 4; ++j) {
        int p = p0 + ty + j*8;
        float v = tile[tx][ty + j*8];
        size_t oidx = ((size_t)b*(HW_*HW_) + p)*C_ + c0 + tx;
        g_Xh[oidx] = __float2half(v);
    }
}

// ---------------- wmma fp16 2-pass implicit-GEMM conv ----------------------
#define NCHUNK 144

__global__ void __launch_bounds__(256) k_conv_wmma(float* __restrict__ out) {
    __shared__ __half sA[2][128*AST];
    __shared__ __half sB[2][128*AST];

    int tid = threadIdx.x;
    int wid = tid >> 5;
    int warp_m = wid >> 2;
    int warp_n = wid & 3;
    int b  = blockIdx.z;
    int o0 = blockIdx.y * 128;
    int n0 = blockIdx.x * 128;

    int lrow  = tid >> 1;
    int lhalf = (tid & 1) << 4;

    uint32_t aBase[2] = { smem_u32(&sA[0][0]), smem_u32(&sA[1][0]) };
    uint32_t bBase[2] = { smem_u32(&sB[0][0]), smem_u32(&sB[1][0]) };
    uint32_t aDst0 = (uint32_t)(lrow*AST + lhalf) * 2;
    uint32_t bDst0 = aDst0;

    wmma::fragment<wmma::accumulator, 16, 16, 16, float> acc[4][2];
#pragma unroll
    for (int i = 0; i < 4; ++i)
#pragma unroll
        for (int j = 0; j < 2; ++j)
            wmma::fill_fragment(acc[i][j], 0.f);

    auto issue = [&](int c, int buf) {
        int pass = c / 72;                 // 0: Whi, 1: Wlo
        int rem  = c % 72;
        int st   = rem >> 3;
        int i0   = (rem & 7) << 5;
        int s    = st / 3, t = st % 3;
        const __half* Wp = pass ? g_Wlo : g_Whi;

        const __half* asrc = Wp + (size_t)b*(C_*9*C_)
                             + (size_t)(o0 + lrow)*2304 + st*256 + i0 + lhalf;
        uint32_t ad = aBase[buf] + aDst0;
        cp_async16(ad,      asrc,     16);
        cp_async16(ad + 16, asrc + 8, 16);

        int n  = n0 + lrow;
        int yy = (n >> 6) + s - 1;
        int xx = (n & 63) + t - 1;
        int ok = (((unsigned)yy < HW_) && ((unsigned)xx < HW_)) ? 16 : 0;
        const __half* bsrc = g_Xh + (((size_t)b*(HW_*HW_) + yy*HW_ + xx)*C_
                                     + i0 + lhalf);
        uint32_t bd = bBase[buf] + bDst0;
        cp_async16(bd,      bsrc,     ok);
        cp_async16(bd + 16, bsrc + 8, ok);
        CP_COMMIT();
    };

    issue(0, 0);

    for (int c = 0; c < NCHUNK; ++c) {
        int buf = c & 1;
        if (c + 1 < NCHUNK) {
            issue(c + 1, (c + 1) & 1);
            CP_WAIT(1);
        } else {
            CP_WAIT(0);
        }
        __syncthreads();

#pragma unroll
        for (int kk = 0; kk < 2; ++kk) {
            wmma::fragment<wmma::matrix_a, 16, 16, 16, __half, wmma::row_major> af[4];
            wmma::fragment<wmma::matrix_b, 16, 16, 16, __half, wmma::col_major> bfr[2];
#pragma unroll
            for (int i = 0; i < 4; ++i)
                wmma::load_matrix_sync(af[i],
                    &sA[buf][(warp_m*64 + i*16)*AST + kk*16], AST);
#pragma unroll
            for (int j = 0; j < 2; ++j)
                wmma::load_matrix_sync(bfr[j],
                    &sB[buf][(warp_n*32 + j*16)*AST + kk*16], AST);
#pragma unroll
            for (int i = 0; i < 4; ++i)
#pragma unroll
                for (int j = 0; j < 2; ++j)
                    wmma::mma_sync(acc[i][j], af[i], bfr[j], acc[i][j]);
        }
        __syncthreads();
    }

    float* ob = out + ((size_t)b*C_ + o0 + warp_m*64)*(HW_*HW_) + n0 + warp_n*32;
#pragma unroll
    for (int i = 0; i < 4; ++i)
#pragma unroll
        for (int j = 0; j < 2; ++j) {
#pragma unroll
            for (int e = 0; e < acc[i][j].num_elements; ++e)
                acc[i][j].x[e] *= OSCALE;
            wmma::store_matrix_sync(ob + (size_t)i*16*(HW_*HW_) + j*16,
                                    acc[i][j], HW_*HW_, wmma::mem_row_major);
        }
}

// ---------------- launch ----------------------------------------------------
extern "C" void kernel_launch(void* const* d_in, const int* in_sizes, int n_in,
                              void* d_out, int out_size) {
    const float* x    = (const float*)d_in[0];
    const float* dw   = (const float*)d_in[1];
    const float* katt = (const float*)d_in[2];
    const int*   fh   = (const int*)d_in[3];
    const int*   fw   = (const int*)d_in[4];
    float* out = (float*)d_out;

    k_setup  <<<1, 768>>>(katt);
    k_fillTA <<<(1536*1536 + 255)/256, 256>>>();
    k_fillTB <<<(D2*KB2 + 255)/256, 256>>>();
    k_scatter<<<(NF + 255)/256, 256>>>(dw, fh, fw);
    k_xsplit <<<dim3(HW_*HW_/32, C_/32, B_), dim3(32, 8)>>>(x);

    k_gemmA<<<dim3(QPAD/128, 1536/128, KN_), 256>>>();
    k_yconv<<<(KN_*D1*D2R + 255)/256, 256>>>();
    k_gemmB<<<dim3(D2/128, (KN_*D1)/128, 1), 256>>>();

    k_combine_fp16<<<(B_*C_*C_*9)/256, 256>>>();
    k_conv_wmma   <<<dim3(HW_*HW_/128, C_/128, B_), 256>>>(out);
}

// round 10
// speedup vs baseline: 2.7560x; 1.7342x over previous
#include <cuda_runtime.h>
#include <cuda_bf16.h>
#include <cuda_fp16.h>
#include <mma.h>
#include <math.h>
#include <stdint.h>

using namespace nvcuda;

#define D1 768
#define D2 768
#define D2R 385
#define NF (D1*D2R)     // 295680
#define KN_ 4
#define B_ 8
#define C_ 256
#define HW_ 64

// GEMM layout constants
#define QPAD 512          // padded N for stage A (q dimension)
#define KB2  800          // padded K for stage B (770 -> 800)

// scales
#define WSCALE 2147483648.0f            // 2^31  (conv weights)
#define OSCALE 4.6566128730773926e-10f  // 2^-31
#define GSCALE 1048576.0f               // 2^20  (freq-domain G)
#define SINV   1.1641532182693481e-10f  // 2^-33 (gemmB epilogue)

// ---------------- scratch (static device globals; no allocation) ----------
__device__ float  g_att[B_*KN_];
__device__ float2 g_tw[D1];                 // (cos, sin) of 2*pi*j/768

// Stage A operands: A = stacked twiddles [1536][1536] single fp16;
// B = G^T [k][512][1536] single fp16 (scaled by 2^20)
__device__ __align__(128) __half g_TAh[1536*1536];
__device__ __align__(128) __half g_GTh[KN_*QPAD*1536];
// Stage A output (fp32, = Y_true * 2^20): [k][1536][512]
__device__ __align__(128) float g_Ytmp[KN_*1536*QPAD];
// Stage B operands: A = scaled Y hi/lo [3072][800]; B = twiddles hi/lo [768][800]
__device__ __align__(128) __half g_YAh[KN_*D1*KB2];
__device__ __align__(128) __half g_YAl[KN_*D1*KB2];
__device__ __align__(128) __half g_TB_hi[D2*KB2];
__device__ __align__(128) __half g_TB_lo[D2*KB2];
// spatial weights [k][m][t]
__device__ __align__(128) float g_S[KN_][D1*D2];

// single fp16 conv weights (scaled by 2^31), per batch, K-major: [b][o][st*256+i]
__device__ __align__(128) __half g_Wh[B_*C_*9*C_];
// fp16 input, channel-last: [b][pixel][i]
__device__ __align__(128) __half g_Xh[B_*HW_*HW_*C_];

// ============================ helpers ======================================
__device__ __forceinline__ uint32_t smem_u32(const void* p) {
    uint32_t a;
    asm("{ .reg .u64 t; cvta.to.shared.u64 t, %1; cvt.u32.u64 %0, t; }"
        : "=r"(a) : "l"(p));
    return a;
}
__device__ __forceinline__ void cp_async16(uint32_t dst, const void* src, int pbytes) {
    asm volatile("cp.async.cg.shared.global [%0], [%1], 16, %2;"
                 :: "r"(dst), "l"(src), "r"(pbytes));
}
#define CP_COMMIT() asm volatile("cp.async.commit_group;" ::: "memory")
#define CP_WAIT(N)  asm volatile("cp.async.wait_group %0;" :: "n"(N) : "memory")

__device__ __forceinline__ void h_split(float v, __half& hi, __half& lo) {
    hi = __float2half(v);
    lo = __float2half(v - __half2float(hi));
}

// ---------------- setup: attention + twiddle table -------------------------
__global__ void k_setup(const float* __restrict__ katt) {
    int j = threadIdx.x;
    if (j < D1) {
        double ang = 2.0 * M_PI * (double)j / (double)D1;
        g_tw[j] = make_float2((float)cos(ang), (float)sin(ang));
    }
    if (j < B_*KN_) {
        g_att[j] = 0.5f / (1.0f + expf(-katt[j]));
    }
}

// ---------------- fill stage-A twiddle matrix (1536x1536), single fp16 -----
__global__ void k_fillTA() {
    int id = blockIdx.x * 256 + threadIdx.x;
    if (id >= 1536*1536) return;
    int i = id / 1536;
    int j = id - i*1536;
    int m = (i < 768) ? i : i - 768;
    int p = (j < 768) ? j : j - 768;
    int idx = (m * p) % 768;
    float2 cs = g_tw[idx];
    float v = (i < 768) ? ((j < 768) ? cs.x : -cs.y)
                        : ((j < 768) ? cs.y :  cs.x);
    g_TAh[id] = __float2half(v);
}

// ---------------- fill stage-B twiddle matrix (768 x 800), fp16 hi/lo ------
__global__ void k_fillTB() {
    int id = blockIdx.x * 256 + threadIdx.x;
    if (id >= D2*KB2) return;
    int t = id / KB2;
    int c = id - t*KB2;
    float v = 0.f;
    if (c < 385) {
        v = g_tw[(c * t) % 768].x;
    } else if (c < 770) {
        int q = c - 385;
        v = -g_tw[(q * t) % 768].y;
    }
    __half hi, lo; h_split(v, hi, lo);
    g_TB_hi[id] = hi; g_TB_lo[id] = lo;
}

// ------- scatter dft_weight into transposed G (x 2^20), single fp16 --------
__global__ void k_scatter(const float* __restrict__ dw,
                          const int*   __restrict__ fh,
                          const int*   __restrict__ fw) {
    int n = blockIdx.x * 256 + threadIdx.x;
    if (n >= NF) return;
    int p = fh[n];
    int q = fw[n];
    const float2* dw2 = (const float2*)dw;
#pragma unroll
    for (int k = 0; k < KN_; ++k) {
        float2 v = dw2[(size_t)k*NF + n];
        size_t base = (size_t)k*(QPAD*1536) + (size_t)q*1536;
        g_GTh[base + p]       = __float2half(v.x * GSCALE);
        g_GTh[base + 768 + p] = __float2half(v.y * GSCALE);
    }
}

// --------- convert stage-A output -> stage-B A operand (hi/lo fp16) --------
// Ys = Ytmp * (edge?1:2)/72  == Y_true * fold * 2^33
__global__ void k_yconv() {
    int id = blockIdx.x * 256 + threadIdx.x;
    if (id >= KN_*D1*D2R) return;
    int q = id % D2R;
    int r = id / D2R;          // k*768 + m
    int m = r % D1;
    int k = r / D1;
    const float* Yk = g_Ytmp + (size_t)k*(1536*QPAD);
    float yr = Yk[(size_t)m*QPAD + q];
    float yi = Yk[(size_t)(768 + m)*QPAD + q];
    bool edge = (q == 0) || (q == 384);
    float sc  = (edge ? 1.f : 2.f) * (1.f/72.f);
    yr *= sc;
    yi  = edge ? 0.f : yi*sc;
    size_t base = (size_t)r*KB2;
    __half hi, lo;
    h_split(yr, hi, lo);
    g_YAh[base + q] = hi;        g_YAl[base + q] = lo;
    h_split(yi, hi, lo);
    g_YAh[base + 385 + q] = hi;  g_YAl[base + 385 + q] = lo;
}

// ---------------- generic fp16 multi-pass wmma GEMM body -------------------
#define AST 40

template<int NP>
__device__ __forceinline__ void gemm_body_h(
    const __half* A0, const __half* A1, const __half* A2, int lda,
    const __half* B0, const __half* B1, const __half* B2, int ldb,
    float* Cc, int ldc, int K32, float osc)
{
    __shared__ __half sA[2][128*AST];
    __shared__ __half sB[2][128*AST];

    int tid = threadIdx.x;
    int wid = tid >> 5;
    int warp_m = wid >> 2;
    int warp_n = wid & 3;
    int m0 = blockIdx.y * 128;
    int n0 = blockIdx.x * 128;

    int lrow  = tid >> 1;
    int lhalf = (tid & 1) << 4;

    uint32_t aBase[2] = { smem_u32(&sA[0][0]), smem_u32(&sA[1][0]) };
    uint32_t bBase[2] = { smem_u32(&sB[0][0]), smem_u32(&sB[1][0]) };
    uint32_t dOff = (uint32_t)(lrow*AST + lhalf) * 2;

    wmma::fragment<wmma::accumulator, 16, 16, 16, float> acc[4][2];
#pragma unroll
    for (int i = 0; i < 4; ++i)
#pragma unroll
        for (int j = 0; j < 2; ++j)
            wmma::fill_fragment(acc[i][j], 0.f);

    int nchunk = NP*K32;

    auto issue = [&](int c, int buf) {
        int pass = c / K32;
        int k0   = (c - pass*K32) * 32;
        const __half* Ap = (pass == 0) ? A0 : ((pass == 1) ? A1 : A2);
        const __half* Bp = (pass == 0) ? B0 : ((pass == 1) ? B1 : B2);

        const __half* asrc = Ap + (size_t)(m0 + lrow)*lda + k0 + lhalf;
        uint32_t ad = aBase[buf] + dOff;
        cp_async16(ad,      asrc,     16);
        cp_async16(ad + 16, asrc + 8, 16);

        const __half* bsrc = Bp + (size_t)(n0 + lrow)*ldb + k0 + lhalf;
        uint32_t bd = bBase[buf] + dOff;
        cp_async16(bd,      bsrc,     16);
        cp_async16(bd + 16, bsrc + 8, 16);
        CP_COMMIT();
    };

    issue(0, 0);

    for (int c = 0; c < nchunk; ++c) {
        int buf = c & 1;
        if (c + 1 < nchunk) {
            issue(c + 1, (c + 1) & 1);
            CP_WAIT(1);
        } else {
            CP_WAIT(0);
        }
        __syncthreads();

#pragma unroll
        for (int kk = 0; kk < 2; ++kk) {
            wmma::fragment<wmma::matrix_a, 16, 16, 16, __half, wmma::row_major> af[4];
            wmma::fragment<wmma::matrix_b, 16, 16, 16, __half, wmma::col_major> bfr[2];
#pragma unroll
            for (int i = 0; i < 4; ++i)
                wmma::load_matrix_sync(af[i],
                    &sA[buf][(warp_m*64 + i*16)*AST + kk*16], AST);
#pragma unroll
            for (int j = 0; j < 2; ++j)
                wmma::load_matrix_sync(bfr[j],
                    &sB[buf][(warp_n*32 + j*16)*AST + kk*16], AST);
#pragma unroll
            for (int i = 0; i < 4; ++i)
#pragma unroll
                for (int j = 0; j < 2; ++j)
                    wmma::mma_sync(acc[i][j], af[i], bfr[j], acc[i][j]);
        }
        __syncthreads();
    }

    float* ob = Cc + (size_t)(m0 + warp_m*64)*ldc + n0 + warp_n*32;
#pragma unroll
    for (int i = 0; i < 4; ++i)
#pragma unroll
        for (int j = 0; j < 2; ++j) {
#pragma unroll
            for (int e = 0; e < acc[i][j].num_elements; ++e)
                acc[i][j].x[e] *= osc;
            wmma::store_matrix_sync(ob + (size_t)i*16*ldc + j*16,
                                    acc[i][j], ldc, wmma::mem_row_major);
        }
}

// Stage A: [Yr;Yi](1536 x 512) = TA * G^T, per k. 1 pass (single fp16).
__global__ void __launch_bounds__(256) k_gemmA() {
    int z = blockIdx.z;
    const __half* G = g_GTh + (size_t)z*(QPAD*1536);
    gemm_body_h<1>(g_TAh, g_TAh, g_TAh, 1536,
                   G, G, G, 1536,
                   g_Ytmp + (size_t)z*(1536*QPAD), QPAD,
                   1536/32, 1.f);
}

// Stage B: S(3072 x 768) = YA * TB^T. 3 passes: Yhi*TBhi + Ylo*TBhi + Yhi*TBlo.
__global__ void __launch_bounds__(256) k_gemmB() {
    gemm_body_h<3>(g_YAh, g_YAl, g_YAh, KB2,
                   g_TB_hi, g_TB_hi, g_TB_lo, KB2,
                   &g_S[0][0], D2,
                   KB2/32, SINV);
}

// ------- combine per-batch weights -> single fp16 (scaled 2^31), K-major ---
__global__ void k_combine_fp16() {
    int id = blockIdx.x * 256 + threadIdx.x;
    int i  = id & 255;
    int r  = id >> 8;          // (b*256+o)*9 + st
    int st = r % 9;
    int bo = r / 9;
    int o  = bo & 255;
    int b  = bo >> 8;
    int s = st / 3, tt = st % 3;
    int sidx = (o*3 + s)*D2 + i*3 + tt;
    float v = 0.f;
#pragma unroll
    for (int k = 0; k < KN_; ++k)
        v += g_att[b*KN_ + k] * g_S[k][sidx];
    g_Wh[id] = __float2half(v * WSCALE);
}

// ------------- x: convert to fp16 + transpose to channel-last --------------
__global__ void k_xsplit(const float* __restrict__ xin) {
    __shared__ float tile[32][33];
    int b  = blockIdx.z;
    int p0 = blockIdx.x * 32;
    int c0 = blockIdx.y * 32;
    int tx = threadIdx.x, ty = threadIdx.y;   // 32 x 8
#pragma unroll
    for (int j = 0; j < 4; ++j) {
        int ch = c0 + ty + j*8;
        tile[ty + j*8][tx] = xin[((size_t)b*C_ + ch)*(HW_*HW_) + p0 + tx];
    }
    __syncthreads();
#pragma unroll
    for (int j = 0; j < 4; ++j) {
        int p = p0 + ty + j*8;
        float v = tile[tx][ty + j*8];
        size_t oidx = ((size_t)b*(HW_*HW_) + p)*C_ + c0 + tx;
        g_Xh[oidx] = __float2half(v);
    }
}

// ---------------- wmma fp16 single-pass implicit-GEMM conv -----------------
// out = W * X, both single fp16. K = 9 taps x 8 chunks of 32 = 72 chunks.
#define NCHUNK 72

__global__ void __launch_bounds__(256) k_conv_wmma(float* __restrict__ out) {
    __shared__ __half sA[2][128*AST];
    __shared__ __half sB[2][128*AST];

    int tid = threadIdx.x;
    int wid = tid >> 5;
    int warp_m = wid >> 2;
    int warp_n = wid & 3;
    int b  = blockIdx.z;
    int o0 = blockIdx.y * 128;
    int n0 = blockIdx.x * 128;

    int lrow  = tid >> 1;
    int lhalf = (tid & 1) << 4;

    uint32_t aBase[2] = { smem_u32(&sA[0][0]), smem_u32(&sA[1][0]) };
    uint32_t bBase[2] = { smem_u32(&sB[0][0]), smem_u32(&sB[1][0]) };
    uint32_t aDst0 = (uint32_t)(lrow*AST + lhalf) * 2;
    uint32_t bDst0 = aDst0;

    wmma::fragment<wmma::accumulator, 16, 16, 16, float> acc[4][2];
#pragma unroll
    for (int i = 0; i < 4; ++i)
#pragma unroll
        for (int j = 0; j < 2; ++j)
            wmma::fill_fragment(acc[i][j], 0.f);

    auto issue = [&](int c, int buf) {
        int st   = c >> 3;
        int i0   = (c & 7) << 5;
        int s    = st / 3, t = st % 3;

        const __half* asrc = g_Wh + (size_t)b*(C_*9*C_)
                             + (size_t)(o0 + lrow)*2304 + st*256 + i0 + lhalf;
        uint32_t ad = aBase[buf] + aDst0;
        cp_async16(ad,      asrc,     16);
        cp_async16(ad + 16, asrc + 8, 16);

        int n  = n0 + lrow;
        int yy = (n >> 6) + s - 1;
        int xx = (n & 63) + t - 1;
        int ok = (((unsigned)yy < HW_) && ((unsigned)xx < HW_)) ? 16 : 0;
        const __half* bsrc = g_Xh + (((size_t)b*(HW_*HW_) + yy*HW_ + xx)*C_
                                     + i0 + lhalf);
        uint32_t bd = bBase[buf] + bDst0;
        cp_async16(bd,      bsrc,     ok);
        cp_async16(bd + 16, bsrc + 8, ok);
        CP_COMMIT();
    };

    issue(0, 0);

    for (int c = 0; c < NCHUNK; ++c) {
        int buf = c & 1;
        if (c + 1 < NCHUNK) {
            issue(c + 1, (c + 1) & 1);
            CP_WAIT(1);
        } else {
            CP_WAIT(0);
        }
        __syncthreads();

#pragma unroll
        for (int kk = 0; kk < 2; ++kk) {
            wmma::fragment<wmma::matrix_a, 16, 16, 16, __half, wmma::row_major> af[4];
            wmma::fragment<wmma::matrix_b, 16, 16, 16, __half, wmma::col_major> bfr[2];
#pragma unroll
            for (int i = 0; i < 4; ++i)
                wmma::load_matrix_sync(af[i],
                    &sA[buf][(warp_m*64 + i*16)*AST + kk*16], AST);
#pragma unroll
            for (int j = 0; j < 2; ++j)
                wmma::load_matrix_sync(bfr[j],
                    &sB[buf][(warp_n*32 + j*16)*AST + kk*16], AST);
#pragma unroll
            for (int i = 0; i < 4; ++i)
#pragma unroll
                for (int j = 0; j < 2; ++j)
                    wmma::mma_sync(acc[i][j], af[i], bfr[j], acc[i][j]);
        }
        __syncthreads();
    }

    float* ob = out + ((size_t)b*C_ + o0 + warp_m*64)*(HW_*HW_) + n0 + warp_n*32;
#pragma unroll
    for (int i = 0; i < 4; ++i)
#pragma unroll
        for (int j = 0; j < 2; ++j) {
#pragma unroll
            for (int e = 0; e < acc[i][j].num_elements; ++e)
                acc[i][j].x[e] *= OSCALE;
            wmma::store_matrix_sync(ob + (size_t)i*16*(HW_*HW_) + j*16,
                                    acc[i][j], HW_*HW_, wmma::mem_row_major);
        }
}

// ---------------- launch ----------------------------------------------------
extern "C" void kernel_launch(void* const* d_in, const int* in_sizes, int n_in,
                              void* d_out, int out_size) {
    const float* x    = (const float*)d_in[0];
    const float* dw   = (const float*)d_in[1];
    const float* katt = (const float*)d_in[2];
    const int*   fh   = (const int*)d_in[3];
    const int*   fw   = (const int*)d_in[4];
    float* out = (float*)d_out;

    k_setup  <<<1, 768>>>(katt);
    k_fillTA <<<(1536*1536 + 255)/256, 256>>>();
    k_fillTB <<<(D2*KB2 + 255)/256, 256>>>();
    k_scatter<<<(NF + 255)/256, 256>>>(dw, fh, fw);
    k_xsplit <<<dim3(HW_*HW_/32, C_/32, B_), dim3(32, 8)>>>(x);

    k_gemmA<<<dim3(QPAD/128, 1536/128, KN_), 256>>>();
    k_yconv<<<(KN_*D1*D2R + 255)/256, 256>>>();
    k_gemmB<<<dim3(D2/128, (KN_*D1)/128, 1), 256>>>();

    k_combine_fp16<<<(B_*C_*C_*9)/256, 256>>>();
    k_conv_wmma   <<<dim3(HW_*HW_/128, C_/128, B_), 256>>>(out);
}

// round 11
// speedup vs baseline: 3.0696x; 1.1138x over previous
#include <cuda_runtime.h>
#include <cuda_bf16.h>
#include <cuda_fp16.h>
#include <mma.h>
#include <math.h>
#include <stdint.h>

using namespace nvcuda;

#define D1 768
#define D2 768
#define D2R 385
#define NF (D1*D2R)     // 295680
#define KN_ 4
#define B_ 8
#define C_ 256
#define HW_ 64

// GEMM layout constants
#define QPAD 512          // padded N for stage A (q dimension)
#define KB2  800          // padded K for stage B (770 -> 800)

// scales
#define WSCALE 2147483648.0f            // 2^31  (conv weights)
#define OSCALE 4.6566128730773926e-10f  // 2^-31
#define GSCALE 1048576.0f               // 2^20  (freq-domain G)
#define SINV   1.1641532182693481e-10f  // 2^-33 (gemmB epilogue; 2^20/(72*2^33)=1/768^2)

// ---------------- scratch (static device globals; no allocation) ----------
__device__ float  g_att[B_*KN_];
__device__ float2 g_tw[D1];                 // (cos, sin) of 2*pi*j/768

// Stage A operands: A = stacked twiddles [1536][1536] single fp16;
// B = G^T [k][512][1536] single fp16 (scaled by 2^20)
__device__ __align__(128) __half g_TAh[1536*1536];
__device__ __align__(128) __half g_GTh[KN_*QPAD*1536];
// Stage A output (fp32, = Y_true * 2^20): [k][1536][512]
__device__ __align__(128) float g_Ytmp[KN_*1536*QPAD];
// Stage B operands: A = scaled Y [3072][800] fp16; B = twiddles [768][800] fp16
__device__ __align__(128) __half g_YAh[KN_*D1*KB2];
__device__ __align__(128) __half g_TBh[D2*KB2];
// spatial weights [k][m][t]
__device__ __align__(128) float g_S[KN_][D1*D2];

// single fp16 conv weights (scaled by 2^31), per batch, K-major: [b][o][st*256+i]
__device__ __align__(128) __half g_Wh[B_*C_*9*C_];
// fp16 input, channel-last: [b][pixel][i]
__device__ __align__(128) __half g_Xh[B_*HW_*HW_*C_];

// ============================ helpers ======================================
__device__ __forceinline__ uint32_t smem_u32(const void* p) {
    uint32_t a;
    asm("{ .reg .u64 t; cvta.to.shared.u64 t, %1; cvt.u32.u64 %0, t; }"
        : "=r"(a) : "l"(p));
    return a;
}
__device__ __forceinline__ void cp_async16(uint32_t dst, const void* src, int pbytes) {
    asm volatile("cp.async.cg.shared.global [%0], [%1], 16, %2;"
                 :: "r"(dst), "l"(src), "r"(pbytes));
}
#define CP_COMMIT() asm volatile("cp.async.commit_group;" ::: "memory")
#define CP_WAIT(N)  asm volatile("cp.async.wait_group %0;" :: "n"(N) : "memory")

// ---------------- setup: attention + twiddle table -------------------------
__global__ void k_setup(const float* __restrict__ katt) {
    int j = threadIdx.x;
    if (j < D1) {
        double ang = 2.0 * M_PI * (double)j / (double)D1;
        g_tw[j] = make_float2((float)cos(ang), (float)sin(ang));
    }
    if (j < B_*KN_) {
        g_att[j] = 0.5f / (1.0f + expf(-katt[j]));
    }
}

// ---------------- fill stage-A twiddle matrix (1536x1536), single fp16 -----
__global__ void k_fillTA() {
    int id = blockIdx.x * 256 + threadIdx.x;
    if (id >= 1536*1536) return;
    int i = id / 1536;
    int j = id - i*1536;
    int m = (i < 768) ? i : i - 768;
    int p = (j < 768) ? j : j - 768;
    int idx = (m * p) % 768;
    float2 cs = g_tw[idx];
    float v = (i < 768) ? ((j < 768) ? cs.x : -cs.y)
                        : ((j < 768) ? cs.y :  cs.x);
    g_TAh[id] = __float2half(v);
}

// ---------------- fill stage-B twiddle matrix (768 x 800), single fp16 -----
__global__ void k_fillTB() {
    int id = blockIdx.x * 256 + threadIdx.x;
    if (id >= D2*KB2) return;
    int t = id / KB2;
    int c = id - t*KB2;
    float v = 0.f;
    if (c < 385) {
        v = g_tw[(c * t) % 768].x;
    } else if (c < 770) {
        int q = c - 385;
        v = -g_tw[(q * t) % 768].y;
    }
    g_TBh[id] = __float2half(v);
}

// ------- scatter dft_weight into transposed G (x 2^20), single fp16 --------
__global__ void k_scatter(const float* __restrict__ dw,
                          const int*   __restrict__ fh,
                          const int*   __restrict__ fw) {
    int n = blockIdx.x * 256 + threadIdx.x;
    if (n >= NF) return;
    int p = fh[n];
    int q = fw[n];
    const float2* dw2 = (const float2*)dw;
#pragma unroll
    for (int k = 0; k < KN_; ++k) {
        float2 v = dw2[(size_t)k*NF + n];
        size_t base = (size_t)k*(QPAD*1536) + (size_t)q*1536;
        g_GTh[base + p]       = __float2half(v.x * GSCALE);
        g_GTh[base + 768 + p] = __float2half(v.y * GSCALE);
    }
}

// --------- convert stage-A output -> stage-B A operand (single fp16) -------
// Ys = Ytmp * (edge?1:2)/72  == Y_true * fold * 2^33
__global__ void k_yconv() {
    int id = blockIdx.x * 256 + threadIdx.x;
    if (id >= KN_*D1*D2R) return;
    int q = id % D2R;
    int r = id / D2R;          // k*768 + m
    int m = r % D1;
    int k = r / D1;
    const float* Yk = g_Ytmp + (size_t)k*(1536*QPAD);
    float yr = Yk[(size_t)m*QPAD + q];
    float yi = Yk[(size_t)(768 + m)*QPAD + q];
    bool edge = (q == 0) || (q == 384);
    float sc  = (edge ? 1.f : 2.f) * (1.f/72.f);
    yr *= sc;
    yi  = edge ? 0.f : yi*sc;
    size_t base = (size_t)r*KB2;
    g_YAh[base + q]       = __float2half(yr);
    g_YAh[base + 385 + q] = __float2half(yi);
}

// ---------------- generic fp16 multi-pass wmma GEMM body -------------------
#define AST 40

template<int NP>
__device__ __forceinline__ void gemm_body_h(
    const __half* A0, const __half* A1, const __half* A2, int lda,
    const __half* B0, const __half* B1, const __half* B2, int ldb,
    float* Cc, int ldc, int K32, float osc)
{
    __shared__ __half sA[2][128*AST];
    __shared__ __half sB[2][128*AST];

    int tid = threadIdx.x;
    int wid = tid >> 5;
    int warp_m = wid >> 2;
    int warp_n = wid & 3;
    int m0 = blockIdx.y * 128;
    int n0 = blockIdx.x * 128;

    int lrow  = tid >> 1;
    int lhalf = (tid & 1) << 4;

    uint32_t aBase[2] = { smem_u32(&sA[0][0]), smem_u32(&sA[1][0]) };
    uint32_t bBase[2] = { smem_u32(&sB[0][0]), smem_u32(&sB[1][0]) };
    uint32_t dOff = (uint32_t)(lrow*AST + lhalf) * 2;

    wmma::fragment<wmma::accumulator, 16, 16, 16, float> acc[4][2];
#pragma unroll
    for (int i = 0; i < 4; ++i)
#pragma unroll
        for (int j = 0; j < 2; ++j)
            wmma::fill_fragment(acc[i][j], 0.f);

    int nchunk = NP*K32;

    auto issue = [&](int c, int buf) {
        int pass = c / K32;
        int k0   = (c - pass*K32) * 32;
        const __half* Ap = (pass == 0) ? A0 : ((pass == 1) ? A1 : A2);
        const __half* Bp = (pass == 0) ? B0 : ((pass == 1) ? B1 : B2);

        const __half* asrc = Ap + (size_t)(m0 + lrow)*lda + k0 + lhalf;
        uint32_t ad = aBase[buf] + dOff;
        cp_async16(ad,      asrc,     16);
        cp_async16(ad + 16, asrc + 8, 16);

        const __half* bsrc = Bp + (size_t)(n0 + lrow)*ldb + k0 + lhalf;
        uint32_t bd = bBase[buf] + dOff;
        cp_async16(bd,      bsrc,     16);
        cp_async16(bd + 16, bsrc + 8, 16);
        CP_COMMIT();
    };

    issue(0, 0);

    for (int c = 0; c < nchunk; ++c) {
        int buf = c & 1;
        if (c + 1 < nchunk) {
            issue(c + 1, (c + 1) & 1);
            CP_WAIT(1);
        } else {
            CP_WAIT(0);
        }
        __syncthreads();

#pragma unroll
        for (int kk = 0; kk < 2; ++kk) {
            wmma::fragment<wmma::matrix_a, 16, 16, 16, __half, wmma::row_major> af[4];
            wmma::fragment<wmma::matrix_b, 16, 16, 16, __half, wmma::col_major> bfr[2];
#pragma unroll
            for (int i = 0; i < 4; ++i)
                wmma::load_matrix_sync(af[i],
                    &sA[buf][(warp_m*64 + i*16)*AST + kk*16], AST);
#pragma unroll
            for (int j = 0; j < 2; ++j)
                wmma::load_matrix_sync(bfr[j],
                    &sB[buf][(warp_n*32 + j*16)*AST + kk*16], AST);
#pragma unroll
            for (int i = 0; i < 4; ++i)
#pragma unroll
                for (int j = 0; j < 2; ++j)
                    wmma::mma_sync(acc[i][j], af[i], bfr[j], acc[i][j]);
        }
        __syncthreads();
    }

    float* ob = Cc + (size_t)(m0 + warp_m*64)*ldc + n0 + warp_n*32;
#pragma unroll
    for (int i = 0; i < 4; ++i)
#pragma unroll
        for (int j = 0; j < 2; ++j) {
#pragma unroll
            for (int e = 0; e < acc[i][j].num_elements; ++e)
                acc[i][j].x[e] *= osc;
            wmma::store_matrix_sync(ob + (size_t)i*16*ldc + j*16,
                                    acc[i][j], ldc, wmma::mem_row_major);
        }
}

// Stage A: [Yr;Yi](1536 x 512) = TA * G^T, per k. 1 pass (single fp16).
__global__ void __launch_bounds__(256) k_gemmA() {
    int z = blockIdx.z;
    const __half* G = g_GTh + (size_t)z*(QPAD*1536);
    gemm_body_h<1>(g_TAh, g_TAh, g_TAh, 1536,
                   G, G, G, 1536,
                   g_Ytmp + (size_t)z*(1536*QPAD), QPAD,
                   1536/32, 1.f);
}

// Stage B: S(3072 x 768) = YA * TB^T. 1 pass (single fp16).
__global__ void __launch_bounds__(256) k_gemmB() {
    gemm_body_h<1>(g_YAh, g_YAh, g_YAh, KB2,
                   g_TBh, g_TBh, g_TBh, KB2,
                   &g_S[0][0], D2,
                   KB2/32, SINV);
}

// ------- combine per-batch weights -> single fp16 (scaled 2^31), K-major ---
__global__ void k_combine_fp16() {
    int id = blockIdx.x * 256 + threadIdx.x;
    int i  = id & 255;
    int r  = id >> 8;          // (b*256+o)*9 + st
    int st = r % 9;
    int bo = r / 9;
    int o  = bo & 255;
    int b  = bo >> 8;
    int s = st / 3, tt = st % 3;
    int sidx = (o*3 + s)*D2 + i*3 + tt;
    float v = 0.f;
#pragma unroll
    for (int k = 0; k < KN_; ++k)
        v += g_att[b*KN_ + k] * g_S[k][sidx];
    g_Wh[id] = __float2half(v * WSCALE);
}

// ------------- x: convert to fp16 + transpose to channel-last --------------
__global__ void k_xsplit(const float* __restrict__ xin) {
    __shared__ float tile[32][33];
    int b  = blockIdx.z;
    int p0 = blockIdx.x * 32;
    int c0 = blockIdx.y * 32;
    int tx = threadIdx.x, ty = threadIdx.y;   // 32 x 8
#pragma unroll
    for (int j = 0; j < 4; ++j) {
        int ch = c0 + ty + j*8;
        tile[ty + j*8][tx] = xin[((size_t)b*C_ + ch)*(HW_*HW_) + p0 + tx];
    }
    __syncthreads();
#pragma unroll
    for (int j = 0; j < 4; ++j) {
        int p = p0 + ty + j*8;
        float v = tile[tx][ty + j*8];
        size_t oidx = ((size_t)b*(HW_*HW_) + p)*C_ + c0 + tx;
        g_Xh[oidx] = __float2half(v);
    }
}

// ---------------- wmma fp16 single-pass implicit-GEMM conv -----------------
// out = W * X, both single fp16. K = 9 taps x 8 chunks of 32 = 72 chunks.
#define NCHUNK 72

__global__ void __launch_bounds__(256) k_conv_wmma(float* __restrict__ out) {
    __shared__ __half sA[2][128*AST];
    __shared__ __half sB[2][128*AST];

    int tid = threadIdx.x;
    int wid = tid >> 5;
    int warp_m = wid >> 2;
    int warp_n = wid & 3;
    int b  = blockIdx.z;
    int o0 = blockIdx.y * 128;
    int n0 = blockIdx.x * 128;

    int lrow  = tid >> 1;
    int lhalf = (tid & 1) << 4;

    uint32_t aBase[2] = { smem_u32(&sA[0][0]), smem_u32(&sA[1][0]) };
    uint32_t bBase[2] = { smem_u32(&sB[0][0]), smem_u32(&sB[1][0]) };
    uint32_t aDst0 = (uint32_t)(lrow*AST + lhalf) * 2;
    uint32_t bDst0 = aDst0;

    wmma::fragment<wmma::accumulator, 16, 16, 16, float> acc[4][2];
#pragma unroll
    for (int i = 0; i < 4; ++i)
#pragma unroll
        for (int j = 0; j < 2; ++j)
            wmma::fill_fragment(acc[i][j], 0.f);

    auto issue = [&](int c, int buf) {
        int st   = c >> 3;
        int i0   = (c & 7) << 5;
        int s    = st / 3, t = st % 3;

        const __half* asrc = g_Wh + (size_t)b*(C_*9*C_)
                             + (size_t)(o0 + lrow)*2304 + st*256 + i0 + lhalf;
        uint32_t ad = aBase[buf] + aDst0;
        cp_async16(ad,      asrc,     16);
        cp_async16(ad + 16, asrc + 8, 16);

        int n  = n0 + lrow;
        int yy = (n >> 6) + s - 1;
        int xx = (n & 63) + t - 1;
        int ok = (((unsigned)yy < HW_) && ((unsigned)xx < HW_)) ? 16 : 0;
        const __half* bsrc = g_Xh + (((size_t)b*(HW_*HW_) + yy*HW_ + xx)*C_
                                     + i0 + lhalf);
        uint32_t bd = bBase[buf] + bDst0;
        cp_async16(bd,      bsrc,     ok);
        cp_async16(bd + 16, bsrc + 8, ok);
        CP_COMMIT();
    };

    issue(0, 0);

    for (int c = 0; c < NCHUNK; ++c) {
        int buf = c & 1;
        if (c + 1 < NCHUNK) {
            issue(c + 1, (c + 1) & 1);
            CP_WAIT(1);
        } else {
            CP_WAIT(0);
        }
        __syncthreads();

#pragma unroll
        for (int kk = 0; kk < 2; ++kk) {
            wmma::fragment<wmma::matrix_a, 16, 16, 16, __half, wmma::row_major> af[4];
            wmma::fragment<wmma::matrix_b, 16, 16, 16, __half, wmma::col_major> bfr[2];
#pragma unroll
            for (int i = 0; i < 4; ++i)
                wmma::load_matrix_sync(af[i],
                    &sA[buf][(warp_m*64 + i*16)*AST + kk*16], AST);
#pragma unroll
            for (int j = 0; j < 2; ++j)
                wmma::load_matrix_sync(bfr[j],
                    &sB[buf][(warp_n*32 + j*16)*AST + kk*16], AST);
#pragma unroll
            for (int i = 0; i < 4; ++i)
#pragma unroll
                for (int j = 0; j < 2; ++j)
                    wmma::mma_sync(acc[i][j], af[i], bfr[j], acc[i][j]);
        }
        __syncthreads();
    }

    float* ob = out + ((size_t)b*C_ + o0 + warp_m*64)*(HW_*HW_) + n0 + warp_n*32;
#pragma unroll
    for (int i = 0; i < 4; ++i)
#pragma unroll
        for (int j = 0; j < 2; ++j) {
#pragma unroll
            for (int e = 0; e < acc[i][j].num_elements; ++e)
                acc[i][j].x[e] *= OSCALE;
            wmma::store_matrix_sync(ob + (size_t)i*16*(HW_*HW_) + j*16,
                                    acc[i][j], HW_*HW_, wmma::mem_row_major);
        }
}

// ---------------- launch ----------------------------------------------------
extern "C" void kernel_launch(void* const* d_in, const int* in_sizes, int n_in,
                              void* d_out, int out_size) {
    const float* x    = (const float*)d_in[0];
    const float* dw   = (const float*)d_in[1];
    const float* katt = (const float*)d_in[2];
    const int*   fh   = (const int*)d_in[3];
    const int*   fw   = (const int*)d_in[4];
    float* out = (float*)d_out;

    k_setup  <<<1, 768>>>(katt);
    k_fillTA <<<(1536*1536 + 255)/256, 256>>>();
    k_fillTB <<<(D2*KB2 + 255)/256, 256>>>();
    k_scatter<<<(NF + 255)/256, 256>>>(dw, fh, fw);
    k_xsplit <<<dim3(HW_*HW_/32, C_/32, B_), dim3(32, 8)>>>(x);

    k_gemmA<<<dim3(QPAD/128, 1536/128, KN_), 256>>>();
    k_yconv<<<(KN_*D1*D2R + 255)/256, 256>>>();
    k_gemmB<<<dim3(D2/128, (KN_*D1)/128, 1), 256>>>();

    k_combine_fp16<<<(B_*C_*C_*9)/256, 256>>>();
    k_conv_wmma   <<<dim3(HW_*HW_/128, C_/128, B_), 256>>>(out);
}

// round 12
// speedup vs baseline: 3.2238x; 1.0502x over previous
#include <cuda_runtime.h>
#include <cuda_bf16.h>
#include <cuda_fp16.h>
#include <mma.h>
#include <math.h>
#include <stdint.h>

using namespace nvcuda;

#define D1 768
#define D2 768
#define D2R 385
#define NF (D1*D2R)     // 295680
#define KN_ 4
#define B_ 8
#define C_ 256
#define HW_ 64

// GEMM layout constants
#define NPACK (KN_*D2R)   // 1540: all k-planes packed in N
#define NPAD  1664        // 13 x 128 tiles
#define KB2   800         // padded K for stage B (770 -> 800)

// scales
#define WSCALE 2147483648.0f            // 2^31  (conv weights)
#define OSCALE 4.6566128730773926e-10f  // 2^-31
#define GSCALE 1048576.0f               // 2^20  (freq-domain G)
#define SINV   1.1641532182693481e-10f  // 2^-33 (gemmB epilogue; 2^20/(72*2^33)=1/768^2)

// ---------------- scratch (static device globals; no allocation) ----------
__device__ float  g_att[B_*KN_];
__device__ float2 g_tw[D1];                 // (cos, sin) of 2*pi*j/768

// Stage A: A = interleaved twiddles [1536][1536] fp16
//   row i<768 (Yr_m): col 2p = cos(mp), col 2p+1 = -sin(mp)
//   row i>=768 (Yi_m): col 2p = sin(mp), col 2p+1 =  cos(mp)
// B = G packed [n = k*385+q][1536] fp16, cols interleaved (Gr_p, Gi_p)
__device__ __align__(128) __half g_TAh[1536*1536];
__device__ __align__(128) __half g_GTh[NPAD*1536];   // rows >=1540 stay zero
// Stage A output (fp32, = Y_true * 2^20): [1536][NPAD]
__device__ __align__(128) float g_Ytmp[1536*NPAD];
// Stage B operands: A = scaled Y [3072][800] fp16; B = twiddles [768][800] fp16
__device__ __align__(128) __half g_YAh[KN_*D1*KB2];
__device__ __align__(128) __half g_TBh[D2*KB2];
// spatial weights [k][m][t]
__device__ __align__(128) float g_S[KN_][D1*D2];

// single fp16 conv weights (scaled by 2^31), per batch, K-major: [b][o][st*256+i]
__device__ __align__(128) __half g_Wh[B_*C_*9*C_];
// fp16 input, channel-last: [b][pixel][i]
__device__ __align__(128) __half g_Xh[B_*HW_*HW_*C_];

// ============================ helpers ======================================
__device__ __forceinline__ uint32_t smem_u32(const void* p) {
    uint32_t a;
    asm("{ .reg .u64 t; cvta.to.shared.u64 t, %1; cvt.u32.u64 %0, t; }"
        : "=r"(a) : "l"(p));
    return a;
}
__device__ __forceinline__ void cp_async16(uint32_t dst, const void* src, int pbytes) {
    asm volatile("cp.async.cg.shared.global [%0], [%1], 16, %2;"
                 :: "r"(dst), "l"(src), "r"(pbytes));
}
#define CP_COMMIT() asm volatile("cp.async.commit_group;" ::: "memory")
#define CP_WAIT(N)  asm volatile("cp.async.wait_group %0;" :: "n"(N) : "memory")

// ---------------- setup: attention + twiddle table -------------------------
__global__ void k_setup(const float* __restrict__ katt) {
    int j = threadIdx.x;
    if (j < D1) {
        double ang = 2.0 * M_PI * (double)j / (double)D1;
        g_tw[j] = make_float2((float)cos(ang), (float)sin(ang));
    }
    if (j < B_*KN_) {
        g_att[j] = 0.5f / (1.0f + expf(-katt[j]));
    }
}

// ------- fill stage-A twiddle matrix (1536x1536), interleaved cols ---------
__global__ void k_fillTA() {
    int id = blockIdx.x * 256 + threadIdx.x;
    if (id >= 1536*1536) return;
    int i = id / 1536;
    int j = id - i*1536;
    int p = j >> 1;
    int m = (i < 768) ? i : i - 768;
    int idx = (m * p) % 768;
    float2 cs = g_tw[idx];
    float v = (i < 768) ? (((j & 1) == 0) ? cs.x : -cs.y)
                        : (((j & 1) == 0) ? cs.y :  cs.x);
    g_TAh[id] = __float2half(v);
}

// ---------------- fill stage-B twiddle matrix (768 x 800), single fp16 -----
__global__ void k_fillTB() {
    int id = blockIdx.x * 256 + threadIdx.x;
    if (id >= D2*KB2) return;
    int t = id / KB2;
    int c = id - t*KB2;
    float v = 0.f;
    if (c < 385) {
        v = g_tw[(c * t) % 768].x;
    } else if (c < 770) {
        int q = c - 385;
        v = -g_tw[(q * t) % 768].y;
    }
    g_TBh[id] = __float2half(v);
}

// ------- scatter dft_weight into packed interleaved G (x 2^20) -------------
// one aligned 4B half2 store per (k, n)
__global__ void k_scatter(const float* __restrict__ dw,
                          const int*   __restrict__ fh,
                          const int*   __restrict__ fw) {
    int n = blockIdx.x * 256 + threadIdx.x;
    if (n >= NF) return;
    int p = fh[n];
    int q = fw[n];
    const float2* dw2 = (const float2*)dw;
#pragma unroll
    for (int k = 0; k < KN_; ++k) {
        float2 v = dw2[(size_t)k*NF + n];
        __half2 h = __floats2half2_rn(v.x * GSCALE, v.y * GSCALE);
        *(__half2*)&g_GTh[(size_t)(k*D2R + q)*1536 + 2*p] = h;
    }
}

// --------- convert stage-A output -> stage-B A operand (single fp16) -------
// Ys = Ytmp * (edge?1:2)/72  == Y_true * fold * 2^33
__global__ void k_yconv() {
    int id = blockIdx.x * 256 + threadIdx.x;
    if (id >= KN_*D1*D2R) return;
    int q = id % D2R;
    int r = id / D2R;          // k*768 + m
    int m = r % D1;
    int k = r / D1;
    int col = k*D2R + q;
    float yr = g_Ytmp[(size_t)m*NPAD + col];
    float yi = g_Ytmp[(size_t)(768 + m)*NPAD + col];
    bool edge = (q == 0) || (q == 384);
    float sc  = (edge ? 1.f : 2.f) * (1.f/72.f);
    yr *= sc;
    yi  = edge ? 0.f : yi*sc;
    size_t base = (size_t)r*KB2;
    g_YAh[base + q]       = __float2half(yr);
    g_YAh[base + 385 + q] = __float2half(yi);
}

// ---------------- generic fp16 single-pass wmma GEMM body ------------------
#define AST 40

__device__ __forceinline__ void gemm_body_h(
    const __half* A0, int lda,
    const __half* B0, int ldb,
    float* Cc, int ldc, int K32, float osc)
{
    __shared__ __half sA[2][128*AST];
    __shared__ __half sB[2][128*AST];

    int tid = threadIdx.x;
    int wid = tid >> 5;
    int warp_m = wid >> 2;
    int warp_n = wid & 3;
    int m0 = blockIdx.y * 128;
    int n0 = blockIdx.x * 128;

    int lrow  = tid >> 1;
    int lhalf = (tid & 1) << 4;

    uint32_t aBase[2] = { smem_u32(&sA[0][0]), smem_u32(&sA[1][0]) };
    uint32_t bBase[2] = { smem_u32(&sB[0][0]), smem_u32(&sB[1][0]) };
    uint32_t dOff = (uint32_t)(lrow*AST + lhalf) * 2;

    wmma::fragment<wmma::accumulator, 16, 16, 16, float> acc[4][2];
#pragma unroll
    for (int i = 0; i < 4; ++i)
#pragma unroll
        for (int j = 0; j < 2; ++j)
            wmma::fill_fragment(acc[i][j], 0.f);

    auto issue = [&](int c, int buf) {
        int k0 = c * 32;
        const __half* asrc = A0 + (size_t)(m0 + lrow)*lda + k0 + lhalf;
        uint32_t ad = aBase[buf] + dOff;
        cp_async16(ad,      asrc,     16);
        cp_async16(ad + 16, asrc + 8, 16);

        const __half* bsrc = B0 + (size_t)(n0 + lrow)*ldb + k0 + lhalf;
        uint32_t bd = bBase[buf] + dOff;
        cp_async16(bd,      bsrc,     16);
        cp_async16(bd + 16, bsrc + 8, 16);
        CP_COMMIT();
    };

    issue(0, 0);

    for (int c = 0; c < K32; ++c) {
        int buf = c & 1;
        if (c + 1 < K32) {
            issue(c + 1, (c + 1) & 1);
            CP_WAIT(1);
        } else {
            CP_WAIT(0);
        }
        __syncthreads();

#pragma unroll
        for (int kk = 0; kk < 2; ++kk) {
            wmma::fragment<wmma::matrix_a, 16, 16, 16, __half, wmma::row_major> af[4];
            wmma::fragment<wmma::matrix_b, 16, 16, 16, __half, wmma::col_major> bfr[2];
#pragma unroll
            for (int i = 0; i < 4; ++i)
                wmma::load_matrix_sync(af[i],
                    &sA[buf][(warp_m*64 + i*16)*AST + kk*16], AST);
#pragma unroll
            for (int j = 0; j < 2; ++j)
                wmma::load_matrix_sync(bfr[j],
                    &sB[buf][(warp_n*32 + j*16)*AST + kk*16], AST);
#pragma unroll
            for (int i = 0; i < 4; ++i)
#pragma unroll
                for (int j = 0; j < 2; ++j)
                    wmma::mma_sync(acc[i][j], af[i], bfr[j], acc[i][j]);
        }
        __syncthreads();
    }

    float* ob = Cc + (size_t)(m0 + warp_m*64)*ldc + n0 + warp_n*32;
#pragma unroll
    for (int i = 0; i < 4; ++i)
#pragma unroll
        for (int j = 0; j < 2; ++j) {
#pragma unroll
            for (int e = 0; e < acc[i][j].num_elements; ++e)
                acc[i][j].x[e] *= osc;
            wmma::store_matrix_sync(ob + (size_t)i*16*ldc + j*16,
                                    acc[i][j], ldc, wmma::mem_row_major);
        }
}

// Stage A: Y(1536 x 1664) = TA(1536x1536) * G^T (all k packed in N)
__global__ void __launch_bounds__(256) k_gemmA() {
    gemm_body_h(g_TAh, 1536, g_GTh, 1536, g_Ytmp, NPAD, 1536/32, 1.f);
}

// Stage B: S(3072 x 768) = YA * TB^T
__global__ void __launch_bounds__(256) k_gemmB() {
    gemm_body_h(g_YAh, KB2, g_TBh, KB2, &g_S[0][0], D2, KB2/32, SINV);
}

// ------- combine per-batch weights -> single fp16 (scaled 2^31), K-major ---
// block = (b, o, s): stage the 768-float S row through smem (coalesced reads),
// each thread emits 3 taps (tt) for its i (coalesced writes).
__global__ void __launch_bounds__(256) k_combine_fp16() {
    __shared__ float srow[768];
    int blk = blockIdx.x;
    int s = blk % 3;
    int o = (blk / 3) & 255;
    int b = blk / (3*256);
    int tid = threadIdx.x;

    int row = (o*3 + s) * D2;
    float a0 = g_att[b*KN_ + 0];
    float a1 = g_att[b*KN_ + 1];
    float a2 = g_att[b*KN_ + 2];
    float a3 = g_att[b*KN_ + 3];
#pragma unroll
    for (int rep = 0; rep < 3; ++rep) {
        int t = tid + rep*256;
        srow[t] = a0*g_S[0][row + t] + a1*g_S[1][row + t]
                + a2*g_S[2][row + t] + a3*g_S[3][row + t];
    }
    __syncthreads();

    size_t obase = ((size_t)(b*256 + o)*9 + s*3) * 256 + tid;
#pragma unroll
    for (int tt = 0; tt < 3; ++tt)
        g_Wh[obase + (size_t)tt*256] = __float2half(srow[tid*3 + tt] * WSCALE);
}

// ------------- x: convert to fp16 + transpose to channel-last --------------
__global__ void k_xsplit(const float* __restrict__ xin) {
    __shared__ float tile[32][33];
    int b  = blockIdx.z;
    int p0 = blockIdx.x * 32;
    int c0 = blockIdx.y * 32;
    int tx = threadIdx.x, ty = threadIdx.y;   // 32 x 8
#pragma unroll
    for (int j = 0; j < 4; ++j) {
        int ch = c0 + ty + j*8;
        tile[ty + j*8][tx] = xin[((size_t)b*C_ + ch)*(HW_*HW_) + p0 + tx];
    }
    __syncthreads();
#pragma unroll
    for (int j = 0; j < 4; ++j) {
        int p = p0 + ty + j*8;
        float v = tile[tx][ty + j*8];
        size_t oidx = ((size_t)b*(HW_*HW_) + p)*C_ + c0 + tx;
        g_Xh[oidx] = __float2half(v);
    }
}

// ---------------- wmma fp16 single-pass implicit-GEMM conv -----------------
// out = W * X, both single fp16. K = 9 taps x 8 chunks of 32 = 72 chunks.
#define NCHUNK 72

__global__ void __launch_bounds__(256) k_conv_wmma(float* __restrict__ out) {
    __shared__ __half sA[2][128*AST];
    __shared__ __half sB[2][128*AST];

    int tid = threadIdx.x;
    int wid = tid >> 5;
    int warp_m = wid >> 2;
    int warp_n = wid & 3;
    int b  = blockIdx.z;
    int o0 = blockIdx.y * 128;
    int n0 = blockIdx.x * 128;

    int lrow  = tid >> 1;
    int lhalf = (tid & 1) << 4;

    uint32_t aBase[2] = { smem_u32(&sA[0][0]), smem_u32(&sA[1][0]) };
    uint32_t bBase[2] = { smem_u32(&sB[0][0]), smem_u32(&sB[1][0]) };
    uint32_t aDst0 = (uint32_t)(lrow*AST + lhalf) * 2;
    uint32_t bDst0 = aDst0;

    wmma::fragment<wmma::accumulator, 16, 16, 16, float> acc[4][2];
#pragma unroll
    for (int i = 0; i < 4; ++i)
#pragma unroll
        for (int j = 0; j < 2; ++j)
            wmma::fill_fragment(acc[i][j], 0.f);

    auto issue = [&](int c, int buf) {
        int st   = c >> 3;
        int i0   = (c & 7) << 5;
        int s    = st / 3, t = st % 3;

        const __half* asrc = g_Wh + (size_t)b*(C_*9*C_)
                             + (size_t)(o0 + lrow)*2304 + st*256 + i0 + lhalf;
        uint32_t ad = aBase[buf] + aDst0;
        cp_async16(ad,      asrc,     16);
        cp_async16(ad + 16, asrc + 8, 16);

        int n  = n0 + lrow;
        int yy = (n >> 6) + s - 1;
        int xx = (n & 63) + t - 1;
        int ok = (((unsigned)yy < HW_) && ((unsigned)xx < HW_)) ? 16 : 0;
        const __half* bsrc = g_Xh + (((size_t)b*(HW_*HW_) + yy*HW_ + xx)*C_
                                     + i0 + lhalf);
        uint32_t bd = bBase[buf] + bDst0;
        cp_async16(bd,      bsrc,     ok);
        cp_async16(bd + 16, bsrc + 8, ok);
        CP_COMMIT();
    };

    issue(0, 0);

    for (int c = 0; c < NCHUNK; ++c) {
        int buf = c & 1;
        if (c + 1 < NCHUNK) {
            issue(c + 1, (c + 1) & 1);
            CP_WAIT(1);
        } else {
            CP_WAIT(0);
        }
        __syncthreads();

#pragma unroll
        for (int kk = 0; kk < 2; ++kk) {
            wmma::fragment<wmma::matrix_a, 16, 16, 16, __half, wmma::row_major> af[4];
            wmma::fragment<wmma::matrix_b, 16, 16, 16, __half, wmma::col_major> bfr[2];
#pragma unroll
            for (int i = 0; i < 4; ++i)
                wmma::load_matrix_sync(af[i],
                    &sA[buf][(warp_m*64 + i*16)*AST + kk*16], AST);
#pragma unroll
            for (int j = 0; j < 2; ++j)
                wmma::load_matrix_sync(bfr[j],
                    &sB[buf][(warp_n*32 + j*16)*AST + kk*16], AST);
#pragma unroll
            for (int i = 0; i < 4; ++i)
#pragma unroll
                for (int j = 0; j < 2; ++j)
                    wmma::mma_sync(acc[i][j], af[i], bfr[j], acc[i][j]);
        }
        __syncthreads();
    }

    float* ob = out + ((size_t)b*C_ + o0 + warp_m*64)*(HW_*HW_) + n0 + warp_n*32;
#pragma unroll
    for (int i = 0; i < 4; ++i)
#pragma unroll
        for (int j = 0; j < 2; ++j) {
#pragma unroll
            for (int e = 0; e < acc[i][j].num_elements; ++e)
                acc[i][j].x[e] *= OSCALE;
            wmma::store_matrix_sync(ob + (size_t)i*16*(HW_*HW_) + j*16,
                                    acc[i][j], HW_*HW_, wmma::mem_row_major);
        }
}

// ---------------- launch ----------------------------------------------------
extern "C" void kernel_launch(void* const* d_in, const int* in_sizes, int n_in,
                              void* d_out, int out_size) {
    const float* x    = (const float*)d_in[0];
    const float* dw   = (const float*)d_in[1];
    const float* katt = (const float*)d_in[2];
    const int*   fh   = (const int*)d_in[3];
    const int*   fw   = (const int*)d_in[4];
    float* out = (float*)d_out;

    k_setup  <<<1, 768>>>(katt);
    k_fillTA <<<(1536*1536 + 255)/256, 256>>>();
    k_fillTB <<<(D2*KB2 + 255)/256, 256>>>();
    k_scatter<<<(NF + 255)/256, 256>>>(dw, fh, fw);
    k_xsplit <<<dim3(HW_*HW_/32, C_/32, B_), dim3(32, 8)>>>(x);

    k_gemmA<<<dim3(NPAD/128, 1536/128, 1), 256>>>();
    k_yconv<<<(KN_*D1*D2R + 255)/256, 256>>>();
    k_gemmB<<<dim3(D2/128, (KN_*D1)/128, 1), 256>>>();

    k_combine_fp16<<<B_*C_*3, 256>>>();
    k_conv_wmma   <<<dim3(HW_*HW_/128, C_/128, B_), 256>>>(out);
}

// round 13
// speedup vs baseline: 3.6350x; 1.1276x over previous
#include <cuda_runtime.h>
#include <cuda_bf16.h>
#include <cuda_fp16.h>
#include <mma.h>
#include <math.h>
#include <stdint.h>

using namespace nvcuda;

#define D1 768
#define D2 768
#define D2R 385
#define NF (D1*D2R)     // 295680
#define KN_ 4
#define B_ 8
#define C_ 256
#define HW_ 64

// GEMM layout constants
#define NPACK (KN_*D2R)   // 1540: all k-planes packed in N
#define NPAD  1664        // 13 x 128 tiles
#define KB2   800         // padded K for stage B (770 -> 800)

// scales
#define WSCALE 2147483648.0f            // 2^31  (conv weights)
#define OSCALE 4.6566128730773926e-10f  // 2^-31
#define GSCALE 1048576.0f               // 2^20  (freq-domain G)
#define SINV   1.1641532182693481e-10f  // 2^-33 (gemmB epilogue; 2^20/(72*2^33)=1/768^2)

// pipeline constants
#define AST 40
#define PIPE 3
#define STG_E (128*AST)              // elements per operand stage (5120)
#define STG_B (STG_E*2)              // bytes (10240)
#define SMEM_PIPE (PIPE*2*STG_B)     // 61440 bytes

// ---------------- scratch (static device globals; no allocation) ----------
__device__ float  g_att[B_*KN_];
__device__ float2 g_tw[D1];                 // (cos, sin) of 2*pi*j/768

// Stage A: A = interleaved twiddles [1536][1536] fp16
//   row i<768 (Yr_m): col 2p = cos(mp), col 2p+1 = -sin(mp)
//   row i>=768 (Yi_m): col 2p = sin(mp), col 2p+1 =  cos(mp)
// B = G packed [n = k*385+q][1536] fp16, cols interleaved (Gr_p, Gi_p)
__device__ __align__(128) __half g_TAh[1536*1536];
__device__ __align__(128) __half g_GTh[NPAD*1536];   // rows >=1540 stay zero
// Stage A output (fp32, = Y_true * 2^20): [1536][NPAD]
__device__ __align__(128) float g_Ytmp[1536*NPAD];
// Stage B operands: A = scaled Y [3072][800] fp16; B = twiddles [768][800] fp16
__device__ __align__(128) __half g_YAh[KN_*D1*KB2];
__device__ __align__(128) __half g_TBh[D2*KB2];
// spatial weights [k][m][t]
__device__ __align__(128) float g_S[KN_][D1*D2];

// single fp16 conv weights (scaled by 2^31), per batch, K-major: [b][o][st*256+i]
__device__ __align__(128) __half g_Wh[B_*C_*9*C_];
// fp16 input, channel-last: [b][pixel][i]
__device__ __align__(128) __half g_Xh[B_*HW_*HW_*C_];

// ============================ helpers ======================================
__device__ __forceinline__ uint32_t smem_u32(const void* p) {
    uint32_t a;
    asm("{ .reg .u64 t; cvta.to.shared.u64 t, %1; cvt.u32.u64 %0, t; }"
        : "=r"(a) : "l"(p));
    return a;
}
__device__ __forceinline__ void cp_async16(uint32_t dst, const void* src, int pbytes) {
    asm volatile("cp.async.cg.shared.global [%0], [%1], 16, %2;"
                 :: "r"(dst), "l"(src), "r"(pbytes));
}
#define CP_COMMIT() asm volatile("cp.async.commit_group;" ::: "memory")
#define CP_WAIT(N)  asm volatile("cp.async.wait_group %0;" :: "n"(N) : "memory")

// ---------------- setup: attention + twiddle table -------------------------
__global__ void k_setup(const float* __restrict__ katt) {
    int j = threadIdx.x;
    if (j < D1) {
        double ang = 2.0 * M_PI * (double)j / (double)D1;
        g_tw[j] = make_float2((float)cos(ang), (float)sin(ang));
    }
    if (j < B_*KN_) {
        g_att[j] = 0.5f / (1.0f + expf(-katt[j]));
    }
}

// ------- fill stage-A twiddle matrix (1536x1536), interleaved cols ---------
__global__ void k_fillTA() {
    int id = blockIdx.x * 256 + threadIdx.x;
    if (id >= 1536*1536) return;
    int i = id / 1536;
    int j = id - i*1536;
    int p = j >> 1;
    int m = (i < 768) ? i : i - 768;
    int idx = (m * p) % 768;
    float2 cs = g_tw[idx];
    float v = (i < 768) ? (((j & 1) == 0) ? cs.x : -cs.y)
                        : (((j & 1) == 0) ? cs.y :  cs.x);
    g_TAh[id] = __float2half(v);
}

// ---------------- fill stage-B twiddle matrix (768 x 800), single fp16 -----
__global__ void k_fillTB() {
    int id = blockIdx.x * 256 + threadIdx.x;
    if (id >= D2*KB2) return;
    int t = id / KB2;
    int c = id - t*KB2;
    float v = 0.f;
    if (c < 385) {
        v = g_tw[(c * t) % 768].x;
    } else if (c < 770) {
        int q = c - 385;
        v = -g_tw[(q * t) % 768].y;
    }
    g_TBh[id] = __float2half(v);
}

// ------- scatter dft_weight into packed interleaved G (x 2^20) -------------
__global__ void k_scatter(const float* __restrict__ dw,
                          const int*   __restrict__ fh,
                          const int*   __restrict__ fw) {
    int n = blockIdx.x * 256 + threadIdx.x;
    if (n >= NF) return;
    int p = fh[n];
    int q = fw[n];
    const float2* dw2 = (const float2*)dw;
#pragma unroll
    for (int k = 0; k < KN_; ++k) {
        float2 v = dw2[(size_t)k*NF + n];
        __half2 h = __floats2half2_rn(v.x * GSCALE, v.y * GSCALE);
        *(__half2*)&g_GTh[(size_t)(k*D2R + q)*1536 + 2*p] = h;
    }
}

// --------- convert stage-A output -> stage-B A operand (single fp16) -------
__global__ void k_yconv() {
    int id = blockIdx.x * 256 + threadIdx.x;
    if (id >= KN_*D1*D2R) return;
    int q = id % D2R;
    int r = id / D2R;          // k*768 + m
    int m = r % D1;
    int k = r / D1;
    int col = k*D2R + q;
    float yr = g_Ytmp[(size_t)m*NPAD + col];
    float yi = g_Ytmp[(size_t)(768 + m)*NPAD + col];
    bool edge = (q == 0) || (q == 384);
    float sc  = (edge ? 1.f : 2.f) * (1.f/72.f);
    yr *= sc;
    yi  = edge ? 0.f : yi*sc;
    size_t base = (size_t)r*KB2;
    g_YAh[base + q]       = __float2half(yr);
    g_YAh[base + 385 + q] = __float2half(yi);
}

// ------- fp16 single-pass wmma GEMM body, 3-stage pipe, 1 sync/chunk -------
__device__ __forceinline__ void gemm_body_h(
    const __half* A0, int lda,
    const __half* B0, int ldb,
    float* Cc, int ldc, int K32, float osc)
{
    extern __shared__ __half dsm[];
    __half* sA = dsm;                 // PIPE stages of 128x40
    __half* sB = dsm + PIPE*STG_E;    // PIPE stages of 128x40

    int tid = threadIdx.x;
    int wid = tid >> 5;
    int warp_m = wid >> 2;
    int warp_n = wid & 3;
    int m0 = blockIdx.y * 128;
    int n0 = blockIdx.x * 128;

    int lrow  = tid >> 1;
    int lhalf = (tid & 1) << 4;

    uint32_t aB = smem_u32(sA);
    uint32_t bB = smem_u32(sB);
    uint32_t dOff = (uint32_t)(lrow*AST + lhalf) * 2;

    wmma::fragment<wmma::accumulator, 16, 16, 16, float> acc[4][2];
#pragma unroll
    for (int i = 0; i < 4; ++i)
#pragma unroll
        for (int j = 0; j < 2; ++j)
            wmma::fill_fragment(acc[i][j], 0.f);

    auto issue = [&](int c, int stg) {
        int k0 = c * 32;
        const __half* asrc = A0 + (size_t)(m0 + lrow)*lda + k0 + lhalf;
        uint32_t ad = aB + stg*STG_B + dOff;
        cp_async16(ad,      asrc,     16);
        cp_async16(ad + 16, asrc + 8, 16);

        const __half* bsrc = B0 + (size_t)(n0 + lrow)*ldb + k0 + lhalf;
        uint32_t bd = bB + stg*STG_B + dOff;
        cp_async16(bd,      bsrc,     16);
        cp_async16(bd + 16, bsrc + 8, 16);
        CP_COMMIT();
    };

    issue(0, 0);
    if (K32 > 1) issue(1, 1);

    for (int c = 0; c < K32; ++c) {
        if (c + 1 < K32) CP_WAIT(1);
        else             CP_WAIT(0);
        __syncthreads();

        int stg = c % PIPE;
        const __half* sAc = sA + stg*STG_E;
        const __half* sBc = sB + stg*STG_E;
#pragma unroll
        for (int kk = 0; kk < 2; ++kk) {
            wmma::fragment<wmma::matrix_a, 16, 16, 16, __half, wmma::row_major> af[4];
            wmma::fragment<wmma::matrix_b, 16, 16, 16, __half, wmma::col_major> bfr[2];
#pragma unroll
            for (int i = 0; i < 4; ++i)
                wmma::load_matrix_sync(af[i],
                    sAc + (warp_m*64 + i*16)*AST + kk*16, AST);
#pragma unroll
            for (int j = 0; j < 2; ++j)
                wmma::load_matrix_sync(bfr[j],
                    sBc + (warp_n*32 + j*16)*AST + kk*16, AST);
#pragma unroll
            for (int i = 0; i < 4; ++i)
#pragma unroll
                for (int j = 0; j < 2; ++j)
                    wmma::mma_sync(acc[i][j], af[i], bfr[j], acc[i][j]);
        }

        if (c + 2 < K32) issue(c + 2, (c + 2) % PIPE);
    }

    float* ob = Cc + (size_t)(m0 + warp_m*64)*ldc + n0 + warp_n*32;
#pragma unroll
    for (int i = 0; i < 4; ++i)
#pragma unroll
        for (int j = 0; j < 2; ++j) {
#pragma unroll
            for (int e = 0; e < acc[i][j].num_elements; ++e)
                acc[i][j].x[e] *= osc;
            wmma::store_matrix_sync(ob + (size_t)i*16*ldc + j*16,
                                    acc[i][j], ldc, wmma::mem_row_major);
        }
}

// Stage A: Y(1536 x 1664) = TA(1536x1536) * G^T (all k packed in N)
__global__ void __launch_bounds__(256) k_gemmA() {
    gemm_body_h(g_TAh, 1536, g_GTh, 1536, g_Ytmp, NPAD, 1536/32, 1.f);
}

// Stage B: S(3072 x 768) = YA * TB^T
__global__ void __launch_bounds__(256) k_gemmB() {
    gemm_body_h(g_YAh, KB2, g_TBh, KB2, &g_S[0][0], D2, KB2/32, SINV);
}

// ------- combine per-batch weights -> single fp16 (scaled 2^31), K-major ---
__global__ void __launch_bounds__(256) k_combine_fp16() {
    __shared__ float srow[768];
    int blk = blockIdx.x;
    int s = blk % 3;
    int o = (blk / 3) & 255;
    int b = blk / (3*256);
    int tid = threadIdx.x;

    int row = (o*3 + s) * D2;
    float a0 = g_att[b*KN_ + 0];
    float a1 = g_att[b*KN_ + 1];
    float a2 = g_att[b*KN_ + 2];
    float a3 = g_att[b*KN_ + 3];
#pragma unroll
    for (int rep = 0; rep < 3; ++rep) {
        int t = tid + rep*256;
        srow[t] = a0*g_S[0][row + t] + a1*g_S[1][row + t]
                + a2*g_S[2][row + t] + a3*g_S[3][row + t];
    }
    __syncthreads();

    size_t obase = ((size_t)(b*256 + o)*9 + s*3) * 256 + tid;
#pragma unroll
    for (int tt = 0; tt < 3; ++tt)
        g_Wh[obase + (size_t)tt*256] = __float2half(srow[tid*3 + tt] * WSCALE);
}

// ------------- x: convert to fp16 + transpose to channel-last --------------
__global__ void k_xsplit(const float* __restrict__ xin) {
    __shared__ float tile[32][33];
    int b  = blockIdx.z;
    int p0 = blockIdx.x * 32;
    int c0 = blockIdx.y * 32;
    int tx = threadIdx.x, ty = threadIdx.y;   // 32 x 8
#pragma unroll
    for (int j = 0; j < 4; ++j) {
        int ch = c0 + ty + j*8;
        tile[ty + j*8][tx] = xin[((size_t)b*C_ + ch)*(HW_*HW_) + p0 + tx];
    }
    __syncthreads();
#pragma unroll
    for (int j = 0; j < 4; ++j) {
        int p = p0 + ty + j*8;
        float v = tile[tx][ty + j*8];
        size_t oidx = ((size_t)b*(HW_*HW_) + p)*C_ + c0 + tx;
        g_Xh[oidx] = __float2half(v);
    }
}

// --------- wmma fp16 conv, 3-stage pipe, 1 sync/chunk ----------------------
// out = W * X. K = 9 taps x 8 chunks of 32 = 72 chunks.
#define NCHUNK 72

__global__ void __launch_bounds__(256) k_conv_wmma(float* __restrict__ out) {
    extern __shared__ __half dsm[];
    __half* sA = dsm;
    __half* sB = dsm + PIPE*STG_E;

    int tid = threadIdx.x;
    int wid = tid >> 5;
    int warp_m = wid >> 2;
    int warp_n = wid & 3;
    int b  = blockIdx.z;
    int o0 = blockIdx.y * 128;
    int n0 = blockIdx.x * 128;

    int lrow  = tid >> 1;
    int lhalf = (tid & 1) << 4;

    uint32_t aB = smem_u32(sA);
    uint32_t bB = smem_u32(sB);
    uint32_t dOff = (uint32_t)(lrow*AST + lhalf) * 2;

    wmma::fragment<wmma::accumulator, 16, 16, 16, float> acc[4][2];
#pragma unroll
    for (int i = 0; i < 4; ++i)
#pragma unroll
        for (int j = 0; j < 2; ++j)
            wmma::fill_fragment(acc[i][j], 0.f);

    auto issue = [&](int c, int stg) {
        int st   = c >> 3;
        int i0   = (c & 7) << 5;
        int s    = st / 3, t = st % 3;

        const __half* asrc = g_Wh + (size_t)b*(C_*9*C_)
                             + (size_t)(o0 + lrow)*2304 + st*256 + i0 + lhalf;
        uint32_t ad = aB + stg*STG_B + dOff;
        cp_async16(ad,      asrc,     16);
        cp_async16(ad + 16, asrc + 8, 16);

        int n  = n0 + lrow;
        int yy = (n >> 6) + s - 1;
        int xx = (n & 63) + t - 1;
        int ok = (((unsigned)yy < HW_) && ((unsigned)xx < HW_)) ? 16 : 0;
        const __half* bsrc = g_Xh + (((size_t)b*(HW_*HW_) + yy*HW_ + xx)*C_
                                     + i0 + lhalf);
        uint32_t bd = bB + stg*STG_B + dOff;
        cp_async16(bd,      bsrc,     ok);
        cp_async16(bd + 16, bsrc + 8, ok);
        CP_COMMIT();
    };

    issue(0, 0);
    issue(1, 1);

    for (int c = 0; c < NCHUNK; ++c) {
        if (c + 1 < NCHUNK) CP_WAIT(1);
        else                CP_WAIT(0);
        __syncthreads();

        int stg = c % PIPE;
        const __half* sAc = sA + stg*STG_E;
        const __half* sBc = sB + stg*STG_E;
#pragma unroll
        for (int kk = 0; kk < 2; ++kk) {
            wmma::fragment<wmma::matrix_a, 16, 16, 16, __half, wmma::row_major> af[4];
            wmma::fragment<wmma::matrix_b, 16, 16, 16, __half, wmma::col_major> bfr[2];
#pragma unroll
            for (int i = 0; i < 4; ++i)
                wmma::load_matrix_sync(af[i],
                    sAc + (warp_m*64 + i*16)*AST + kk*16, AST);
#pragma unroll
            for (int j = 0; j < 2; ++j)
                wmma::load_matrix_sync(bfr[j],
                    sBc + (warp_n*32 + j*16)*AST + kk*16, AST);
#pragma unroll
            for (int i = 0; i < 4; ++i)
#pragma unroll
                for (int j = 0; j < 2; ++j)
                    wmma::mma_sync(acc[i][j], af[i], bfr[j], acc[i][j]);
        }

        if (c + 2 < NCHUNK) issue(c + 2, (c + 2) % PIPE);
    }

    float* ob = out + ((size_t)b*C_ + o0 + warp_m*64)*(HW_*HW_) + n0 + warp_n*32;
#pragma unroll
    for (int i = 0; i < 4; ++i)
#pragma unroll
        for (int j = 0; j < 2; ++j) {
#pragma unroll
            for (int e = 0; e < acc[i][j].num_elements; ++e)
                acc[i][j].x[e] *= OSCALE;
            wmma::store_matrix_sync(ob + (size_t)i*16*(HW_*HW_) + j*16,
                                    acc[i][j], HW_*HW_, wmma::mem_row_major);
        }
}

// ---------------- launch ----------------------------------------------------
extern "C" void kernel_launch(void* const* d_in, const int* in_sizes, int n_in,
                              void* d_out, int out_size) {
    const float* x    = (const float*)d_in[0];
    const float* dw   = (const float*)d_in[1];
    const float* katt = (const float*)d_in[2];
    const int*   fh   = (const int*)d_in[3];
    const int*   fw   = (const int*)d_in[4];
    float* out = (float*)d_out;

    cudaFuncSetAttribute(k_gemmA, cudaFuncAttributeMaxDynamicSharedMemorySize, SMEM_PIPE);
    cudaFuncSetAttribute(k_gemmB, cudaFuncAttributeMaxDynamicSharedMemorySize, SMEM_PIPE);
    cudaFuncSetAttribute(k_conv_wmma, cudaFuncAttributeMaxDynamicSharedMemorySize, SMEM_PIPE);

    k_setup  <<<1, 768>>>(katt);
    k_fillTA <<<(1536*1536 + 255)/256, 256>>>();
    k_fillTB <<<(D2*KB2 + 255)/256, 256>>>();
    k_scatter<<<(NF + 255)/256, 256>>>(dw, fh, fw);
    k_xsplit <<<dim3(HW_*HW_/32, C_/32, B_), dim3(32, 8)>>>(x);

    k_gemmA<<<dim3(NPAD/128, 1536/128, 1), 256, SMEM_PIPE>>>();
    k_yconv<<<(KN_*D1*D2R + 255)/256, 256>>>();
    k_gemmB<<<dim3(D2/128, (KN_*D1)/128, 1), 256, SMEM_PIPE>>>();

    k_combine_fp16<<<B_*C_*3, 256>>>();
    k_conv_wmma   <<<dim3(HW_*HW_/128, C_/128, B_), 256, SMEM_PIPE>>>(out);
}

// round 14
// speedup vs baseline: 3.7759x; 1.0388x over previous
#include <cuda_runtime.h>
#include <cuda_bf16.h>
#include <cuda_fp16.h>
#include <mma.h>
#include <math.h>
#include <stdint.h>

using namespace nvcuda;

#define D1 768
#define D2 768
#define D2R 385
#define NF (D1*D2R)     // 295680
#define KN_ 4
#define B_ 8
#define C_ 256
#define HW_ 64

// GEMM layout constants
#define NPACK (KN_*D2R)   // 1540: all k-planes packed in N
#define NPAD  1664        // 13 x 128 tiles
#define KB2   800         // padded K for stage B (770 -> 800)

// scales
#define WSCALE 2147483648.0f            // 2^31  (conv weights)
#define OSCALE 4.6566128730773926e-10f  // 2^-31
#define GSCALE 1048576.0f               // 2^20  (freq-domain G)
#define SINV   1.1641532182693481e-10f  // 2^-33 (gemmB epilogue; 2^20/(72*2^33)=1/768^2)

// pipeline constants
#define AST 40
#define PIPE 3
#define STG_E (128*AST)              // elements per operand stage (5120)
#define STG_B (STG_E*2)              // bytes (10240)
#define SMEM_PIPE (PIPE*2*STG_B)     // 61440 bytes

// ---------------- scratch (static device globals; no allocation) ----------
__device__ float  g_att[B_*KN_];
__device__ float2 g_tw[D1];                 // (cos, sin) of 2*pi*j/768

// Stage A: A = interleaved twiddles [1536][1536] fp16
// B = G packed [n = k*385+q][1536] fp16, cols interleaved (Gr_p, Gi_p)
__device__ __align__(128) __half g_TAh[1536*1536];
__device__ __align__(128) __half g_GTh[NPAD*1536];   // rows >=1540 stay zero
// Stage A output, split-K x2 partials (fp32, sum = Y_true * 2^20): [z][1536][NPAD]
__device__ __align__(128) float g_Ytmp[2][1536*NPAD];
// Stage B operands: A = scaled Y [3072][800] fp16; B = twiddles [768][800] fp16
__device__ __align__(128) __half g_YAh[KN_*D1*KB2];
__device__ __align__(128) __half g_TBh[D2*KB2];
// spatial weights, split-K x2 partials: [z][k][m*768+t]
__device__ __align__(128) float g_Sp[2][KN_][D1*D2];

// single fp16 conv weights (scaled by 2^31), per batch, K-major: [b][o][st*256+i]
__device__ __align__(128) __half g_Wh[B_*C_*9*C_];
// fp16 input, channel-last: [b][pixel][i]
__device__ __align__(128) __half g_Xh[B_*HW_*HW_*C_];

// ============================ helpers ======================================
__device__ __forceinline__ uint32_t smem_u32(const void* p) {
    uint32_t a;
    asm("{ .reg .u64 t; cvta.to.shared.u64 t, %1; cvt.u32.u64 %0, t; }"
        : "=r"(a) : "l"(p));
    return a;
}
__device__ __forceinline__ void cp_async16(uint32_t dst, const void* src, int pbytes) {
    asm volatile("cp.async.cg.shared.global [%0], [%1], 16, %2;"
                 :: "r"(dst), "l"(src), "r"(pbytes));
}
#define CP_COMMIT() asm volatile("cp.async.commit_group;" ::: "memory")
#define CP_WAIT(N)  asm volatile("cp.async.wait_group %0;" :: "n"(N) : "memory")

// ---------------- setup: attention + twiddle table -------------------------
__global__ void k_setup(const float* __restrict__ katt) {
    int j = threadIdx.x;
    if (j < D1) {
        double ang = 2.0 * M_PI * (double)j / (double)D1;
        g_tw[j] = make_float2((float)cos(ang), (float)sin(ang));
    }
    if (j < B_*KN_) {
        g_att[j] = 0.5f / (1.0f + expf(-katt[j]));
    }
}

// ------- fill stage-A twiddle matrix (1536x1536), interleaved cols ---------
__global__ void k_fillTA() {
    int id = blockIdx.x * 256 + threadIdx.x;
    if (id >= 1536*1536) return;
    int i = id / 1536;
    int j = id - i*1536;
    int p = j >> 1;
    int m = (i < 768) ? i : i - 768;
    int idx = (m * p) % 768;
    float2 cs = g_tw[idx];
    float v = (i < 768) ? (((j & 1) == 0) ? cs.x : -cs.y)
                        : (((j & 1) == 0) ? cs.y :  cs.x);
    g_TAh[id] = __float2half(v);
}

// ---------------- fill stage-B twiddle matrix (768 x 800), single fp16 -----
__global__ void k_fillTB() {
    int id = blockIdx.x * 256 + threadIdx.x;
    if (id >= D2*KB2) return;
    int t = id / KB2;
    int c = id - t*KB2;
    float v = 0.f;
    if (c < 385) {
        v = g_tw[(c * t) % 768].x;
    } else if (c < 770) {
        int q = c - 385;
        v = -g_tw[(q * t) % 768].y;
    }
    g_TBh[id] = __float2half(v);
}

// ------- scatter dft_weight into packed interleaved G (x 2^20) -------------
__global__ void k_scatter(const float* __restrict__ dw,
                          const int*   __restrict__ fh,
                          const int*   __restrict__ fw) {
    int n = blockIdx.x * 256 + threadIdx.x;
    if (n >= NF) return;
    int p = fh[n];
    int q = fw[n];
    const float2* dw2 = (const float2*)dw;
#pragma unroll
    for (int k = 0; k < KN_; ++k) {
        float2 v = dw2[(size_t)k*NF + n];
        __half2 h = __floats2half2_rn(v.x * GSCALE, v.y * GSCALE);
        *(__half2*)&g_GTh[(size_t)(k*D2R + q)*1536 + 2*p] = h;
    }
}

// --------- convert stage-A output -> stage-B A operand (single fp16) -------
// sums the two split-K partials
__global__ void k_yconv() {
    int id = blockIdx.x * 256 + threadIdx.x;
    if (id >= KN_*D1*D2R) return;
    int q = id % D2R;
    int r = id / D2R;          // k*768 + m
    int m = r % D1;
    int k = r / D1;
    int col = k*D2R + q;
    size_t ir = (size_t)m*NPAD + col;
    size_t ii = (size_t)(768 + m)*NPAD + col;
    float yr = g_Ytmp[0][ir] + g_Ytmp[1][ir];
    float yi = g_Ytmp[0][ii] + g_Ytmp[1][ii];
    bool edge = (q == 0) || (q == 384);
    float sc  = (edge ? 1.f : 2.f) * (1.f/72.f);
    yr *= sc;
    yi  = edge ? 0.f : yi*sc;
    size_t base = (size_t)r*KB2;
    g_YAh[base + q]       = __float2half(yr);
    g_YAh[base + 385 + q] = __float2half(yi);
}

// --- fp16 single-pass wmma GEMM body, 3-stage pipe, 1 sync/chunk, split-K --
__device__ __forceinline__ void gemm_body_h(
    const __half* A0, int lda,
    const __half* B0, int ldb,
    float* Cc, int ldc, int c0, int c1, float osc)
{
    extern __shared__ __half dsm[];
    __half* sA = dsm;                 // PIPE stages of 128x40
    __half* sB = dsm + PIPE*STG_E;    // PIPE stages of 128x40

    int tid = threadIdx.x;
    int wid = tid >> 5;
    int warp_m = wid >> 2;
    int warp_n = wid & 3;
    int m0 = blockIdx.y * 128;
    int n0 = blockIdx.x * 128;

    int lrow  = tid >> 1;
    int lhalf = (tid & 1) << 4;

    uint32_t aB = smem_u32(sA);
    uint32_t bB = smem_u32(sB);
    uint32_t dOff = (uint32_t)(lrow*AST + lhalf) * 2;

    wmma::fragment<wmma::accumulator, 16, 16, 16, float> acc[4][2];
#pragma unroll
    for (int i = 0; i < 4; ++i)
#pragma unroll
        for (int j = 0; j < 2; ++j)
            wmma::fill_fragment(acc[i][j], 0.f);

    auto issue = [&](int c, int stg) {
        int k0 = c * 32;
        const __half* asrc = A0 + (size_t)(m0 + lrow)*lda + k0 + lhalf;
        uint32_t ad = aB + stg*STG_B + dOff;
        cp_async16(ad,      asrc,     16);
        cp_async16(ad + 16, asrc + 8, 16);

        const __half* bsrc = B0 + (size_t)(n0 + lrow)*ldb + k0 + lhalf;
        uint32_t bd = bB + stg*STG_B + dOff;
        cp_async16(bd,      bsrc,     16);
        cp_async16(bd + 16, bsrc + 8, 16);
        CP_COMMIT();
    };

    issue(c0, 0);
    if (c0 + 1 < c1) issue(c0 + 1, 1);

    for (int c = c0; c < c1; ++c) {
        if (c + 1 < c1) CP_WAIT(1);
        else            CP_WAIT(0);
        __syncthreads();

        int stg = (c - c0) % PIPE;
        const __half* sAc = sA + stg*STG_E;
        const __half* sBc = sB + stg*STG_E;
#pragma unroll
        for (int kk = 0; kk < 2; ++kk) {
            wmma::fragment<wmma::matrix_a, 16, 16, 16, __half, wmma::row_major> af[4];
            wmma::fragment<wmma::matrix_b, 16, 16, 16, __half, wmma::col_major> bfr[2];
#pragma unroll
            for (int i = 0; i < 4; ++i)
                wmma::load_matrix_sync(af[i],
                    sAc + (warp_m*64 + i*16)*AST + kk*16, AST);
#pragma unroll
            for (int j = 0; j < 2; ++j)
                wmma::load_matrix_sync(bfr[j],
                    sBc + (warp_n*32 + j*16)*AST + kk*16, AST);
#pragma unroll
            for (int i = 0; i < 4; ++i)
#pragma unroll
                for (int j = 0; j < 2; ++j)
                    wmma::mma_sync(acc[i][j], af[i], bfr[j], acc[i][j]);
        }

        if (c + 2 < c1) issue(c + 2, (c + 2 - c0) % PIPE);
    }

    float* ob = Cc + (size_t)(m0 + warp_m*64)*ldc + n0 + warp_n*32;
#pragma unroll
    for (int i = 0; i < 4; ++i)
#pragma unroll
        for (int j = 0; j < 2; ++j) {
#pragma unroll
            for (int e = 0; e < acc[i][j].num_elements; ++e)
                acc[i][j].x[e] *= osc;
            wmma::store_matrix_sync(ob + (size_t)i*16*ldc + j*16,
                                    acc[i][j], ldc, wmma::mem_row_major);
        }
}

// Stage A: Y(1536 x 1664) = TA(1536x1536) * G^T. split-K x2 via blockIdx.z.
__global__ void __launch_bounds__(256) k_gemmA() {
    int z = blockIdx.z;                 // 0: chunks [0,24), 1: [24,48)
    gemm_body_h(g_TAh, 1536, g_GTh, 1536,
                g_Ytmp[z], NPAD, z*24, (z+1)*24, 1.f);
}

// Stage B: S(3072 x 768) = YA * TB^T. split-K x2 (13 + 12 chunks).
__global__ void __launch_bounds__(256) k_gemmB() {
    int z = blockIdx.z;
    int c0 = z ? 13 : 0;
    int c1 = z ? 25 : 13;
    gemm_body_h(g_YAh, KB2, g_TBh, KB2,
                &g_Sp[z][0][0], D2, c0, c1, SINV);
}

// ------- combine per-batch weights -> single fp16 (scaled 2^31), K-major ---
// sums split-K partials of S
__global__ void __launch_bounds__(256) k_combine_fp16() {
    __shared__ float srow[768];
    int blk = blockIdx.x;
    int s = blk % 3;
    int o = (blk / 3) & 255;
    int b = blk / (3*256);
    int tid = threadIdx.x;

    int row = (o*3 + s) * D2;
    float a0 = g_att[b*KN_ + 0];
    float a1 = g_att[b*KN_ + 1];
    float a2 = g_att[b*KN_ + 2];
    float a3 = g_att[b*KN_ + 3];
#pragma unroll
    for (int rep = 0; rep < 3; ++rep) {
        int t = tid + rep*256;
        srow[t] = a0*(g_Sp[0][0][row + t] + g_Sp[1][0][row + t])
                + a1*(g_Sp[0][1][row + t] + g_Sp[1][1][row + t])
                + a2*(g_Sp[0][2][row + t] + g_Sp[1][2][row + t])
                + a3*(g_Sp[0][3][row + t] + g_Sp[1][3][row + t]);
    }
    __syncthreads();

    size_t obase = ((size_t)(b*256 + o)*9 + s*3) * 256 + tid;
#pragma unroll
    for (int tt = 0; tt < 3; ++tt)
        g_Wh[obase + (size_t)tt*256] = __float2half(srow[tid*3 + tt] * WSCALE);
}

// ------------- x: convert to fp16 + transpose to channel-last --------------
__global__ void k_xsplit(const float* __restrict__ xin) {
    __shared__ float tile[32][33];
    int b  = blockIdx.z;
    int p0 = blockIdx.x * 32;
    int c0 = blockIdx.y * 32;
    int tx = threadIdx.x, ty = threadIdx.y;   // 32 x 8
#pragma unroll
    for (int j = 0; j < 4; ++j) {
        int ch = c0 + ty + j*8;
        tile[ty + j*8][tx] = xin[((size_t)b*C_ + ch)*(HW_*HW_) + p0 + tx];
    }
    __syncthreads();
#pragma unroll
    for (int j = 0; j < 4; ++j) {
        int p = p0 + ty + j*8;
        float v = tile[tx][ty + j*8];
        size_t oidx = ((size_t)b*(HW_*HW_) + p)*C_ + c0 + tx;
        g_Xh[oidx] = __float2half(v);
    }
}

// --------- wmma fp16 conv, 3-stage pipe, 1 sync/chunk ----------------------
// out = W * X. K = 9 taps x 8 chunks of 32 = 72 chunks.
#define NCHUNK 72

__global__ void __launch_bounds__(256) k_conv_wmma(float* __restrict__ out) {
    extern __shared__ __half dsm[];
    __half* sA = dsm;
    __half* sB = dsm + PIPE*STG_E;

    int tid = threadIdx.x;
    int wid = tid >> 5;
    int warp_m = wid >> 2;
    int warp_n = wid & 3;
    int b  = blockIdx.z;
    int o0 = blockIdx.y * 128;
    int n0 = blockIdx.x * 128;

    int lrow  = tid >> 1;
    int lhalf = (tid & 1) << 4;

    uint32_t aB = smem_u32(sA);
    uint32_t bB = smem_u32(sB);
    uint32_t dOff = (uint32_t)(lrow*AST + lhalf) * 2;

    wmma::fragment<wmma::accumulator, 16, 16, 16, float> acc[4][2];
#pragma unroll
    for (int i = 0; i < 4; ++i)
#pragma unroll
        for (int j = 0; j < 2; ++j)
            wmma::fill_fragment(acc[i][j], 0.f);

    auto issue = [&](int c, int stg) {
        int st   = c >> 3;
        int i0   = (c & 7) << 5;
        int s    = st / 3, t = st % 3;

        const __half* asrc = g_Wh + (size_t)b*(C_*9*C_)
                             + (size_t)(o0 + lrow)*2304 + st*256 + i0 + lhalf;
        uint32_t ad = aB + stg*STG_B + dOff;
        cp_async16(ad,      asrc,     16);
        cp_async16(ad + 16, asrc + 8, 16);

        int n  = n0 + lrow;
        int yy = (n >> 6) + s - 1;
        int xx = (n & 63) + t - 1;
        int ok = (((unsigned)yy < HW_) && ((unsigned)xx < HW_)) ? 16 : 0;
        const __half* bsrc = g_Xh + (((size_t)b*(HW_*HW_) + yy*HW_ + xx)*C_
                                     + i0 + lhalf);
        uint32_t bd = bB + stg*STG_B + dOff;
        cp_async16(bd,      bsrc,     ok);
        cp_async16(bd + 16, bsrc + 8, ok);
        CP_COMMIT();
    };

    issue(0, 0);
    issue(1, 1);

    for (int c = 0; c < NCHUNK; ++c) {
        if (c + 1 < NCHUNK) CP_WAIT(1);
        else                CP_WAIT(0);
        __syncthreads();

        int stg = c % PIPE;
        const __half* sAc = sA + stg*STG_E;
        const __half* sBc = sB + stg*STG_E;
#pragma unroll
        for (int kk = 0; kk < 2; ++kk) {
            wmma::fragment<wmma::matrix_a, 16, 16, 16, __half, wmma::row_major> af[4];
            wmma::fragment<wmma::matrix_b, 16, 16, 16, __half, wmma::col_major> bfr[2];
#pragma unroll
            for (int i = 0; i < 4; ++i)
                wmma::load_matrix_sync(af[i],
                    sAc + (warp_m*64 + i*16)*AST + kk*16, AST);
#pragma unroll
            for (int j = 0; j < 2; ++j)
                wmma::load_matrix_sync(bfr[j],
                    sBc + (warp_n*32 + j*16)*AST + kk*16, AST);
#pragma unroll
            for (int i = 0; i < 4; ++i)
#pragma unroll
                for (int j = 0; j < 2; ++j)
                    wmma::mma_sync(acc[i][j], af[i], bfr[j], acc[i][j]);
        }

        if (c + 2 < NCHUNK) issue(c + 2, (c + 2) % PIPE);
    }

    float* ob = out + ((size_t)b*C_ + o0 + warp_m*64)*(HW_*HW_) + n0 + warp_n*32;
#pragma unroll
    for (int i = 0; i < 4; ++i)
#pragma unroll
        for (int j = 0; j < 2; ++j) {
#pragma unroll
            for (int e = 0; e < acc[i][j].num_elements; ++e)
                acc[i][j].x[e] *= OSCALE;
            wmma::store_matrix_sync(ob + (size_t)i*16*(HW_*HW_) + j*16,
                                    acc[i][j], HW_*HW_, wmma::mem_row_major);
        }
}

// ---------------- launch ----------------------------------------------------
extern "C" void kernel_launch(void* const* d_in, const int* in_sizes, int n_in,
                              void* d_out, int out_size) {
    const float* x    = (const float*)d_in[0];
    const float* dw   = (const float*)d_in[1];
    const float* katt = (const float*)d_in[2];
    const int*   fh   = (const int*)d_in[3];
    const int*   fw   = (const int*)d_in[4];
    float* out = (float*)d_out;

    cudaFuncSetAttribute(k_gemmA, cudaFuncAttributeMaxDynamicSharedMemorySize, SMEM_PIPE);
    cudaFuncSetAttribute(k_gemmB, cudaFuncAttributeMaxDynamicSharedMemorySize, SMEM_PIPE);
    cudaFuncSetAttribute(k_conv_wmma, cudaFuncAttributeMaxDynamicSharedMemorySize, SMEM_PIPE);

    k_setup  <<<1, 768>>>(katt);
    k_fillTA <<<(1536*1536 + 255)/256, 256>>>();
    k_fillTB <<<(D2*KB2 + 255)/256, 256>>>();
    k_scatter<<<(NF + 255)/256, 256>>>(dw, fh, fw);
    k_xsplit <<<dim3(HW_*HW_/32, C_/32, B_), dim3(32, 8)>>>(x);

    k_gemmA<<<dim3(NPAD/128, 1536/128, 2), 256, SMEM_PIPE>>>();
    k_yconv<<<(KN_*D1*D2R + 255)/256, 256>>>();
    k_gemmB<<<dim3(D2/128, (KN_*D1)/128, 2), 256, SMEM_PIPE>>>();

    k_combine_fp16<<<B_*C_*3, 256>>>();
    k_conv_wmma   <<<dim3(HW_*HW_/128, C_/128, B_), 256, SMEM_PIPE>>>(out);
}

// round 15
// speedup vs baseline: 3.9317x; 1.0413x over previous
#include <cuda_runtime.h>
#include <cuda_bf16.h>
#include <cuda_fp16.h>
#include <mma.h>
#include <math.h>
#include <stdint.h>

using namespace nvcuda;

#define D1 768
#define D2 768
#define D2R 385
#define NF (D1*D2R)     // 295680
#define KN_ 4
#define B_ 8
#define C_ 256
#define HW_ 64

// GEMM layout constants
#define NPACK (KN_*D2R)   // 1540: all k-planes packed in N
#define NPAD  1664        // 13 x 128 tiles
#define KB2   800         // padded K for stage B (770 -> 800)

// scales
#define WSCALE 2147483648.0f            // 2^31  (conv weights)
#define OSCALE 4.6566128730773926e-10f  // 2^-31
#define GSCALE 1048576.0f               // 2^20  (freq-domain G)
#define SINV   1.1641532182693481e-10f  // 2^-33 (gemmB epilogue; 2^20/(72*2^33)=1/768^2)

// pipeline constants
#define AST 40
#define PIPE 3
#define STG_E (128*AST)              // elements per operand stage (5120)
#define STG_B (STG_E*2)              // bytes (10240)
#define SMEM_PIPE (PIPE*2*STG_B)     // 61440 bytes

// prep-kernel block ranges
#define NB_TA   9216                  // 1536*1536/256
#define NB_TB   2400                  // 768*800/256
#define NB_SC   1155                  // ceil(295680/256)
#define NB_XS   8192                  // 128 * 8 * 8
#define NB_PREP (NB_TA + NB_TB + NB_SC + NB_XS)

// ---------------- scratch (static device globals; no allocation) ----------
__device__ float  g_att[B_*KN_];
__device__ float2 g_tw[D1];                 // (cos, sin) of 2*pi*j/768

// Stage A: A = interleaved twiddles [1536][1536] fp16
// B = G packed [n = k*385+q][1536] fp16, cols interleaved (Gr_p, Gi_p)
__device__ __align__(128) __half g_TAh[1536*1536];
__device__ __align__(128) __half g_GTh[NPAD*1536];   // rows >=1540 stay zero
// Stage A output, split-K x2 partials (fp32, sum = Y_true * 2^20): [z][1536][NPAD]
__device__ __align__(128) float g_Ytmp[2][1536*NPAD];
// Stage B operands: A = scaled Y [3072][800] fp16; B = twiddles [768][800] fp16
__device__ __align__(128) __half g_YAh[KN_*D1*KB2];
__device__ __align__(128) __half g_TBh[D2*KB2];
// spatial weights, split-K x2 partials: [z][k][m*768+t]
__device__ __align__(128) float g_Sp[2][KN_][D1*D2];

// single fp16 conv weights (scaled by 2^31), per batch, K-major: [b][o][st*256+i]
__device__ __align__(128) __half g_Wh[B_*C_*9*C_];
// fp16 input, channel-last: [b][pixel][i]
__device__ __align__(128) __half g_Xh[B_*HW_*HW_*C_];

// ============================ helpers ======================================
__device__ __forceinline__ uint32_t smem_u32(const void* p) {
    uint32_t a;
    asm("{ .reg .u64 t; cvta.to.shared.u64 t, %1; cvt.u32.u64 %0, t; }"
        : "=r"(a) : "l"(p));
    return a;
}
__device__ __forceinline__ void cp_async16(uint32_t dst, const void* src, int pbytes) {
    asm volatile("cp.async.cg.shared.global [%0], [%1], 16, %2;"
                 :: "r"(dst), "l"(src), "r"(pbytes));
}
#define CP_COMMIT() asm volatile("cp.async.commit_group;" ::: "memory")
#define CP_WAIT(N)  asm volatile("cp.async.wait_group %0;" :: "n"(N) : "memory")

// ---------------- setup: attention + twiddle table -------------------------
__global__ void k_setup(const float* __restrict__ katt) {
    int j = threadIdx.x;
    if (j < D1) {
        double ang = 2.0 * M_PI * (double)j / (double)D1;
        g_tw[j] = make_float2((float)cos(ang), (float)sin(ang));
    }
    if (j < B_*KN_) {
        g_att[j] = 0.5f / (1.0f + expf(-katt[j]));
    }
}

// ------------- fused prep: fillTA | fillTB | scatter | xsplit --------------
__global__ void __launch_bounds__(256) k_prep(const float* __restrict__ xin,
                                              const float* __restrict__ dw,
                                              const int*   __restrict__ fh,
                                              const int*   __restrict__ fw) {
    __shared__ float tile[32][33];
    int blk = blockIdx.x;
    int tid = threadIdx.x;

    if (blk < NB_TA) {
        // ---- fill stage-A twiddle matrix (1536x1536), interleaved cols ----
        int id = blk * 256 + tid;
        int i = id / 1536;
        int j = id - i*1536;
        int p = j >> 1;
        int m = (i < 768) ? i : i - 768;
        int idx = (m * p) % 768;
        float2 cs = g_tw[idx];
        float v = (i < 768) ? (((j & 1) == 0) ? cs.x : -cs.y)
                            : (((j & 1) == 0) ? cs.y :  cs.x);
        g_TAh[id] = __float2half(v);
        return;
    }
    blk -= NB_TA;

    if (blk < NB_TB) {
        // ---- fill stage-B twiddle matrix (768 x 800) -----------------------
        int id = blk * 256 + tid;
        int t = id / KB2;
        int c = id - t*KB2;
        float v = 0.f;
        if (c < 385) {
            v = g_tw[(c * t) % 768].x;
        } else if (c < 770) {
            int q = c - 385;
            v = -g_tw[(q * t) % 768].y;
        }
        g_TBh[id] = __float2half(v);
        return;
    }
    blk -= NB_TB;

    if (blk < NB_SC) {
        // ---- scatter dft_weight into packed interleaved G (x 2^20) --------
        int n = blk * 256 + tid;
        if (n >= NF) return;
        int p = fh[n];
        int q = fw[n];
        const float2* dw2 = (const float2*)dw;
#pragma unroll
        for (int k = 0; k < KN_; ++k) {
            float2 v = dw2[(size_t)k*NF + n];
            __half2 h = __floats2half2_rn(v.x * GSCALE, v.y * GSCALE);
            *(__half2*)&g_GTh[(size_t)(k*D2R + q)*1536 + 2*p] = h;
        }
        return;
    }
    blk -= NB_SC;

    // ---- x: convert to fp16 + transpose to channel-last -------------------
    {
        int b  = blk / (128*8);
        int r  = blk % (128*8);
        int pb = r & 127;
        int cb = r >> 7;
        int p0 = pb * 32;
        int c0 = cb * 32;
        int tx = tid & 31, ty = tid >> 5;   // 32 x 8
#pragma unroll
        for (int j = 0; j < 4; ++j) {
            int ch = c0 + ty + j*8;
            tile[ty + j*8][tx] = xin[((size_t)b*C_ + ch)*(HW_*HW_) + p0 + tx];
        }
        __syncthreads();
#pragma unroll
        for (int j = 0; j < 4; ++j) {
            int p = p0 + ty + j*8;
            float v = tile[tx][ty + j*8];
            size_t oidx = ((size_t)b*(HW_*HW_) + p)*C_ + c0 + tx;
            g_Xh[oidx] = __float2half(v);
        }
    }
}

// --------- convert stage-A output -> stage-B A operand (single fp16) -------
// sums the two split-K partials
__global__ void k_yconv() {
    int id = blockIdx.x * 256 + threadIdx.x;
    if (id >= KN_*D1*D2R) return;
    int q = id % D2R;
    int r = id / D2R;          // k*768 + m
    int m = r % D1;
    int k = r / D1;
    int col = k*D2R + q;
    size_t ir = (size_t)m*NPAD + col;
    size_t ii = (size_t)(768 + m)*NPAD + col;
    float yr = g_Ytmp[0][ir] + g_Ytmp[1][ir];
    float yi = g_Ytmp[0][ii] + g_Ytmp[1][ii];
    bool edge = (q == 0) || (q == 384);
    float sc  = (edge ? 1.f : 2.f) * (1.f/72.f);
    yr *= sc;
    yi  = edge ? 0.f : yi*sc;
    size_t base = (size_t)r*KB2;
    g_YAh[base + q]       = __float2half(yr);
    g_YAh[base + 385 + q] = __float2half(yi);
}

// --- fp16 single-pass wmma GEMM body, 3-stage pipe, 1 sync/chunk, split-K --
__device__ __forceinline__ void gemm_body_h(
    const __half* A0, int lda,
    const __half* B0, int ldb,
    float* Cc, int ldc, int c0, int c1, float osc)
{
    extern __shared__ __half dsm[];
    __half* sA = dsm;                 // PIPE stages of 128x40
    __half* sB = dsm + PIPE*STG_E;    // PIPE stages of 128x40

    int tid = threadIdx.x;
    int wid = tid >> 5;
    int warp_m = wid >> 2;
    int warp_n = wid & 3;
    int m0 = blockIdx.y * 128;
    int n0 = blockIdx.x * 128;

    int lrow  = tid >> 1;
    int lhalf = (tid & 1) << 4;

    uint32_t aB = smem_u32(sA);
    uint32_t bB = smem_u32(sB);
    uint32_t dOff = (uint32_t)(lrow*AST + lhalf) * 2;

    wmma::fragment<wmma::accumulator, 16, 16, 16, float> acc[4][2];
#pragma unroll
    for (int i = 0; i < 4; ++i)
#pragma unroll
        for (int j = 0; j < 2; ++j)
            wmma::fill_fragment(acc[i][j], 0.f);

    auto issue = [&](int c, int stg) {
        int k0 = c * 32;
        const __half* asrc = A0 + (size_t)(m0 + lrow)*lda + k0 + lhalf;
        uint32_t ad = aB + stg*STG_B + dOff;
        cp_async16(ad,      asrc,     16);
        cp_async16(ad + 16, asrc + 8, 16);

        const __half* bsrc = B0 + (size_t)(n0 + lrow)*ldb + k0 + lhalf;
        uint32_t bd = bB + stg*STG_B + dOff;
        cp_async16(bd,      bsrc,     16);
        cp_async16(bd + 16, bsrc + 8, 16);
        CP_COMMIT();
    };

    issue(c0, 0);
    if (c0 + 1 < c1) issue(c0 + 1, 1);

    for (int c = c0; c < c1; ++c) {
        if (c + 1 < c1) CP_WAIT(1);
        else            CP_WAIT(0);
        __syncthreads();

        int stg = (c - c0) % PIPE;
        const __half* sAc = sA + stg*STG_E;
        const __half* sBc = sB + stg*STG_E;
#pragma unroll
        for (int kk = 0; kk < 2; ++kk) {
            wmma::fragment<wmma::matrix_a, 16, 16, 16, __half, wmma::row_major> af[4];
            wmma::fragment<wmma::matrix_b, 16, 16, 16, __half, wmma::col_major> bfr[2];
#pragma unroll
            for (int i = 0; i < 4; ++i)
                wmma::load_matrix_sync(af[i],
                    sAc + (warp_m*64 + i*16)*AST + kk*16, AST);
#pragma unroll
            for (int j = 0; j < 2; ++j)
                wmma::load_matrix_sync(bfr[j],
                    sBc + (warp_n*32 + j*16)*AST + kk*16, AST);
#pragma unroll
            for (int i = 0; i < 4; ++i)
#pragma unroll
                for (int j = 0; j < 2; ++j)
                    wmma::mma_sync(acc[i][j], af[i], bfr[j], acc[i][j]);
        }

        if (c + 2 < c1) issue(c + 2, (c + 2 - c0) % PIPE);
    }

    float* ob = Cc + (size_t)(m0 + warp_m*64)*ldc + n0 + warp_n*32;
#pragma unroll
    for (int i = 0; i < 4; ++i)
#pragma unroll
        for (int j = 0; j < 2; ++j) {
#pragma unroll
            for (int e = 0; e < acc[i][j].num_elements; ++e)
                acc[i][j].x[e] *= osc;
            wmma::store_matrix_sync(ob + (size_t)i*16*ldc + j*16,
                                    acc[i][j], ldc, wmma::mem_row_major);
        }
}

// Stage A: Y(1536 x 1664) = TA(1536x1536) * G^T. split-K x2 via blockIdx.z.
__global__ void __launch_bounds__(256) k_gemmA() {
    int z = blockIdx.z;                 // 0: chunks [0,24), 1: [24,48)
    gemm_body_h(g_TAh, 1536, g_GTh, 1536,
                g_Ytmp[z], NPAD, z*24, (z+1)*24, 1.f);
}

// Stage B: S(3072 x 768) = YA * TB^T. split-K x2 (13 + 12 chunks).
__global__ void __launch_bounds__(256) k_gemmB() {
    int z = blockIdx.z;
    int c0 = z ? 13 : 0;
    int c1 = z ? 25 : 13;
    gemm_body_h(g_YAh, KB2, g_TBh, KB2,
                &g_Sp[z][0][0], D2, c0, c1, SINV);
}

// ------- combine per-batch weights -> single fp16 (scaled 2^31), K-major ---
// block = (o, s); reduce split-K partials into smem once, emit all 8 batches.
__global__ void __launch_bounds__(256) k_combine_fp16() {
    __shared__ float sk[KN_][768];
    int blk = blockIdx.x;              // 0 .. 767
    int s = blk % 3;
    int o = blk / 3;
    int tid = threadIdx.x;

    int row = (o*3 + s) * D2;
#pragma unroll
    for (int k = 0; k < KN_; ++k)
#pragma unroll
        for (int rep = 0; rep < 3; ++rep) {
            int t = tid + rep*256;
            sk[k][t] = g_Sp[0][k][row + t] + g_Sp[1][k][row + t];
        }
    __syncthreads();

#pragma unroll
    for (int b = 0; b < B_; ++b) {
        float a0 = g_att[b*KN_ + 0];
        float a1 = g_att[b*KN_ + 1];
        float a2 = g_att[b*KN_ + 2];
        float a3 = g_att[b*KN_ + 3];
        size_t obase = ((size_t)(b*256 + o)*9 + s*3) * 256 + tid;
#pragma unroll
        for (int tt = 0; tt < 3; ++tt) {
            int t = tid*3 + tt;
            float v = a0*sk[0][t] + a1*sk[1][t] + a2*sk[2][t] + a3*sk[3][t];
            g_Wh[obase + (size_t)tt*256] = __float2half(v * WSCALE);
        }
    }
}

// --------- wmma fp16 conv, 3-stage pipe, 1 sync/chunk ----------------------
// out = W * X. K = 9 taps x 8 chunks of 32 = 72 chunks.
#define NCHUNK 72

__global__ void __launch_bounds__(256) k_conv_wmma(float* __restrict__ out) {
    extern __shared__ __half dsm[];
    __half* sA = dsm;
    __half* sB = dsm + PIPE*STG_E;

    int tid = threadIdx.x;
    int wid = tid >> 5;
    int warp_m = wid >> 2;
    int warp_n = wid & 3;
    int b  = blockIdx.z;
    int o0 = blockIdx.y * 128;
    int n0 = blockIdx.x * 128;

    int lrow  = tid >> 1;
    int lhalf = (tid & 1) << 4;

    uint32_t aB = smem_u32(sA);
    uint32_t bB = smem_u32(sB);
    uint32_t dOff = (uint32_t)(lrow*AST + lhalf) * 2;

    wmma::fragment<wmma::accumulator, 16, 16, 16, float> acc[4][2];
#pragma unroll
    for (int i = 0; i < 4; ++i)
#pragma unroll
        for (int j = 0; j < 2; ++j)
            wmma::fill_fragment(acc[i][j], 0.f);

    auto issue = [&](int c, int stg) {
        int st   = c >> 3;
        int i0   = (c & 7) << 5;
        int s    = st / 3, t = st % 3;

        const __half* asrc = g_Wh + (size_t)b*(C_*9*C_)
                             + (size_t)(o0 + lrow)*2304 + st*256 + i0 + lhalf;
        uint32_t ad = aB + stg*STG_B + dOff;
        cp_async16(ad,      asrc,     16);
        cp_async16(ad + 16, asrc + 8, 16);

        int n  = n0 + lrow;
        int yy = (n >> 6) + s - 1;
        int xx = (n & 63) + t - 1;
        int ok = (((unsigned)yy < HW_) && ((unsigned)xx < HW_)) ? 16 : 0;
        const __half* bsrc = g_Xh + (((size_t)b*(HW_*HW_) + yy*HW_ + xx)*C_
                                     + i0 + lhalf);
        uint32_t bd = bB + stg*STG_B + dOff;
        cp_async16(bd,      bsrc,     ok);
        cp_async16(bd + 16, bsrc + 8, ok);
        CP_COMMIT();
    };

    issue(0, 0);
    issue(1, 1);

    for (int c = 0; c < NCHUNK; ++c) {
        if (c + 1 < NCHUNK) CP_WAIT(1);
        else                CP_WAIT(0);
        __syncthreads();

        int stg = c % PIPE;
        const __half* sAc = sA + stg*STG_E;
        const __half* sBc = sB + stg*STG_E;
#pragma unroll
        for (int kk = 0; kk < 2; ++kk) {
            wmma::fragment<wmma::matrix_a, 16, 16, 16, __half, wmma::row_major> af[4];
            wmma::fragment<wmma::matrix_b, 16, 16, 16, __half, wmma::col_major> bfr[2];
#pragma unroll
            for (int i = 0; i < 4; ++i)
                wmma::load_matrix_sync(af[i],
                    sAc + (warp_m*64 + i*16)*AST + kk*16, AST);
#pragma unroll
            for (int j = 0; j < 2; ++j)
                wmma::load_matrix_sync(bfr[j],
                    sBc + (warp_n*32 + j*16)*AST + kk*16, AST);
#pragma unroll
            for (int i = 0; i < 4; ++i)
#pragma unroll
                for (int j = 0; j < 2; ++j)
                    wmma::mma_sync(acc[i][j], af[i], bfr[j], acc[i][j]);
        }

        if (c + 2 < NCHUNK) issue(c + 2, (c + 2) % PIPE);
    }

    float* ob = out + ((size_t)b*C_ + o0 + warp_m*64)*(HW_*HW_) + n0 + warp_n*32;
#pragma unroll
    for (int i = 0; i < 4; ++i)
#pragma unroll
        for (int j = 0; j < 2; ++j) {
#pragma unroll
            for (int e = 0; e < acc[i][j].num_elements; ++e)
                acc[i][j].x[e] *= OSCALE;
            wmma::store_matrix_sync(ob + (size_t)i*16*(HW_*HW_) + j*16,
                                    acc[i][j], HW_*HW_, wmma::mem_row_major);
        }
}

// ---------------- launch ----------------------------------------------------
extern "C" void kernel_launch(void* const* d_in, const int* in_sizes, int n_in,
                              void* d_out, int out_size) {
    const float* x    = (const float*)d_in[0];
    const float* dw   = (const float*)d_in[1];
    const float* katt = (const float*)d_in[2];
    const int*   fh   = (const int*)d_in[3];
    const int*   fw   = (const int*)d_in[4];
    float* out = (float*)d_out;

    cudaFuncSetAttribute(k_gemmA, cudaFuncAttributeMaxDynamicSharedMemorySize, SMEM_PIPE);
    cudaFuncSetAttribute(k_gemmB, cudaFuncAttributeMaxDynamicSharedMemorySize, SMEM_PIPE);
    cudaFuncSetAttribute(k_conv_wmma, cudaFuncAttributeMaxDynamicSharedMemorySize, SMEM_PIPE);

    k_setup<<<1, 768>>>(katt);
    k_prep <<<NB_PREP, 256>>>(x, dw, fh, fw);

    k_gemmA<<<dim3(NPAD/128, 1536/128, 2), 256, SMEM_PIPE>>>();
    k_yconv<<<(KN_*D1*D2R + 255)/256, 256>>>();
    k_gemmB<<<dim3(D2/128, (KN_*D1)/128, 2), 256, SMEM_PIPE>>>();

    k_combine_fp16<<<C_*3, 256>>>();
    k_conv_wmma   <<<dim3(HW_*HW_/128, C_/128, B_), 256, SMEM_PIPE>>>(out);
}

// round 16
// speedup vs baseline: 3.9702x; 1.0098x over previous
#include <cuda_runtime.h>
#include <cuda_bf16.h>
#include <cuda_fp16.h>
#include <mma.h>
#include <math.h>
#include <stdint.h>

using namespace nvcuda;

#define D1 768
#define D2 768
#define D2R 385
#define NF (D1*D2R)     // 295680
#define KN_ 4
#define B_ 8
#define C_ 256
#define HW_ 64

// GEMM layout constants
#define NPACK (KN_*D2R)   // 1540: all k-planes packed in N
#define NPAD  1664        // 13 x 128 tiles
#define KB2   800         // padded K for stage B (770 -> 800)

// scales
#define WSCALE 2147483648.0f            // 2^31  (conv weights)
#define OSCALE 4.6566128730773926e-10f  // 2^-31
#define GSCALE 1048576.0f               // 2^20  (freq-domain G)
#define SINV   1.1641532182693481e-10f  // 2^-33 (gemmB epilogue; 2^20/(72*2^33)=1/768^2)

// pipeline constants (shared DFT gemms)
#define AST 40
#define PIPE 3
#define STG_E (128*AST)              // elements per operand stage (5120)
#define STG_B (STG_E*2)              // bytes (10240)
#define SMEM_PIPE (PIPE*2*STG_B)     // 61440 bytes

// conv pipeline constants (M=128, N=256 tile, 512 threads)
#define ASTG_E (128*AST)             // A stage elements
#define BSTG_E (256*AST)             // B stage elements
#define ASTG_B (ASTG_E*2)
#define BSTG_B (BSTG_E*2)
#define SMEM_CONV (PIPE*(ASTG_B + BSTG_B))   // 92160 bytes

// prep-kernel block ranges
#define NB_TA   9216                  // 1536*1536/256
#define NB_TB   2400                  // 768*800/256
#define NB_SC   1155                  // ceil(295680/256)
#define NB_XS   8192                  // 128 * 8 * 8
#define NB_PREP (NB_TA + NB_TB + NB_SC + NB_XS)

// ---------------- scratch (static device globals; no allocation) ----------
__device__ float  g_att[B_*KN_];
__device__ float2 g_tw[D1];                 // (cos, sin) of 2*pi*j/768

// Stage A: A = interleaved twiddles [1536][1536] fp16
// B = G packed [n = k*385+q][1536] fp16, cols interleaved (Gr_p, Gi_p)
__device__ __align__(128) __half g_TAh[1536*1536];
__device__ __align__(128) __half g_GTh[NPAD*1536];   // rows >=1540 stay zero
// Stage A output, split-K x2 partials (fp32, sum = Y_true * 2^20): [z][1536][NPAD]
__device__ __align__(128) float g_Ytmp[2][1536*NPAD];
// Stage B operands: A = scaled Y [3072][800] fp16; B = twiddles [768][800] fp16
__device__ __align__(128) __half g_YAh[KN_*D1*KB2];
__device__ __align__(128) __half g_TBh[D2*KB2];
// spatial weights, split-K x2 partials: [z][k][m*768+t]
__device__ __align__(128) float g_Sp[2][KN_][D1*D2];

// single fp16 conv weights (scaled by 2^31), per batch, K-major: [b][o][st*256+i]
__device__ __align__(128) __half g_Wh[B_*C_*9*C_];
// fp16 input, channel-last: [b][pixel][i]
__device__ __align__(128) __half g_Xh[B_*HW_*HW_*C_];

// ============================ helpers ======================================
__device__ __forceinline__ uint32_t smem_u32(const void* p) {
    uint32_t a;
    asm("{ .reg .u64 t; cvta.to.shared.u64 t, %1; cvt.u32.u64 %0, t; }"
        : "=r"(a) : "l"(p));
    return a;
}
__device__ __forceinline__ void cp_async16(uint32_t dst, const void* src, int pbytes) {
    asm volatile("cp.async.cg.shared.global [%0], [%1], 16, %2;"
                 :: "r"(dst), "l"(src), "r"(pbytes));
}
#define CP_COMMIT() asm volatile("cp.async.commit_group;" ::: "memory")
#define CP_WAIT(N)  asm volatile("cp.async.wait_group %0;" :: "n"(N) : "memory")

// ---------------- setup: attention + twiddle table -------------------------
__global__ void k_setup(const float* __restrict__ katt) {
    int j = threadIdx.x;
    if (j < D1) {
        double ang = 2.0 * M_PI * (double)j / (double)D1;
        g_tw[j] = make_float2((float)cos(ang), (float)sin(ang));
    }
    if (j < B_*KN_) {
        g_att[j] = 0.5f / (1.0f + expf(-katt[j]));
    }
}

// ------------- fused prep: fillTA | fillTB | scatter | xsplit --------------
__global__ void __launch_bounds__(256) k_prep(const float* __restrict__ xin,
                                              const float* __restrict__ dw,
                                              const int*   __restrict__ fh,
                                              const int*   __restrict__ fw) {
    __shared__ float tile[32][33];
    int blk = blockIdx.x;
    int tid = threadIdx.x;

    if (blk < NB_TA) {
        int id = blk * 256 + tid;
        int i = id / 1536;
        int j = id - i*1536;
        int p = j >> 1;
        int m = (i < 768) ? i : i - 768;
        int idx = (m * p) % 768;
        float2 cs = g_tw[idx];
        float v = (i < 768) ? (((j & 1) == 0) ? cs.x : -cs.y)
                            : (((j & 1) == 0) ? cs.y :  cs.x);
        g_TAh[id] = __float2half(v);
        return;
    }
    blk -= NB_TA;

    if (blk < NB_TB) {
        int id = blk * 256 + tid;
        int t = id / KB2;
        int c = id - t*KB2;
        float v = 0.f;
        if (c < 385) {
            v = g_tw[(c * t) % 768].x;
        } else if (c < 770) {
            int q = c - 385;
            v = -g_tw[(q * t) % 768].y;
        }
        g_TBh[id] = __float2half(v);
        return;
    }
    blk -= NB_TB;

    if (blk < NB_SC) {
        int n = blk * 256 + tid;
        if (n >= NF) return;
        int p = fh[n];
        int q = fw[n];
        const float2* dw2 = (const float2*)dw;
#pragma unroll
        for (int k = 0; k < KN_; ++k) {
            float2 v = dw2[(size_t)k*NF + n];
            __half2 h = __floats2half2_rn(v.x * GSCALE, v.y * GSCALE);
            *(__half2*)&g_GTh[(size_t)(k*D2R + q)*1536 + 2*p] = h;
        }
        return;
    }
    blk -= NB_SC;

    {
        int b  = blk / (128*8);
        int r  = blk % (128*8);
        int pb = r & 127;
        int cb = r >> 7;
        int p0 = pb * 32;
        int c0 = cb * 32;
        int tx = tid & 31, ty = tid >> 5;   // 32 x 8
#pragma unroll
        for (int j = 0; j < 4; ++j) {
            int ch = c0 + ty + j*8;
            tile[ty + j*8][tx] = xin[((size_t)b*C_ + ch)*(HW_*HW_) + p0 + tx];
        }
        __syncthreads();
#pragma unroll
        for (int j = 0; j < 4; ++j) {
            int p = p0 + ty + j*8;
            float v = tile[tx][ty + j*8];
            size_t oidx = ((size_t)b*(HW_*HW_) + p)*C_ + c0 + tx;
            g_Xh[oidx] = __float2half(v);
        }
    }
}

// --------- convert stage-A output -> stage-B A operand (single fp16) -------
__global__ void k_yconv() {
    int id = blockIdx.x * 256 + threadIdx.x;
    if (id >= KN_*D1*D2R) return;
    int q = id % D2R;
    int r = id / D2R;          // k*768 + m
    int m = r % D1;
    int k = r / D1;
    int col = k*D2R + q;
    size_t ir = (size_t)m*NPAD + col;
    size_t ii = (size_t)(768 + m)*NPAD + col;
    float yr = g_Ytmp[0][ir] + g_Ytmp[1][ir];
    float yi = g_Ytmp[0][ii] + g_Ytmp[1][ii];
    bool edge = (q == 0) || (q == 384);
    float sc  = (edge ? 1.f : 2.f) * (1.f/72.f);
    yr *= sc;
    yi  = edge ? 0.f : yi*sc;
    size_t base = (size_t)r*KB2;
    g_YAh[base + q]       = __float2half(yr);
    g_YAh[base + 385 + q] = __float2half(yi);
}

// --- fp16 single-pass wmma GEMM body, 3-stage pipe, 1 sync/chunk, split-K --
__device__ __forceinline__ void gemm_body_h(
    const __half* A0, int lda,
    const __half* B0, int ldb,
    float* Cc, int ldc, int c0, int c1, float osc)
{
    extern __shared__ __half dsm[];
    __half* sA = dsm;
    __half* sB = dsm + PIPE*STG_E;

    int tid = threadIdx.x;
    int wid = tid >> 5;
    int warp_m = wid >> 2;
    int warp_n = wid & 3;
    int m0 = blockIdx.y * 128;
    int n0 = blockIdx.x * 128;

    int lrow  = tid >> 1;
    int lhalf = (tid & 1) << 4;

    uint32_t aB = smem_u32(sA);
    uint32_t bB = smem_u32(sB);
    uint32_t dOff = (uint32_t)(lrow*AST + lhalf) * 2;

    wmma::fragment<wmma::accumulator, 16, 16, 16, float> acc[4][2];
#pragma unroll
    for (int i = 0; i < 4; ++i)
#pragma unroll
        for (int j = 0; j < 2; ++j)
            wmma::fill_fragment(acc[i][j], 0.f);

    auto issue = [&](int c, int stg) {
        int k0 = c * 32;
        const __half* asrc = A0 + (size_t)(m0 + lrow)*lda + k0 + lhalf;
        uint32_t ad = aB + stg*STG_B + dOff;
        cp_async16(ad,      asrc,     16);
        cp_async16(ad + 16, asrc + 8, 16);

        const __half* bsrc = B0 + (size_t)(n0 + lrow)*ldb + k0 + lhalf;
        uint32_t bd = bB + stg*STG_B + dOff;
        cp_async16(bd,      bsrc,     16);
        cp_async16(bd + 16, bsrc + 8, 16);
        CP_COMMIT();
    };

    issue(c0, 0);
    if (c0 + 1 < c1) issue(c0 + 1, 1);

    for (int c = c0; c < c1; ++c) {
        if (c + 1 < c1) CP_WAIT(1);
        else            CP_WAIT(0);
        __syncthreads();

        int stg = (c - c0) % PIPE;
        const __half* sAc = sA + stg*STG_E;
        const __half* sBc = sB + stg*STG_E;
#pragma unroll
        for (int kk = 0; kk < 2; ++kk) {
            wmma::fragment<wmma::matrix_a, 16, 16, 16, __half, wmma::row_major> af[4];
            wmma::fragment<wmma::matrix_b, 16, 16, 16, __half, wmma::col_major> bfr[2];
#pragma unroll
            for (int i = 0; i < 4; ++i)
                wmma::load_matrix_sync(af[i],
                    sAc + (warp_m*64 + i*16)*AST + kk*16, AST);
#pragma unroll
            for (int j = 0; j < 2; ++j)
                wmma::load_matrix_sync(bfr[j],
                    sBc + (warp_n*32 + j*16)*AST + kk*16, AST);
#pragma unroll
            for (int i = 0; i < 4; ++i)
#pragma unroll
                for (int j = 0; j < 2; ++j)
                    wmma::mma_sync(acc[i][j], af[i], bfr[j], acc[i][j]);
        }

        if (c + 2 < c1) issue(c + 2, (c + 2 - c0) % PIPE);
    }

    float* ob = Cc + (size_t)(m0 + warp_m*64)*ldc + n0 + warp_n*32;
#pragma unroll
    for (int i = 0; i < 4; ++i)
#pragma unroll
        for (int j = 0; j < 2; ++j) {
#pragma unroll
            for (int e = 0; e < acc[i][j].num_elements; ++e)
                acc[i][j].x[e] *= osc;
            wmma::store_matrix_sync(ob + (size_t)i*16*ldc + j*16,
                                    acc[i][j], ldc, wmma::mem_row_major);
        }
}

// Stage A: Y(1536 x 1664) = TA(1536x1536) * G^T. split-K x2 via blockIdx.z.
__global__ void __launch_bounds__(256) k_gemmA() {
    int z = blockIdx.z;                 // 0: chunks [0,24), 1: [24,48)
    gemm_body_h(g_TAh, 1536, g_GTh, 1536,
                g_Ytmp[z], NPAD, z*24, (z+1)*24, 1.f);
}

// Stage B: S(3072 x 768) = YA * TB^T. split-K x2 (13 + 12 chunks).
__global__ void __launch_bounds__(256) k_gemmB() {
    int z = blockIdx.z;
    int c0 = z ? 13 : 0;
    int c1 = z ? 25 : 13;
    gemm_body_h(g_YAh, KB2, g_TBh, KB2,
                &g_Sp[z][0][0], D2, c0, c1, SINV);
}

// ------- combine per-batch weights -> single fp16 (scaled 2^31), K-major ---
__global__ void __launch_bounds__(256) k_combine_fp16() {
    __shared__ float sk[KN_][768];
    int blk = blockIdx.x;              // 0 .. 767
    int s = blk % 3;
    int o = blk / 3;
    int tid = threadIdx.x;

    int row = (o*3 + s) * D2;
#pragma unroll
    for (int k = 0; k < KN_; ++k)
#pragma unroll
        for (int rep = 0; rep < 3; ++rep) {
            int t = tid + rep*256;
            sk[k][t] = g_Sp[0][k][row + t] + g_Sp[1][k][row + t];
        }
    __syncthreads();

#pragma unroll
    for (int b = 0; b < B_; ++b) {
        float a0 = g_att[b*KN_ + 0];
        float a1 = g_att[b*KN_ + 1];
        float a2 = g_att[b*KN_ + 2];
        float a3 = g_att[b*KN_ + 3];
        size_t obase = ((size_t)(b*256 + o)*9 + s*3) * 256 + tid;
#pragma unroll
        for (int tt = 0; tt < 3; ++tt) {
            int t = tid*3 + tt;
            float v = a0*sk[0][t] + a1*sk[1][t] + a2*sk[2][t] + a3*sk[3][t];
            g_Wh[obase + (size_t)tt*256] = __float2half(v * WSCALE);
        }
    }
}

// --------- wmma fp16 conv: M=128 x N=256 tile, 16 warps of 64x32 -----------
// out = W * X. K = 9 taps x 8 chunks of 32 = 72 chunks. 3-stage, 1 sync/chunk.
#define NCHUNK 72

__global__ void __launch_bounds__(512) k_conv_wmma(float* __restrict__ out) {
    extern __shared__ __half dsm[];
    __half* sA = dsm;                    // PIPE stages of 128x40
    __half* sB = dsm + PIPE*ASTG_E;      // PIPE stages of 256x40

    int tid = threadIdx.x;
    int wid = tid >> 5;                  // 0..15
    int warp_m = wid >> 3;               // 0..1  -> *64
    int warp_n = wid & 7;                // 0..7  -> *32
    int b  = blockIdx.z;
    int o0 = blockIdx.y * 128;
    int n0 = blockIdx.x * 256;           // 256 pixels = 4 rows

    // A load mapping: 4 threads per 128 rows, 16B each
    int arow = tid >> 2;                 // 0..127
    int aseg = (tid & 3) << 3;           // 0,8,16,24 halves
    // B load mapping: 2 threads per 256 rows, 32B each
    int brow = tid >> 1;                 // 0..255
    int bseg = (tid & 1) << 4;           // 0,16 halves

    uint32_t aB = smem_u32(sA);
    uint32_t bB = smem_u32(sB);
    uint32_t aOff = (uint32_t)(arow*AST + aseg) * 2;
    uint32_t bOff = (uint32_t)(brow*AST + bseg) * 2;

    wmma::fragment<wmma::accumulator, 16, 16, 16, float> acc[4][2];
#pragma unroll
    for (int i = 0; i < 4; ++i)
#pragma unroll
        for (int j = 0; j < 2; ++j)
            wmma::fill_fragment(acc[i][j], 0.f);

    auto issue = [&](int c, int stg) {
        int st   = c >> 3;
        int i0   = (c & 7) << 5;
        int s    = st / 3, t = st % 3;

        const __half* asrc = g_Wh + (size_t)b*(C_*9*C_)
                             + (size_t)(o0 + arow)*2304 + st*256 + i0 + aseg;
        cp_async16(aB + stg*ASTG_B + aOff, asrc, 16);

        int n  = n0 + brow;
        int yy = (n >> 6) + s - 1;
        int xx = (n & 63) + t - 1;
        int ok = (((unsigned)yy < HW_) && ((unsigned)xx < HW_)) ? 16 : 0;
        const __half* bsrc = g_Xh + (((size_t)b*(HW_*HW_) + yy*HW_ + xx)*C_
                                     + i0 + bseg);
        uint32_t bd = bB + stg*BSTG_B + bOff;
        cp_async16(bd,      bsrc,     ok);
        cp_async16(bd + 16, bsrc + 8, ok);
        CP_COMMIT();
    };

    issue(0, 0);
    issue(1, 1);

    for (int c = 0; c < NCHUNK; ++c) {
        if (c + 1 < NCHUNK) CP_WAIT(1);
        else                CP_WAIT(0);
        __syncthreads();

        int stg = c % PIPE;
        const __half* sAc = sA + stg*ASTG_E;
        const __half* sBc = sB + stg*BSTG_E;
#pragma unroll
        for (int kk = 0; kk < 2; ++kk) {
            wmma::fragment<wmma::matrix_a, 16, 16, 16, __half, wmma::row_major> af[4];
            wmma::fragment<wmma::matrix_b, 16, 16, 16, __half, wmma::col_major> bfr[2];
#pragma unroll
            for (int i = 0; i < 4; ++i)
                wmma::load_matrix_sync(af[i],
                    sAc + (warp_m*64 + i*16)*AST + kk*16, AST);
#pragma unroll
            for (int j = 0; j < 2; ++j)
                wmma::load_matrix_sync(bfr[j],
                    sBc + (warp_n*32 + j*16)*AST + kk*16, AST);
#pragma unroll
            for (int i = 0; i < 4; ++i)
#pragma unroll
                for (int j = 0; j < 2; ++j)
                    wmma::mma_sync(acc[i][j], af[i], bfr[j], acc[i][j]);
        }

        if (c + 2 < NCHUNK) issue(c + 2, (c + 2) % PIPE);
    }

    float* ob = out + ((size_t)b*C_ + o0 + warp_m*64)*(HW_*HW_) + n0 + warp_n*32;
#pragma unroll
    for (int i = 0; i < 4; ++i)
#pragma unroll
        for (int j = 0; j < 2; ++j) {
#pragma unroll
            for (int e = 0; e < acc[i][j].num_elements; ++e)
                acc[i][j].x[e] *= OSCALE;
            wmma::store_matrix_sync(ob + (size_t)i*16*(HW_*HW_) + j*16,
                                    acc[i][j], HW_*HW_, wmma::mem_row_major);
        }
}

// ---------------- launch ----------------------------------------------------
extern "C" void kernel_launch(void* const* d_in, const int* in_sizes, int n_in,
                              void* d_out, int out_size) {
    const float* x    = (const float*)d_in[0];
    const float* dw   = (const float*)d_in[1];
    const float* katt = (const float*)d_in[2];
    const int*   fh   = (const int*)d_in[3];
    const int*   fw   = (const int*)d_in[4];
    float* out = (float*)d_out;

    cudaFuncSetAttribute(k_gemmA, cudaFuncAttributeMaxDynamicSharedMemorySize, SMEM_PIPE);
    cudaFuncSetAttribute(k_gemmB, cudaFuncAttributeMaxDynamicSharedMemorySize, SMEM_PIPE);
    cudaFuncSetAttribute(k_conv_wmma, cudaFuncAttributeMaxDynamicSharedMemorySize, SMEM_CONV);

    k_setup<<<1, 768>>>(katt);
    k_prep <<<NB_PREP, 256>>>(x, dw, fh, fw);

    k_gemmA<<<dim3(NPAD/128, 1536/128, 2), 256, SMEM_PIPE>>>();
    k_yconv<<<(KN_*D1*D2R + 255)/256, 256>>>();
    k_gemmB<<<dim3(D2/128, (KN_*D1)/128, 2), 256, SMEM_PIPE>>>();

    k_combine_fp16<<<C_*3, 256>>>();
    k_conv_wmma   <<<dim3(HW_*HW_/256, C_/128, B_), 512, SMEM_CONV>>>(out);
}

// round 17
// speedup vs baseline: 4.0311x; 1.0153x over previous
#include <cuda_runtime.h>
#include <cuda_bf16.h>
#include <cuda_fp16.h>
#include <mma.h>
#include <math.h>
#include <stdint.h>

using namespace nvcuda;

#define D1 768
#define D2 768
#define D2R 385
#define NF (D1*D2R)     // 295680
#define KN_ 4
#define B_ 8
#define C_ 256
#define HW_ 64

// GEMM layout constants
#define NSTRIDE 416       // per-k column stride inside packed N (4*416 = 1664)
#define NPAD  1664        // 13 x 128 tiles
#define KB2   800         // stage-B K: real [0,385), imag [400,785), zero gaps

// scales
#define WSCALE 2147483648.0f            // 2^31  (conv weights)
#define OSCALE 4.6566128730773926e-10f  // 2^-31
#define GSCALE 1048576.0f               // 2^20  (freq-domain G)
#define SINV   1.1641532182693481e-10f  // 2^-33 (gemmB epilogue; 2^20/(72*2^33)=1/768^2)

// pipeline constants (shared DFT gemms)
#define AST 40
#define PIPE 3
#define STG_E (128*AST)              // elements per operand stage (5120)
#define STG_B (STG_E*2)              // bytes (10240)
#define SMEM_PIPE (PIPE*2*STG_B)     // 61440 bytes

// conv pipeline constants (M=128, N=256 tile, 512 threads)
#define ASTG_E (128*AST)
#define BSTG_E (256*AST)
#define ASTG_B (ASTG_E*2)
#define BSTG_B (BSTG_E*2)
#define SMEM_CONV (PIPE*(ASTG_B + BSTG_B))   // 92160 bytes

// prep-kernel block ranges
#define NB_TA   1152                  // 1536*1536/(256*8)
#define NB_TB   300                   // 768*800/(256*8)
#define NB_SC   1155                  // ceil(295680/256)
#define NB_XS   8192                  // 128 * 8 * 8
#define NB_PREP (NB_TA + NB_TB + NB_SC + NB_XS)

// ---------------- scratch (static device globals; no allocation) ----------
__device__ float  g_att[B_*KN_];
__device__ float2 g_tw[D1];                 // (cos, sin) of 2*pi*j/768

// Stage A: A = interleaved twiddles [1536][1536] fp16
// B = G packed [n = k*416+q][1536] fp16, cols interleaved (Gr_p, Gi_p)
__device__ __align__(128) __half g_TAh[1536*1536];
__device__ __align__(128) __half g_GTh[NPAD*1536];   // rows k*416+[385,416) stay zero
// Stage A output, split-K x2 partials (fp32, sum = Y_true * 2^20): [z][1536][NPAD]
__device__ __align__(128) float g_Ytmp[2][1536*NPAD];
// Stage B operands: A = scaled Y [3072][800] fp16; B = twiddles [768][800] fp16
__device__ __align__(128) __half g_YAh[KN_*D1*KB2];
__device__ __align__(128) __half g_TBh[D2*KB2];
// spatial weights, split-K x2 partials: [z][k][m*768+t]
__device__ __align__(128) float g_Sp[2][KN_][D1*D2];

// single fp16 conv weights (scaled by 2^31), per batch, K-major: [b][o][st*256+i]
__device__ __align__(128) __half g_Wh[B_*C_*9*C_];
// fp16 input, channel-last: [b][pixel][i]
__device__ __align__(128) __half g_Xh[B_*HW_*HW_*C_];

// ============================ helpers ======================================
__device__ __forceinline__ uint32_t smem_u32(const void* p) {
    uint32_t a;
    asm("{ .reg .u64 t; cvta.to.shared.u64 t, %1; cvt.u32.u64 %0, t; }"
        : "=r"(a) : "l"(p));
    return a;
}
__device__ __forceinline__ void cp_async16(uint32_t dst, const void* src, int pbytes) {
    asm volatile("cp.async.cg.shared.global [%0], [%1], 16, %2;"
                 :: "r"(dst), "l"(src), "r"(pbytes));
}
#define CP_COMMIT() asm volatile("cp.async.commit_group;" ::: "memory")
#define CP_WAIT(N)  asm volatile("cp.async.wait_group %0;" :: "n"(N) : "memory")

// ---------------- setup: attention + twiddle table -------------------------
__global__ void k_setup(const float* __restrict__ katt) {
    int j = threadIdx.x;
    if (j < D1) {
        double ang = 2.0 * M_PI * (double)j / (double)D1;
        g_tw[j] = make_float2((float)cos(ang), (float)sin(ang));
    }
    if (j < B_*KN_) {
        g_att[j] = 0.5f / (1.0f + expf(-katt[j]));
    }
}

// ------------- fused prep: fillTA | fillTB | scatter | xsplit --------------
__global__ void __launch_bounds__(256) k_prep(const float* __restrict__ xin,
                                              const float* __restrict__ dw,
                                              const int*   __restrict__ fh,
                                              const int*   __restrict__ fw) {
    __shared__ float tile[32][33];
    int blk = blockIdx.x;
    int tid = threadIdx.x;

    if (blk < NB_TA) {
        // ---- fill TA (1536x1536), 8 elems (4 p's) per thread ---------------
        int id8 = blk * 256 + tid;          // 0 .. 1536*192-1
        int i  = id8 / 192;
        int jb = (id8 - i*192) * 8;
        int m  = (i < 768) ? i : i - 768;
        int idx = (m * (jb >> 1)) % 768;
        __half h[8];
        bool top = (i < 768);
#pragma unroll
        for (int u = 0; u < 4; ++u) {
            float2 cs = g_tw[idx];
            h[2*u]   = __float2half(top ? cs.x : cs.y);
            h[2*u+1] = __float2half(top ? -cs.y : cs.x);
            idx += m; if (idx >= 768) idx -= 768;
        }
        *(uint4*)&g_TAh[(size_t)i*1536 + jb] = *(uint4*)h;
        return;
    }
    blk -= NB_TA;

    if (blk < NB_TB) {
        // ---- fill TB (768 x 800): cos at [0,385), -sin at [400,785) --------
        int id8 = blk * 256 + tid;          // 0 .. 768*100-1
        int t  = id8 / 100;
        int cb = (id8 - t*100) * 8;
        __half h[8];
#pragma unroll
        for (int u = 0; u < 8; ++u) {
            int c = cb + u;
            float v = 0.f;
            if (c < 385) {
                v = g_tw[(c * t) % 768].x;
            } else if (c >= 400 && c < 785) {
                v = -g_tw[((c - 400) * t) % 768].y;
            }
            h[u] = __float2half(v);
        }
        *(uint4*)&g_TBh[(size_t)t*KB2 + cb] = *(uint4*)h;
        return;
    }
    blk -= NB_TB;

    if (blk < NB_SC) {
        // ---- scatter dft_weight into packed interleaved G (x 2^20) --------
        int n = blk * 256 + tid;
        if (n >= NF) return;
        int p = fh[n];
        int q = fw[n];
        const float2* dw2 = (const float2*)dw;
#pragma unroll
        for (int k = 0; k < KN_; ++k) {
            float2 v = dw2[(size_t)k*NF + n];
            __half2 h = __floats2half2_rn(v.x * GSCALE, v.y * GSCALE);
            *(__half2*)&g_GTh[(size_t)(k*NSTRIDE + q)*1536 + 2*p] = h;
        }
        return;
    }
    blk -= NB_SC;

    {
        // ---- x: convert to fp16 + transpose to channel-last ----------------
        int b  = blk / (128*8);
        int r  = blk % (128*8);
        int pb = r & 127;
        int cb = r >> 7;
        int p0 = pb * 32;
        int c0 = cb * 32;
        int tx = tid & 31, ty = tid >> 5;   // 32 x 8
#pragma unroll
        for (int j = 0; j < 4; ++j) {
            int ch = c0 + ty + j*8;
            tile[ty + j*8][tx] = xin[((size_t)b*C_ + ch)*(HW_*HW_) + p0 + tx];
        }
        __syncthreads();
#pragma unroll
        for (int j = 0; j < 4; ++j) {
            int p = p0 + ty + j*8;
            float v = tile[tx][ty + j*8];
            size_t oidx = ((size_t)b*(HW_*HW_) + p)*C_ + c0 + tx;
            g_Xh[oidx] = __float2half(v);
        }
    }
}

// --------- convert stage-A output -> stage-B A operand (single fp16) -------
// sums split-K partials; 2 q per thread, aligned float2 loads / half2 stores
__global__ void k_yconv() {
    int id = blockIdx.x * 256 + threadIdx.x;
    if (id >= KN_*D1*193) return;
    int qp = id % 193;
    int r  = id / 193;          // k*768 + m
    int m  = r % D1;
    int k  = r / D1;
    int q  = qp * 2;
    int col = k*NSTRIDE + q;
    size_t ir = (size_t)m*NPAD + col;
    size_t ii = (size_t)(768 + m)*NPAD + col;
    float2 a0 = *(const float2*)&g_Ytmp[0][ir];
    float2 a1 = *(const float2*)&g_Ytmp[1][ir];
    float2 b0 = *(const float2*)&g_Ytmp[0][ii];
    float2 b1 = *(const float2*)&g_Ytmp[1][ii];

    bool edge0 = (q == 0) || (q == 384);
    float sc0  = (edge0 ? 1.f : 2.f) * (1.f/72.f);
    float yr0  = (a0.x + a1.x) * sc0;
    float yi0  = edge0 ? 0.f : (b0.x + b1.x) * sc0;

    size_t base = (size_t)r*KB2;
    if (qp < 192) {
        float sc1 = 2.f/72.f;                    // q+1 odd, never an edge
        float yr1 = (a0.y + a1.y) * sc1;
        float yi1 = (b0.y + b1.y) * sc1;
        *(__half2*)&g_YAh[base + q]       = __floats2half2_rn(yr0, yr1);
        *(__half2*)&g_YAh[base + 400 + q] = __floats2half2_rn(yi0, yi1);
    } else {
        g_YAh[base + 384] = __float2half(yr0);
        g_YAh[base + 784] = __float2half(yi0);
    }
}

// --- fp16 single-pass wmma GEMM body, 3-stage pipe, 1 sync/chunk, split-K --
__device__ __forceinline__ void gemm_body_h(
    const __half* A0, int lda,
    const __half* B0, int ldb,
    float* Cc, int ldc, int c0, int c1, float osc)
{
    extern __shared__ __half dsm[];
    __half* sA = dsm;
    __half* sB = dsm + PIPE*STG_E;

    int tid = threadIdx.x;
    int wid = tid >> 5;
    int warp_m = wid >> 2;
    int warp_n = wid & 3;
    int m0 = blockIdx.y * 128;
    int n0 = blockIdx.x * 128;

    int lrow  = tid >> 1;
    int lhalf = (tid & 1) << 4;

    uint32_t aB = smem_u32(sA);
    uint32_t bB = smem_u32(sB);
    uint32_t dOff = (uint32_t)(lrow*AST + lhalf) * 2;

    wmma::fragment<wmma::accumulator, 16, 16, 16, float> acc[4][2];
#pragma unroll
    for (int i = 0; i < 4; ++i)
#pragma unroll
        for (int j = 0; j < 2; ++j)
            wmma::fill_fragment(acc[i][j], 0.f);

    auto issue = [&](int c, int stg) {
        int k0 = c * 32;
        const __half* asrc = A0 + (size_t)(m0 + lrow)*lda + k0 + lhalf;
        uint32_t ad = aB + stg*STG_B + dOff;
        cp_async16(ad,      asrc,     16);
        cp_async16(ad + 16, asrc + 8, 16);

        const __half* bsrc = B0 + (size_t)(n0 + lrow)*ldb + k0 + lhalf;
        uint32_t bd = bB + stg*STG_B + dOff;
        cp_async16(bd,      bsrc,     16);
        cp_async16(bd + 16, bsrc + 8, 16);
        CP_COMMIT();
    };

    issue(c0, 0);
    if (c0 + 1 < c1) issue(c0 + 1, 1);

    for (int c = c0; c < c1; ++c) {
        if (c + 1 < c1) CP_WAIT(1);
        else            CP_WAIT(0);
        __syncthreads();

        int stg = (c - c0) % PIPE;
        const __half* sAc = sA + stg*STG_E;
        const __half* sBc = sB + stg*STG_E;
#pragma unroll
        for (int kk = 0; kk < 2; ++kk) {
            wmma::fragment<wmma::matrix_a, 16, 16, 16, __half, wmma::row_major> af[4];
            wmma::fragment<wmma::matrix_b, 16, 16, 16, __half, wmma::col_major> bfr[2];
#pragma unroll
            for (int i = 0; i < 4; ++i)
                wmma::load_matrix_sync(af[i],
                    sAc + (warp_m*64 + i*16)*AST + kk*16, AST);
#pragma unroll
            for (int j = 0; j < 2; ++j)
                wmma::load_matrix_sync(bfr[j],
                    sBc + (warp_n*32 + j*16)*AST + kk*16, AST);
#pragma unroll
            for (int i = 0; i < 4; ++i)
#pragma unroll
                for (int j = 0; j < 2; ++j)
                    wmma::mma_sync(acc[i][j], af[i], bfr[j], acc[i][j]);
        }

        if (c + 2 < c1) issue(c + 2, (c + 2 - c0) % PIPE);
    }

    float* ob = Cc + (size_t)(m0 + warp_m*64)*ldc + n0 + warp_n*32;
#pragma unroll
    for (int i = 0; i < 4; ++i)
#pragma unroll
        for (int j = 0; j < 2; ++j) {
#pragma unroll
            for (int e = 0; e < acc[i][j].num_elements; ++e)
                acc[i][j].x[e] *= osc;
            wmma::store_matrix_sync(ob + (size_t)i*16*ldc + j*16,
                                    acc[i][j], ldc, wmma::mem_row_major);
        }
}

// Stage A: Y(1536 x 1664) = TA(1536x1536) * G^T. split-K x2 via blockIdx.z.
__global__ void __launch_bounds__(256) k_gemmA() {
    int z = blockIdx.z;                 // 0: chunks [0,24), 1: [24,48)
    gemm_body_h(g_TAh, 1536, g_GTh, 1536,
                g_Ytmp[z], NPAD, z*24, (z+1)*24, 1.f);
}

// Stage B: S(3072 x 768) = YA * TB^T. split-K x2 (13 + 12 chunks).
__global__ void __launch_bounds__(256) k_gemmB() {
    int z = blockIdx.z;
    int c0 = z ? 13 : 0;
    int c1 = z ? 25 : 13;
    gemm_body_h(g_YAh, KB2, g_TBh, KB2,
                &g_Sp[z][0][0], D2, c0, c1, SINV);
}

// ------- combine per-batch weights -> single fp16 (scaled 2^31), K-major ---
__global__ void __launch_bounds__(256) k_combine_fp16() {
    __shared__ float sk[KN_][768];
    int blk = blockIdx.x;              // 0 .. 767
    int s = blk % 3;
    int o = blk / 3;
    int tid = threadIdx.x;

    int row = (o*3 + s) * D2;
#pragma unroll
    for (int k = 0; k < KN_; ++k)
#pragma unroll
        for (int rep = 0; rep < 3; ++rep) {
            int t = tid + rep*256;
            sk[k][t] = g_Sp[0][k][row + t] + g_Sp[1][k][row + t];
        }
    __syncthreads();

#pragma unroll
    for (int b = 0; b < B_; ++b) {
        float a0 = g_att[b*KN_ + 0];
        float a1 = g_att[b*KN_ + 1];
        float a2 = g_att[b*KN_ + 2];
        float a3 = g_att[b*KN_ + 3];
        size_t obase = ((size_t)(b*256 + o)*9 + s*3) * 256 + tid;
#pragma unroll
        for (int tt = 0; tt < 3; ++tt) {
            int t = tid*3 + tt;
            float v = a0*sk[0][t] + a1*sk[1][t] + a2*sk[2][t] + a3*sk[3][t];
            g_Wh[obase + (size_t)tt*256] = __float2half(v * WSCALE);
        }
    }
}

// --------- wmma fp16 conv: M=128 x N=256 tile, 16 warps of 64x32 -----------
#define NCHUNK 72

__global__ void __launch_bounds__(512) k_conv_wmma(float* __restrict__ out) {
    extern __shared__ __half dsm[];
    __half* sA = dsm;
    __half* sB = dsm + PIPE*ASTG_E;

    int tid = threadIdx.x;
    int wid = tid >> 5;
    int warp_m = wid >> 3;
    int warp_n = wid & 7;
    int b  = blockIdx.z;
    int o0 = blockIdx.y * 128;
    int n0 = blockIdx.x * 256;

    int arow = tid >> 2;
    int aseg = (tid & 3) << 3;
    int brow = tid >> 1;
    int bseg = (tid & 1) << 4;

    uint32_t aB = smem_u32(sA);
    uint32_t bB = smem_u32(sB);
    uint32_t aOff = (uint32_t)(arow*AST + aseg) * 2;
    uint32_t bOff = (uint32_t)(brow*AST + bseg) * 2;

    wmma::fragment<wmma::accumulator, 16, 16, 16, float> acc[4][2];
#pragma unroll
    for (int i = 0; i < 4; ++i)
#pragma unroll
        for (int j = 0; j < 2; ++j)
            wmma::fill_fragment(acc[i][j], 0.f);

    auto issue = [&](int c, int stg) {
        int st   = c >> 3;
        int i0   = (c & 7) << 5;
        int s    = st / 3, t = st % 3;

        const __half* asrc = g_Wh + (size_t)b*(C_*9*C_)
                             + (size_t)(o0 + arow)*2304 + st*256 + i0 + aseg;
        cp_async16(aB + stg*ASTG_B + aOff, asrc, 16);

        int n  = n0 + brow;
        int yy = (n >> 6) + s - 1;
        int xx = (n & 63) + t - 1;
        int ok = (((unsigned)yy < HW_) && ((unsigned)xx < HW_)) ? 16 : 0;
        const __half* bsrc = g_Xh + (((size_t)b*(HW_*HW_) + yy*HW_ + xx)*C_
                                     + i0 + bseg);
        uint32_t bd = bB + stg*BSTG_B + bOff;
        cp_async16(bd,      bsrc,     ok);
        cp_async16(bd + 16, bsrc + 8, ok);
        CP_COMMIT();
    };

    issue(0, 0);
    issue(1, 1);

    for (int c = 0; c < NCHUNK; ++c) {
        if (c + 1 < NCHUNK) CP_WAIT(1);
        else                CP_WAIT(0);
        __syncthreads();

        int stg = c % PIPE;
        const __half* sAc = sA + stg*ASTG_E;
        const __half* sBc = sB + stg*BSTG_E;
#pragma unroll
        for (int kk = 0; kk < 2; ++kk) {
            wmma::fragment<wmma::matrix_a, 16, 16, 16, __half, wmma::row_major> af[4];
            wmma::fragment<wmma::matrix_b, 16, 16, 16, __half, wmma::col_major> bfr[2];
#pragma unroll
            for (int i = 0; i < 4; ++i)
                wmma::load_matrix_sync(af[i],
                    sAc + (warp_m*64 + i*16)*AST + kk*16, AST);
#pragma unroll
            for (int j = 0; j < 2; ++j)
                wmma::load_matrix_sync(bfr[j],
                    sBc + (warp_n*32 + j*16)*AST + kk*16, AST);
#pragma unroll
            for (int i = 0; i < 4; ++i)
#pragma unroll
                for (int j = 0; j < 2; ++j)
                    wmma::mma_sync(acc[i][j], af[i], bfr[j], acc[i][j]);
        }

        if (c + 2 < NCHUNK) issue(c + 2, (c + 2) % PIPE);
    }

    float* ob = out + ((size_t)b*C_ + o0 + warp_m*64)*(HW_*HW_) + n0 + warp_n*32;
#pragma unroll
    for (int i = 0; i < 4; ++i)
#pragma unroll
        for (int j = 0; j < 2; ++j) {
#pragma unroll
            for (int e = 0; e < acc[i][j].num_elements; ++e)
                acc[i][j].x[e] *= OSCALE;
            wmma::store_matrix_sync(ob + (size_t)i*16*(HW_*HW_) + j*16,
                                    acc[i][j], HW_*HW_, wmma::mem_row_major);
        }
}

// ---------------- launch ----------------------------------------------------
extern "C" void kernel_launch(void* const* d_in, const int* in_sizes, int n_in,
                              void* d_out, int out_size) {
    const float* x    = (const float*)d_in[0];
    const float* dw   = (const float*)d_in[1];
    const float* katt = (const float*)d_in[2];
    const int*   fh   = (const int*)d_in[3];
    const int*   fw   = (const int*)d_in[4];
    float* out = (float*)d_out;

    cudaFuncSetAttribute(k_gemmA, cudaFuncAttributeMaxDynamicSharedMemorySize, SMEM_PIPE);
    cudaFuncSetAttribute(k_gemmB, cudaFuncAttributeMaxDynamicSharedMemorySize, SMEM_PIPE);
    cudaFuncSetAttribute(k_conv_wmma, cudaFuncAttributeMaxDynamicSharedMemorySize, SMEM_CONV);

    k_setup<<<1, 768>>>(katt);
    k_prep <<<NB_PREP, 256>>>(x, dw, fh, fw);

    k_gemmA<<<dim3(NPAD/128, 1536/128, 2), 256, SMEM_PIPE>>>();
    k_yconv<<<(KN_*D1*193 + 255)/256, 256>>>();
    k_gemmB<<<dim3(D2/128, (KN_*D1)/128, 2), 256, SMEM_PIPE>>>();

    k_combine_fp16<<<C_*3, 256>>>();
    k_conv_wmma   <<<dim3(HW_*HW_/256, C_/128, B_), 512, SMEM_CONV>>>(out);
}